// round 2
// baseline (speedup 1.0000x reference)
#include <cuda_runtime.h>
#include <math.h>

#define Bn 256
#define Rn 2048
#define Hn 64
#define En 20
#define LN_EPSF 1e-5f

// Scratch (no allocations allowed): sparse prompts + folded constants.
__device__ float g_prompt[Bn * En * Hn];   // 1.31 MB
__device__ float g_c1[Hn];                 // p0 @ fus_W1[H:] + fus_b1
__device__ float g_cg;                     // p0 . gate_W[H:] + gate_b

// ---------------------------------------------------------------------------
// K0: compute p0 = LN(upd_b)*g+b (prompt for rows with zero aggregation),
// then fold it into c1 / cg. 1 block, 64 threads.
// ---------------------------------------------------------------------------
__global__ void k0_constants(const float* __restrict__ upd_b,
                             const float* __restrict__ ln_g,
                             const float* __restrict__ ln_b,
                             const float* __restrict__ fus_W1,
                             const float* __restrict__ fus_b1,
                             const float* __restrict__ gate_W,
                             const float* __restrict__ gate_b) {
    __shared__ float p0[Hn];
    __shared__ float red[2];
    int j = threadIdx.x;              // 0..63
    float u = upd_b[j];

    float s = u;
    #pragma unroll
    for (int o = 16; o > 0; o >>= 1) s += __shfl_xor_sync(0xffffffffu, s, o);
    if ((j & 31) == 0) red[j >> 5] = s;
    __syncthreads();
    float mu = (red[0] + red[1]) * (1.0f / Hn);
    __syncthreads();

    float d = u - mu;
    s = d * d;
    #pragma unroll
    for (int o = 16; o > 0; o >>= 1) s += __shfl_xor_sync(0xffffffffu, s, o);
    if ((j & 31) == 0) red[j >> 5] = s;
    __syncthreads();
    float var = (red[0] + red[1]) * (1.0f / Hn);

    float p = d * rsqrtf(var + LN_EPSF) * ln_g[j] + ln_b[j];
    p0[j] = p;
    __syncthreads();

    float c = fus_b1[j];
    #pragma unroll 8
    for (int k = 0; k < Hn; k++) c = fmaf(p0[k], fus_W1[(Hn + k) * Hn + j], c);
    g_c1[j] = c;

    s = p0[j] * gate_W[Hn + j];
    #pragma unroll
    for (int o = 16; o > 0; o >>= 1) s += __shfl_xor_sync(0xffffffffu, s, o);
    __syncthreads();
    if ((j & 31) == 0) red[j >> 5] = s;
    __syncthreads();
    if (j == 0) g_cg = red[0] + red[1] + gate_b[0];
}

// ---------------------------------------------------------------------------
// KA: per-sample sparse prompt pipeline. grid=B blocks, 64 threads.
// h -> msg -> segment_sum -> upd -> LayerNorm, for the <=20 touched relations.
// Uses concat([h,h])@msg_W == h@(msg_W[:H]+msg_W[H:]).
// ---------------------------------------------------------------------------
__global__ void kA_prompts(const int* __restrict__ qrel,
                           const int* __restrict__ etype,
                           const float* __restrict__ noise,
                           const float* __restrict__ msg_W,
                           const float* __restrict__ msg_b,
                           const float* __restrict__ upd_W,
                           const float* __restrict__ upd_b,
                           const float* __restrict__ ln_g,
                           const float* __restrict__ ln_b) {
    __shared__ __align__(16) float Wsum[Hn * Hn];   // msg_W[:H] + msg_W[H:]
    __shared__ __align__(16) float Wupd[Hn * Hn];
    __shared__ __align__(16) float hs[En][Hn];      // h, later reused for agg
    __shared__ __align__(16) float ms[En][Hn];      // msg
    __shared__ int   er[En];
    __shared__ float red[2];

    int b = blockIdx.x;
    int j = threadIdx.x;              // 0..63

    for (int idx = j; idx < Hn * Hn; idx += 64) {
        Wsum[idx] = msg_W[idx] + msg_W[Hn * Hn + idx];
        Wupd[idx] = upd_W[idx];
    }
    if (j < En) er[j] = etype[b * En + j];
    __syncthreads();

    int qr = qrel[b];
    for (int e = 0; e < En; e++) {
        int r = er[e];
        hs[e][j] = (r == qr) ? 1.0f
                             : noise[((size_t)b * Rn + r) * Hn + j] * 0.1f;
    }
    __syncthreads();

    for (int e = 0; e < En; e++) {
        float m = msg_b[j];
        #pragma unroll 8
        for (int k = 0; k < Hn; k++) m = fmaf(hs[e][k], Wsum[k * Hn + j], m);
        ms[e][j] = fmaxf(m, 0.0f);
    }
    __syncthreads();

    // agg[e] = sum of msg over edges with same relation (== segment_sum value)
    float aggv[En];
    for (int e = 0; e < En; e++) {
        float a = 0.0f;
        for (int e2 = 0; e2 < En; e2++)
            if (er[e2] == er[e]) a += ms[e2][j];
        aggv[e] = a;
    }
    __syncthreads();
    for (int e = 0; e < En; e++) hs[e][j] = aggv[e];
    __syncthreads();

    for (int e = 0; e < En; e++) {
        float u = upd_b[j];
        #pragma unroll 8
        for (int k = 0; k < Hn; k++) u = fmaf(hs[e][k], Wupd[k * Hn + j], u);

        float s = u;
        #pragma unroll
        for (int o = 16; o > 0; o >>= 1) s += __shfl_xor_sync(0xffffffffu, s, o);
        if ((j & 31) == 0) red[j >> 5] = s;
        __syncthreads();
        float mu = (red[0] + red[1]) * (1.0f / Hn);
        __syncthreads();

        float d = u - mu;
        s = d * d;
        #pragma unroll
        for (int o = 16; o > 0; o >>= 1) s += __shfl_xor_sync(0xffffffffu, s, o);
        if ((j & 31) == 0) red[j >> 5] = s;
        __syncthreads();
        float var = (red[0] + red[1]) * (1.0f / Hn);

        g_prompt[((size_t)b * En + e) * Hn + j] =
            d * rsqrtf(var + LN_EPSF) * ln_g[j] + ln_b[j];
        __syncthreads();
    }
}

// ---------------------------------------------------------------------------
// KB: main fusion over all B*R rows.
//   default row: y = relu(x@W1a + c1); f = y@W2 + b2; g = sigmoid(x.gWa + cg)
//   special row (relation in edge list): c1/cg recomputed from its prompt.
// Each warp handles 4 rows simultaneously so a weight float2 LDS feeds 8 FMAs
// (keeps smem crossbar under the FMA pipe -> FMA-bound at ~64 lane-FMA/cyc/SM).
// ---------------------------------------------------------------------------
#define KB_WARPS 8
#define KB_ROWT  4
#define KB_ITERS 4
#define ROWS_PER_BLOCK (KB_WARPS * KB_ROWT * KB_ITERS)   // 128
#define BLOCKS_PER_B   (Rn / ROWS_PER_BLOCK)             // 16

__global__ __launch_bounds__(256)
void kB_fuse(const float* __restrict__ base,
             const float* __restrict__ fus_W1,
             const float* __restrict__ fus_b1,
             const float* __restrict__ fus_W2,
             const float* __restrict__ fus_b2,
             const float* __restrict__ gate_W,
             const float* __restrict__ gate_b,
             const int*   __restrict__ etype,
             float* __restrict__ out) {
    // NOTE: 16B alignment is load-bearing — float2/float4 casts into these.
    __shared__ __align__(16) float W1s[Hn * Hn];    // fus_W1 rows 0..63 (x part)
    __shared__ __align__(16) float W2s[Hn * Hn];
    __shared__ __align__(16) float xbuf[KB_WARPS][KB_ROWT][Hn];
    __shared__ __align__(16) float c1s[Hn];
    __shared__ __align__(16) float b1s[Hn];
    __shared__ __align__(16) float b2s[Hn];
    __shared__ __align__(16) float gWa[Hn];
    __shared__ int   er[En];
    __shared__ float cgs;

    int tid  = threadIdx.x;
    int b    = blockIdx.x / BLOCKS_PER_B;
    int rblk = blockIdx.x % BLOCKS_PER_B;

    for (int idx = tid; idx < Hn * Hn; idx += 256) {
        W1s[idx] = fus_W1[idx];
        W2s[idx] = fus_W2[idx];
    }
    if (tid < Hn) {
        c1s[tid] = g_c1[tid];
        b1s[tid] = fus_b1[tid];
        b2s[tid] = fus_b2[tid];
        gWa[tid] = gate_W[tid];
    }
    if (tid < En) er[tid] = etype[b * En + tid];
    if (tid == 0) cgs = g_cg;
    __syncthreads();

    int w = tid >> 5, lane = tid & 31;
    float gate_b_v = gate_b[0];
    float cg_v = cgs;

    for (int it = 0; it < KB_ITERS; it++) {
        int r0 = rblk * ROWS_PER_BLOCK + it * (KB_WARPS * KB_ROWT) + w * KB_ROWT;
        const float* xg = base + ((size_t)b * Rn + r0) * Hn;

        float2 xl[KB_ROWT];
        #pragma unroll
        for (int t = 0; t < KB_ROWT; t++) {
            xl[t] = ((const float2*)(xg + t * Hn))[lane];
            ((float2*)xbuf[w][t])[lane] = xl[t];
        }
        __syncwarp();

        // per-row init: folded constant (default) or prompt fixup (special)
        float2 acc[KB_ROWT];
        float  gp[KB_ROWT], gc[KB_ROWT];
        #pragma unroll
        for (int t = 0; t < KB_ROWT; t++) {
            acc[t] = make_float2(c1s[2 * lane], c1s[2 * lane + 1]);
            gp[t]  = xl[t].x * gWa[2 * lane] + xl[t].y * gWa[2 * lane + 1];
            gc[t]  = cg_v;
        }

        #pragma unroll
        for (int t = 0; t < KB_ROWT; t++) {
            int r = r0 + t, sp = -1;
            for (int e = 0; e < En; e++)
                if (er[e] == r) { sp = e; break; }
            if (sp >= 0) {   // rare: <=20 of 2048 rows/sample
                const float* p = g_prompt + ((size_t)b * En + sp) * Hn;
                float2 a = make_float2(b1s[2 * lane], b1s[2 * lane + 1]);
                for (int k = 0; k < Hn; k++) {
                    float  pk = p[k];
                    float2 wv = ((const float2*)(fus_W1 + (Hn + k) * Hn))[lane];
                    a.x = fmaf(pk, wv.x, a.x);
                    a.y = fmaf(pk, wv.y, a.y);
                }
                acc[t] = a;
                gp[t] += p[2 * lane]     * gate_W[Hn + 2 * lane]
                       + p[2 * lane + 1] * gate_W[Hn + 2 * lane + 1];
                gc[t]  = gate_b_v;
            }
        }

        // GEMM1: acc += x @ W1s   (lane owns output cols 2*lane, 2*lane+1)
        #pragma unroll
        for (int k4 = 0; k4 < Hn / 4; k4++) {
            float4 xv[KB_ROWT];
            #pragma unroll
            for (int t = 0; t < KB_ROWT; t++)
                xv[t] = ((const float4*)xbuf[w][t])[k4];
            #pragma unroll
            for (int kk = 0; kk < 4; kk++) {
                float2 wv = ((const float2*)(W1s + (k4 * 4 + kk) * Hn))[lane];
                #pragma unroll
                for (int t = 0; t < KB_ROWT; t++) {
                    float xk = (kk == 0) ? xv[t].x : (kk == 1) ? xv[t].y
                             : (kk == 2) ? xv[t].z : xv[t].w;
                    acc[t].x = fmaf(xk, wv.x, acc[t].x);
                    acc[t].y = fmaf(xk, wv.y, acc[t].y);
                }
            }
        }

        // relu -> stage y (reuse xbuf; x kept in xl regs for epilogue)
        __syncwarp();
        #pragma unroll
        for (int t = 0; t < KB_ROWT; t++) {
            float2 y = make_float2(fmaxf(acc[t].x, 0.0f), fmaxf(acc[t].y, 0.0f));
            ((float2*)xbuf[w][t])[lane] = y;
            acc[t] = make_float2(b2s[2 * lane], b2s[2 * lane + 1]);
        }
        __syncwarp();

        // GEMM2: acc += y @ W2s
        #pragma unroll
        for (int k4 = 0; k4 < Hn / 4; k4++) {
            float4 yv[KB_ROWT];
            #pragma unroll
            for (int t = 0; t < KB_ROWT; t++)
                yv[t] = ((const float4*)xbuf[w][t])[k4];
            #pragma unroll
            for (int kk = 0; kk < 4; kk++) {
                float2 wv = ((const float2*)(W2s + (k4 * 4 + kk) * Hn))[lane];
                #pragma unroll
                for (int t = 0; t < KB_ROWT; t++) {
                    float yk = (kk == 0) ? yv[t].x : (kk == 1) ? yv[t].y
                             : (kk == 2) ? yv[t].z : yv[t].w;
                    acc[t].x = fmaf(yk, wv.x, acc[t].x);
                    acc[t].y = fmaf(yk, wv.y, acc[t].y);
                }
            }
        }
        __syncwarp();

        // gate + blend + store
        #pragma unroll
        for (int t = 0; t < KB_ROWT; t++) {
            float s = gp[t];
            #pragma unroll
            for (int o = 16; o > 0; o >>= 1)
                s += __shfl_xor_sync(0xffffffffu, s, o);
            float z = s + gc[t];
            float g = 1.0f / (1.0f + __expf(-z));
            float2 o2;
            o2.x = xl[t].x + g * (acc[t].x - xl[t].x);
            o2.y = xl[t].y + g * (acc[t].y - xl[t].y);
            ((float2*)(out + ((size_t)b * Rn + r0 + t) * Hn))[lane] = o2;
        }
    }
}

// ---------------------------------------------------------------------------
// Input order (metadata): 0 query_relations, 1 edge_type, 2 base_relation_reprs,
// 3 init_noise, 4 msg_W, 5 msg_b, 6 upd_W, 7 upd_b, 8 ln_g, 9 ln_b,
// 10 fus_W1, 11 fus_b1, 12 fus_W2, 13 fus_b2, 14 gate_W, 15 gate_b
// ---------------------------------------------------------------------------
extern "C" void kernel_launch(void* const* d_in, const int* in_sizes, int n_in,
                              void* d_out, int out_size) {
    const int*   qrel   = (const int*)  d_in[0];
    const int*   etype  = (const int*)  d_in[1];
    const float* base   = (const float*)d_in[2];
    const float* noise  = (const float*)d_in[3];
    const float* msg_W  = (const float*)d_in[4];
    const float* msg_b  = (const float*)d_in[5];
    const float* upd_W  = (const float*)d_in[6];
    const float* upd_b  = (const float*)d_in[7];
    const float* ln_g   = (const float*)d_in[8];
    const float* ln_b   = (const float*)d_in[9];
    const float* fus_W1 = (const float*)d_in[10];
    const float* fus_b1 = (const float*)d_in[11];
    const float* fus_W2 = (const float*)d_in[12];
    const float* fus_b2 = (const float*)d_in[13];
    const float* gate_W = (const float*)d_in[14];
    const float* gate_b = (const float*)d_in[15];
    float* out = (float*)d_out;

    k0_constants<<<1, Hn>>>(upd_b, ln_g, ln_b, fus_W1, fus_b1, gate_W, gate_b);
    kA_prompts<<<Bn, Hn>>>(qrel, etype, noise, msg_W, msg_b,
                           upd_W, upd_b, ln_g, ln_b);
    kB_fuse<<<Bn * BLOCKS_PER_B, 256>>>(base, fus_W1, fus_b1, fus_W2, fus_b2,
                                        gate_W, gate_b, etype, out);
}

// round 3
// speedup vs baseline: 1.1616x; 1.1616x over previous
#include <cuda_runtime.h>
#include <math.h>

#define Bn 256
#define Rn 2048
#define Hn 64
#define En 20
#define LN_EPSF 1e-5f

// Scratch (no allocations allowed).
__device__ float g_prompt[Bn * En * Hn];   // 1.31 MB sparse prompts
__device__ float g_c1[Hn];                 // p0 @ fus_W1[H:] + fus_b1
__device__ float g_cg;                     // p0 . gate_W[H:] + gate_b
__device__ signed char g_special[Bn * Rn]; // per-(b,r): edge slot or -1

// ---- packed f32x2 helpers (FFMA2 path; ptxas never emits these from C++) ----
static __device__ __forceinline__ unsigned long long pack_dup(float x) {
    unsigned long long r;
    asm("mov.b64 %0, {%1, %1};" : "=l"(r) : "f"(x));
    return r;
}
static __device__ __forceinline__ unsigned long long pack2(float lo, float hi) {
    unsigned long long r;
    asm("mov.b64 %0, {%1, %2};" : "=l"(r) : "f"(lo), "f"(hi));
    return r;
}
static __device__ __forceinline__ float2 unpack2(unsigned long long v) {
    float lo, hi;
    asm("mov.b64 {%0, %1}, %2;" : "=f"(lo), "=f"(hi) : "l"(v));
    return make_float2(lo, hi);
}
static __device__ __forceinline__ void fma2(unsigned long long& d,
                                            unsigned long long a,
                                            unsigned long long b) {
    asm("fma.rn.f32x2 %0, %1, %2, %0;" : "+l"(d) : "l"(a), "l"(b));
}

// ---------------------------------------------------------------------------
// K0: p0 = LN(upd_b)*g+b (prompt of untouched rows), folded into c1 / cg.
// ---------------------------------------------------------------------------
__global__ void k0_constants(const float* __restrict__ upd_b,
                             const float* __restrict__ ln_g,
                             const float* __restrict__ ln_b,
                             const float* __restrict__ fus_W1,
                             const float* __restrict__ fus_b1,
                             const float* __restrict__ gate_W,
                             const float* __restrict__ gate_b) {
    __shared__ float p0[Hn];
    __shared__ float red[2];
    int j = threadIdx.x;              // 0..63
    float u = upd_b[j];

    float s = u;
    #pragma unroll
    for (int o = 16; o > 0; o >>= 1) s += __shfl_xor_sync(0xffffffffu, s, o);
    if ((j & 31) == 0) red[j >> 5] = s;
    __syncthreads();
    float mu = (red[0] + red[1]) * (1.0f / Hn);
    __syncthreads();

    float d = u - mu;
    s = d * d;
    #pragma unroll
    for (int o = 16; o > 0; o >>= 1) s += __shfl_xor_sync(0xffffffffu, s, o);
    if ((j & 31) == 0) red[j >> 5] = s;
    __syncthreads();
    float var = (red[0] + red[1]) * (1.0f / Hn);

    float p = d * rsqrtf(var + LN_EPSF) * ln_g[j] + ln_b[j];
    p0[j] = p;
    __syncthreads();

    float c = fus_b1[j];
    #pragma unroll 8
    for (int k = 0; k < Hn; k++) c = fmaf(p0[k], fus_W1[(Hn + k) * Hn + j], c);
    g_c1[j] = c;

    s = p0[j] * gate_W[Hn + j];
    #pragma unroll
    for (int o = 16; o > 0; o >>= 1) s += __shfl_xor_sync(0xffffffffu, s, o);
    __syncthreads();
    if ((j & 31) == 0) red[j >> 5] = s;
    __syncthreads();
    if (j == 0) g_cg = red[0] + red[1] + gate_b[0];
}

// ---------------------------------------------------------------------------
// KA: per-sample sparse prompts (<=20 touched relations) + special-row map.
// ---------------------------------------------------------------------------
__global__ void kA_prompts(const int* __restrict__ qrel,
                           const int* __restrict__ etype,
                           const float* __restrict__ noise,
                           const float* __restrict__ msg_W,
                           const float* __restrict__ msg_b,
                           const float* __restrict__ upd_W,
                           const float* __restrict__ upd_b,
                           const float* __restrict__ ln_g,
                           const float* __restrict__ ln_b) {
    __shared__ __align__(16) float Wsum[Hn * Hn];   // msg_W[:H] + msg_W[H:]
    __shared__ __align__(16) float Wupd[Hn * Hn];
    __shared__ __align__(16) float hs[En][Hn];
    __shared__ __align__(16) float ms[En][Hn];
    __shared__ int   er[En];
    __shared__ float red[2];

    int b = blockIdx.x;
    int j = threadIdx.x;              // 0..63

    for (int idx = j; idx < Hn * Hn; idx += 64) {
        Wsum[idx] = msg_W[idx] + msg_W[Hn * Hn + idx];
        Wupd[idx] = upd_W[idx];
    }
    if (j < En) er[j] = etype[b * En + j];

    // init this sample's special map to -1 (int stores of 0xFFFFFFFF)
    {
        int* sm = (int*)(g_special + (size_t)b * Rn);
        for (int idx = j; idx < Rn / 4; idx += 64) sm[idx] = -1;
    }
    __syncthreads();
    if (j < En) g_special[(size_t)b * Rn + er[j]] = (signed char)j;

    int qr = qrel[b];
    for (int e = 0; e < En; e++) {
        int r = er[e];
        hs[e][j] = (r == qr) ? 1.0f
                             : noise[((size_t)b * Rn + r) * Hn + j] * 0.1f;
    }
    __syncthreads();

    for (int e = 0; e < En; e++) {
        float m = msg_b[j];
        #pragma unroll 8
        for (int k = 0; k < Hn; k++) m = fmaf(hs[e][k], Wsum[k * Hn + j], m);
        ms[e][j] = fmaxf(m, 0.0f);
    }
    __syncthreads();

    // segment-sum value for each edge's relation
    float aggv[En];
    for (int e = 0; e < En; e++) {
        float a = 0.0f;
        for (int e2 = 0; e2 < En; e2++)
            if (er[e2] == er[e]) a += ms[e2][j];
        aggv[e] = a;
    }
    __syncthreads();
    for (int e = 0; e < En; e++) hs[e][j] = aggv[e];
    __syncthreads();

    for (int e = 0; e < En; e++) {
        float u = upd_b[j];
        #pragma unroll 8
        for (int k = 0; k < Hn; k++) u = fmaf(hs[e][k], Wupd[k * Hn + j], u);

        float s = u;
        #pragma unroll
        for (int o = 16; o > 0; o >>= 1) s += __shfl_xor_sync(0xffffffffu, s, o);
        if ((j & 31) == 0) red[j >> 5] = s;
        __syncthreads();
        float mu = (red[0] + red[1]) * (1.0f / Hn);
        __syncthreads();

        float d = u - mu;
        s = d * d;
        #pragma unroll
        for (int o = 16; o > 0; o >>= 1) s += __shfl_xor_sync(0xffffffffu, s, o);
        if ((j & 31) == 0) red[j >> 5] = s;
        __syncthreads();
        float var = (red[0] + red[1]) * (1.0f / Hn);

        g_prompt[((size_t)b * En + e) * Hn + j] =
            d * rsqrtf(var + LN_EPSF) * ln_g[j] + ln_b[j];
        __syncthreads();
    }
}

// ---------------------------------------------------------------------------
// KB: fusion over all B*R rows, FFMA2 inner loops.
// Lane owns packed output columns {2*lane, 2*lane+1}; warp carries 8 rows.
// ---------------------------------------------------------------------------
#define KB_WARPS 8
#define KB_ROWT  8
#define KB_ITERS 2
#define ROWS_PER_BLOCK (KB_WARPS * KB_ROWT * KB_ITERS)   // 128
#define BLOCKS_PER_B   (Rn / ROWS_PER_BLOCK)             // 16

__global__ __launch_bounds__(256)
void kB_fuse(const float* __restrict__ base,
             const float* __restrict__ fus_W1,
             const float* __restrict__ fus_b1,
             const float* __restrict__ fus_W2,
             const float* __restrict__ fus_b2,
             const float* __restrict__ gate_W,
             const float* __restrict__ gate_b,
             float* __restrict__ out) {
    __shared__ __align__(16) float W1s[Hn * Hn];
    __shared__ __align__(16) float W2s[Hn * Hn];
    __shared__ __align__(16) float xbuf[KB_WARPS][KB_ROWT][Hn];
    __shared__ __align__(16) float c1s[Hn];
    __shared__ __align__(16) float b2s[Hn];
    __shared__ __align__(16) float gWa[Hn];
    __shared__ float cgs;

    int tid  = threadIdx.x;
    int b    = blockIdx.x / BLOCKS_PER_B;
    int rblk = blockIdx.x % BLOCKS_PER_B;

    for (int idx = tid; idx < Hn * Hn; idx += 256) {
        W1s[idx] = fus_W1[idx];
        W2s[idx] = fus_W2[idx];
    }
    if (tid < Hn) {
        c1s[tid] = g_c1[tid];
        b2s[tid] = fus_b2[tid];
        gWa[tid] = gate_W[tid];
    }
    if (tid == 0) cgs = g_cg;
    __syncthreads();

    int w = tid >> 5, lane = tid & 31;
    float gate_b_v = gate_b[0];
    float cg_v = cgs;
    float gwx = gWa[2 * lane], gwy = gWa[2 * lane + 1];
    unsigned long long c1p = ((const unsigned long long*)c1s)[lane];
    unsigned long long b2p = ((const unsigned long long*)b2s)[lane];

    for (int it = 0; it < KB_ITERS; it++) {
        int r0 = rblk * ROWS_PER_BLOCK + it * (KB_WARPS * KB_ROWT) + w * KB_ROWT;
        const float* xg = base + ((size_t)b * Rn + r0) * Hn;

        float2 xl[KB_ROWT];
        #pragma unroll
        for (int t = 0; t < KB_ROWT; t++) {
            xl[t] = ((const float2*)(xg + t * Hn))[lane];
            ((float2*)xbuf[w][t])[lane] = xl[t];
        }
        __syncwarp();

        unsigned long long acc2[KB_ROWT];
        float gp[KB_ROWT], gc[KB_ROWT];
        #pragma unroll
        for (int t = 0; t < KB_ROWT; t++) {
            acc2[t] = c1p;
            gp[t]   = xl[t].x * gwx + xl[t].y * gwy;
            gc[t]   = cg_v;
        }

        // special rows (<=20 of 2048 per sample): recompute prompt half
        #pragma unroll
        for (int t = 0; t < KB_ROWT; t++) {
            int sp = g_special[(size_t)b * Rn + r0 + t];
            if (sp >= 0) {
                const float* p = g_prompt + ((size_t)b * En + sp) * Hn;
                float ax = fus_b1[2 * lane], ay = fus_b1[2 * lane + 1];
                for (int k = 0; k < Hn; k++) {
                    float  pk = p[k];
                    float2 wv = ((const float2*)(fus_W1 + (Hn + k) * Hn))[lane];
                    ax = fmaf(pk, wv.x, ax);
                    ay = fmaf(pk, wv.y, ay);
                }
                acc2[t] = pack2(ax, ay);
                gp[t] += p[2 * lane]     * gate_W[Hn + 2 * lane]
                       + p[2 * lane + 1] * gate_W[Hn + 2 * lane + 1];
                gc[t]  = gate_b_v;
            }
        }

        // GEMM1: acc2 += x @ W1s  (packed col pair per lane, FFMA2)
        #pragma unroll 4
        for (int k4 = 0; k4 < Hn / 4; k4++) {
            float4 xv[KB_ROWT];
            #pragma unroll
            for (int t = 0; t < KB_ROWT; t++)
                xv[t] = ((const float4*)xbuf[w][t])[k4];   // warp-broadcast
            #pragma unroll
            for (int kk = 0; kk < 4; kk++) {
                unsigned long long wv =
                    *(const unsigned long long*)(W1s + (k4 * 4 + kk) * Hn + 2 * lane);
                #pragma unroll
                for (int t = 0; t < KB_ROWT; t++) {
                    float xk = (kk == 0) ? xv[t].x : (kk == 1) ? xv[t].y
                             : (kk == 2) ? xv[t].z : xv[t].w;
                    fma2(acc2[t], pack_dup(xk), wv);
                }
            }
        }

        // relu -> stage y into xbuf (x stays live in xl regs)
        __syncwarp();
        #pragma unroll
        for (int t = 0; t < KB_ROWT; t++) {
            float2 y = unpack2(acc2[t]);
            y.x = fmaxf(y.x, 0.0f);
            y.y = fmaxf(y.y, 0.0f);
            ((float2*)xbuf[w][t])[lane] = y;
            acc2[t] = b2p;
        }
        __syncwarp();

        // GEMM2: acc2 += y @ W2s
        #pragma unroll 4
        for (int k4 = 0; k4 < Hn / 4; k4++) {
            float4 yv[KB_ROWT];
            #pragma unroll
            for (int t = 0; t < KB_ROWT; t++)
                yv[t] = ((const float4*)xbuf[w][t])[k4];
            #pragma unroll
            for (int kk = 0; kk < 4; kk++) {
                unsigned long long wv =
                    *(const unsigned long long*)(W2s + (k4 * 4 + kk) * Hn + 2 * lane);
                #pragma unroll
                for (int t = 0; t < KB_ROWT; t++) {
                    float yk = (kk == 0) ? yv[t].x : (kk == 1) ? yv[t].y
                             : (kk == 2) ? yv[t].z : yv[t].w;
                    fma2(acc2[t], pack_dup(yk), wv);
                }
            }
        }
        __syncwarp();

        // gate + blend + store
        #pragma unroll
        for (int t = 0; t < KB_ROWT; t++) {
            float s = gp[t];
            #pragma unroll
            for (int o = 16; o > 0; o >>= 1)
                s += __shfl_xor_sync(0xffffffffu, s, o);
            float z = s + gc[t];
            float g = 1.0f / (1.0f + __expf(-z));
            float2 f = unpack2(acc2[t]);
            float2 o2;
            o2.x = xl[t].x + g * (f.x - xl[t].x);
            o2.y = xl[t].y + g * (f.y - xl[t].y);
            ((float2*)(out + ((size_t)b * Rn + r0 + t) * Hn))[lane] = o2;
        }
    }
}

// ---------------------------------------------------------------------------
// Inputs: 0 query_relations, 1 edge_type, 2 base_relation_reprs, 3 init_noise,
// 4 msg_W, 5 msg_b, 6 upd_W, 7 upd_b, 8 ln_g, 9 ln_b, 10 fus_W1, 11 fus_b1,
// 12 fus_W2, 13 fus_b2, 14 gate_W, 15 gate_b
// ---------------------------------------------------------------------------
extern "C" void kernel_launch(void* const* d_in, const int* in_sizes, int n_in,
                              void* d_out, int out_size) {
    const int*   qrel   = (const int*)  d_in[0];
    const int*   etype  = (const int*)  d_in[1];
    const float* base   = (const float*)d_in[2];
    const float* noise  = (const float*)d_in[3];
    const float* msg_W  = (const float*)d_in[4];
    const float* msg_b  = (const float*)d_in[5];
    const float* upd_W  = (const float*)d_in[6];
    const float* upd_b  = (const float*)d_in[7];
    const float* ln_g   = (const float*)d_in[8];
    const float* ln_b   = (const float*)d_in[9];
    const float* fus_W1 = (const float*)d_in[10];
    const float* fus_b1 = (const float*)d_in[11];
    const float* fus_W2 = (const float*)d_in[12];
    const float* fus_b2 = (const float*)d_in[13];
    const float* gate_W = (const float*)d_in[14];
    const float* gate_b = (const float*)d_in[15];
    float* out = (float*)d_out;

    k0_constants<<<1, Hn>>>(upd_b, ln_g, ln_b, fus_W1, fus_b1, gate_W, gate_b);
    kA_prompts<<<Bn, Hn>>>(qrel, etype, noise, msg_W, msg_b,
                           upd_W, upd_b, ln_g, ln_b);
    kB_fuse<<<Bn * BLOCKS_PER_B, 256>>>(base, fus_W1, fus_b1, fus_W2, fus_b2,
                                        gate_W, gate_b, out);
}

// round 7
// speedup vs baseline: 2.0766x; 1.7877x over previous
#include <cuda_runtime.h>
#include <cuda_bf16.h>
#include <math.h>
#include <stdint.h>

#define Bn 256
#define Rn 2048
#define Hn 64
#define En 20
#define LN_EPSF 1e-5f

// device scratch (no allocs allowed)
__device__ __align__(16) float g_c1[Hn];
__device__ float g_cg;
__device__ signed char g_special[Bn * Rn];
__device__ __align__(16) float g_q1[Bn * En * Hn];
__device__ float g_qg[Bn * En];
// W1a / W2 pre-packed as mma.sync B fragments (hi/lo bf16 split)
// index: (kt*8 + nt)*32 + lane ; .x = {k0,k0+1}, .y = {k0+8,k0+9} at col n
__device__ __align__(16) uint2 g_W1fh[1024];
__device__ __align__(16) uint2 g_W1fl[1024];
__device__ __align__(16) uint2 g_W2fh[1024];
__device__ __align__(16) uint2 g_W2fl[1024];

static __device__ __forceinline__ uint32_t cvt_bf16x2(float e1, float e0) {
    uint32_t r;
    asm("cvt.rn.bf16x2.f32 %0, %1, %2;" : "=r"(r) : "f"(e1), "f"(e0));
    return r;
}
static __device__ __forceinline__ float bf_lo(uint32_t r) {
    return __uint_as_float(r << 16);
}
static __device__ __forceinline__ float bf_hi(uint32_t r) {
    return __uint_as_float(r & 0xFFFF0000u);
}
static __device__ __forceinline__ void mma_bf16(float* c, const uint32_t* a,
                                                uint32_t b0, uint32_t b1) {
    asm volatile(
        "mma.sync.aligned.m16n8k16.row.col.f32.bf16.bf16.f32 "
        "{%0,%1,%2,%3}, {%4,%5,%6,%7}, {%8,%9}, {%0,%1,%2,%3};"
        : "+f"(c[0]), "+f"(c[1]), "+f"(c[2]), "+f"(c[3])
        : "r"(a[0]), "r"(a[1]), "r"(a[2]), "r"(a[3]), "r"(b0), "r"(b1));
}

// ---------------------------------------------------------------------------
// PREP: blocks 0..255 = per-sample prompt pipeline -> q1/qg + special map.
//       block 256     = constants c1/cg + W fragment packing.
// ---------------------------------------------------------------------------
__global__ void prep_kernel(const int* __restrict__ qrel,
                            const int* __restrict__ etype,
                            const float* __restrict__ noise,
                            const float* __restrict__ msg_W,
                            const float* __restrict__ msg_b,
                            const float* __restrict__ upd_W,
                            const float* __restrict__ upd_b,
                            const float* __restrict__ ln_g,
                            const float* __restrict__ ln_b,
                            const float* __restrict__ fus_W1,
                            const float* __restrict__ fus_b1,
                            const float* __restrict__ fus_W2,
                            const float* __restrict__ gate_W,
                            const float* __restrict__ gate_b) {
    __shared__ __align__(16) float Wsum[Hn * Hn];
    __shared__ __align__(16) float Wupd[Hn * Hn];
    __shared__ __align__(16) float hs[En][Hn];
    __shared__ __align__(16) float ms[En][Hn];
    __shared__ int   er[En];
    __shared__ float red[2];
    __shared__ float p0s[Hn];

    int b = blockIdx.x;
    int j = threadIdx.x;   // 0..63

    if (b == Bn) {
        // constants: p0 = LN(upd_b)*g+b, then c1 / cg
        float u = upd_b[j];
        float s = u;
        #pragma unroll
        for (int o = 16; o > 0; o >>= 1) s += __shfl_xor_sync(~0u, s, o);
        if ((j & 31) == 0) red[j >> 5] = s;
        __syncthreads();
        float mu = (red[0] + red[1]) * (1.0f / Hn);
        __syncthreads();
        float d = u - mu;
        s = d * d;
        #pragma unroll
        for (int o = 16; o > 0; o >>= 1) s += __shfl_xor_sync(~0u, s, o);
        if ((j & 31) == 0) red[j >> 5] = s;
        __syncthreads();
        float var = (red[0] + red[1]) * (1.0f / Hn);
        float p = d * rsqrtf(var + LN_EPSF) * ln_g[j] + ln_b[j];
        p0s[j] = p;
        __syncthreads();

        float c = fus_b1[j];
        #pragma unroll 8
        for (int k = 0; k < Hn; k++)
            c = fmaf(p0s[k], fus_W1[(Hn + k) * Hn + j], c);
        g_c1[j] = c;

        s = p0s[j] * gate_W[Hn + j];
        #pragma unroll
        for (int o = 16; o > 0; o >>= 1) s += __shfl_xor_sync(~0u, s, o);
        __syncthreads();
        if ((j & 31) == 0) red[j >> 5] = s;
        __syncthreads();
        if (j == 0) g_cg = red[0] + red[1] + gate_b[0];

        // pack W1a / W2 into B-fragment order, bf16 hi/lo
        for (int idx = j; idx < 1024; idx += 64) {
            int lane = idx & 31;
            int tile = idx >> 5;
            int nt = tile & 7, kt = tile >> 3;
            int n  = nt * 8 + (lane >> 2);
            int k0 = kt * 16 + (lane & 3) * 2;

            {
                float w00 = fus_W1[k0 * Hn + n];
                float w01 = fus_W1[(k0 + 1) * Hn + n];
                float w08 = fus_W1[(k0 + 8) * Hn + n];
                float w09 = fus_W1[(k0 + 9) * Hn + n];
                uint32_t hx = cvt_bf16x2(w01, w00);
                uint32_t hy = cvt_bf16x2(w09, w08);
                uint32_t lx = cvt_bf16x2(w01 - bf_hi(hx), w00 - bf_lo(hx));
                uint32_t ly = cvt_bf16x2(w09 - bf_hi(hy), w08 - bf_lo(hy));
                g_W1fh[idx] = make_uint2(hx, hy);
                g_W1fl[idx] = make_uint2(lx, ly);
            }
            {
                float w00 = fus_W2[k0 * Hn + n];
                float w01 = fus_W2[(k0 + 1) * Hn + n];
                float w08 = fus_W2[(k0 + 8) * Hn + n];
                float w09 = fus_W2[(k0 + 9) * Hn + n];
                uint32_t hx = cvt_bf16x2(w01, w00);
                uint32_t hy = cvt_bf16x2(w09, w08);
                uint32_t lx = cvt_bf16x2(w01 - bf_hi(hx), w00 - bf_lo(hx));
                uint32_t ly = cvt_bf16x2(w09 - bf_hi(hy), w08 - bf_lo(hy));
                g_W2fh[idx] = make_uint2(hx, hy);
                g_W2fl[idx] = make_uint2(lx, ly);
            }
        }
        return;
    }

    // per-sample prompt pipeline
    for (int idx = j; idx < Hn * Hn; idx += 64) {
        Wsum[idx] = msg_W[idx] + msg_W[Hn * Hn + idx];
        Wupd[idx] = upd_W[idx];
    }
    if (j < En) er[j] = etype[b * En + j];
    {
        int* sm = (int*)(g_special + (size_t)b * Rn);
        for (int idx = j; idx < Rn / 4; idx += 64) sm[idx] = -1;
    }
    __syncthreads();
    if (j < En) g_special[(size_t)b * Rn + er[j]] = (signed char)j;

    int qr = qrel[b];
    for (int e = 0; e < En; e++) {
        int r = er[e];
        hs[e][j] = (r == qr) ? 1.0f : noise[((size_t)b * Rn + r) * Hn + j] * 0.1f;
    }
    __syncthreads();

    for (int e = 0; e < En; e++) {
        float m = msg_b[j];
        #pragma unroll 8
        for (int k = 0; k < Hn; k++) m = fmaf(hs[e][k], Wsum[k * Hn + j], m);
        ms[e][j] = fmaxf(m, 0.0f);
    }
    __syncthreads();

    float aggv[En];
    for (int e = 0; e < En; e++) {
        float a = 0.0f;
        for (int e2 = 0; e2 < En; e2++)
            if (er[e2] == er[e]) a += ms[e2][j];
        aggv[e] = a;
    }
    __syncthreads();
    for (int e = 0; e < En; e++) hs[e][j] = aggv[e];
    __syncthreads();

    for (int e = 0; e < En; e++) {
        float u = upd_b[j];
        #pragma unroll 8
        for (int k = 0; k < Hn; k++) u = fmaf(hs[e][k], Wupd[k * Hn + j], u);

        float s = u;
        #pragma unroll
        for (int o = 16; o > 0; o >>= 1) s += __shfl_xor_sync(~0u, s, o);
        if ((j & 31) == 0) red[j >> 5] = s;
        __syncthreads();
        float mu = (red[0] + red[1]) * (1.0f / Hn);
        __syncthreads();

        float d = u - mu;
        s = d * d;
        #pragma unroll
        for (int o = 16; o > 0; o >>= 1) s += __shfl_xor_sync(~0u, s, o);
        if ((j & 31) == 0) red[j >> 5] = s;
        __syncthreads();
        float var = (red[0] + red[1]) * (1.0f / Hn);

        ms[e][j] = d * rsqrtf(var + LN_EPSF) * ln_g[j] + ln_b[j];
        __syncthreads();
    }

    for (int idx = j; idx < Hn * Hn; idx += 64)
        Wsum[idx] = fus_W1[Hn * Hn + idx];   // W1b
    __syncthreads();

    for (int e = 0; e < En; e++) {
        float q = fus_b1[j];
        #pragma unroll 8
        for (int k = 0; k < Hn; k++) q = fmaf(ms[e][k], Wsum[k * Hn + j], q);
        g_q1[((size_t)b * En + e) * Hn + j] = q;

        float s = ms[e][j] * gate_W[Hn + j];
        #pragma unroll
        for (int o = 16; o > 0; o >>= 1) s += __shfl_xor_sync(~0u, s, o);
        if ((j & 31) == 0) red[j >> 5] = s;
        __syncthreads();
        if (j == 0) g_qg[b * En + e] = red[0] + red[1] + gate_b[0];
        __syncthreads();
    }
}

// ---------------------------------------------------------------------------
// KB: mma.sync fused MLP. One CTA = 128 rows; 8 warps, one 16-row slab each.
// bf16 hi/lo 3-MMA split per GEMM. D1 fragments chain directly into A2 frags.
// ---------------------------------------------------------------------------
#define TILE_M 128
#define NTHR   256
#define XPAD   68
#define OFF_XF   0
#define OFF_W1H  34816
#define OFF_W1L  43008
#define OFF_W2H  51200
#define OFF_W2L  59392
#define OFF_GZ   67584
#define OFF_GWA  68096
#define OFF_B2   68352
#define SMEM_TOTAL 68608

__global__ __launch_bounds__(NTHR, 2)
void kB_mma(const float* __restrict__ base,
            const float* __restrict__ fus_b2,
            const float* __restrict__ gate_W,
            float* __restrict__ out) {
    extern __shared__ __align__(16) char sm[];
    float* XF  = (float*)(sm + OFF_XF);
    const uint2* W1H = (const uint2*)(sm + OFF_W1H);
    const uint2* W1L = (const uint2*)(sm + OFF_W1L);
    const uint2* W2H = (const uint2*)(sm + OFF_W2H);
    const uint2* W2L = (const uint2*)(sm + OFF_W2L);
    float* GZ  = (float*)(sm + OFF_GZ);
    float* GWA = (float*)(sm + OFF_GWA);
    float* B2S = (float*)(sm + OFF_B2);

    const int tid = threadIdx.x;
    const int b   = blockIdx.x >> 4;
    const int r0  = (blockIdx.x & 15) * TILE_M;
    const int w = tid >> 5, lane = tid & 31;
    const int g = lane >> 2, tig = lane & 3;

    // stage x tile (coalesced LDG.128 -> padded fp32 smem)
    {
        const float4* xin = (const float4*)(base + ((size_t)(b * Rn + r0)) * Hn);
        #pragma unroll
        for (int s = 0; s < 8; s++) {
            int idx = tid + s * NTHR;
            ((float4*)XF)[(idx >> 4) * 17 + (idx & 15)] = xin[idx];
        }
    }
    // stage W fragments (L2-resident)
    {
        ((uint4*)(sm + OFF_W1H))[tid]       = ((const uint4*)g_W1fh)[tid];
        ((uint4*)(sm + OFF_W1H))[tid + 256] = ((const uint4*)g_W1fh)[tid + 256];
        ((uint4*)(sm + OFF_W1L))[tid]       = ((const uint4*)g_W1fl)[tid];
        ((uint4*)(sm + OFF_W1L))[tid + 256] = ((const uint4*)g_W1fl)[tid + 256];
        ((uint4*)(sm + OFF_W2H))[tid]       = ((const uint4*)g_W2fh)[tid];
        ((uint4*)(sm + OFF_W2H))[tid + 256] = ((const uint4*)g_W2fh)[tid + 256];
        ((uint4*)(sm + OFF_W2L))[tid]       = ((const uint4*)g_W2fl)[tid];
        ((uint4*)(sm + OFF_W2L))[tid + 256] = ((const uint4*)g_W2fl)[tid + 256];
    }
    if (tid < 16) ((float4*)GWA)[tid] = ((const float4*)gate_W)[tid];
    if (tid >= 16 && tid < 32) ((float4*)B2S)[tid - 16] = ((const float4*)fus_b2)[tid - 16];
    __syncthreads();

    // gate dot: 4 threads per row, 2 rows per thread-iteration
    #pragma unroll
    for (int it = 0; it < 2; it++) {
        int slot = tid + it * NTHR;
        int row = slot >> 2, seg = slot & 3;
        const float4* xr = (const float4*)(XF + row * XPAD) + seg * 4;
        const float4* gw = (const float4*)GWA + seg * 4;
        float s = 0.0f;
        #pragma unroll
        for (int jj = 0; jj < 4; jj++) {
            float4 xv = xr[jj], wv = gw[jj];
            s += xv.x * wv.x + xv.y * wv.y + xv.z * wv.z + xv.w * wv.w;
        }
        s += __shfl_xor_sync(~0u, s, 1);
        s += __shfl_xor_sync(~0u, s, 2);
        if (seg == 0) {
            int sp = g_special[(size_t)b * Rn + r0 + row];
            float c = (sp < 0) ? g_cg : g_qg[b * En + sp];
            GZ[row] = s + c;
        }
    }
    __syncthreads();

    const int ra = (w << 4) + g;   // local rows of this thread's fragments
    const int rb = ra + 8;

    // A1 fragments from XF (hi/lo split)
    uint32_t ahi[4][4], alo[4][4];
    #pragma unroll
    for (int kt = 0; kt < 4; kt++) {
        int c0 = kt * 16 + 2 * tig;
        float2 p00 = *(const float2*)(XF + ra * XPAD + c0);
        float2 p10 = *(const float2*)(XF + rb * XPAD + c0);
        float2 p01 = *(const float2*)(XF + ra * XPAD + c0 + 8);
        float2 p11 = *(const float2*)(XF + rb * XPAD + c0 + 8);
        ahi[kt][0] = cvt_bf16x2(p00.y, p00.x);
        ahi[kt][1] = cvt_bf16x2(p10.y, p10.x);
        ahi[kt][2] = cvt_bf16x2(p01.y, p01.x);
        ahi[kt][3] = cvt_bf16x2(p11.y, p11.x);
        alo[kt][0] = cvt_bf16x2(p00.y - bf_hi(ahi[kt][0]), p00.x - bf_lo(ahi[kt][0]));
        alo[kt][1] = cvt_bf16x2(p10.y - bf_hi(ahi[kt][1]), p10.x - bf_lo(ahi[kt][1]));
        alo[kt][2] = cvt_bf16x2(p01.y - bf_hi(ahi[kt][2]), p01.x - bf_lo(ahi[kt][2]));
        alo[kt][3] = cvt_bf16x2(p11.y - bf_hi(ahi[kt][3]), p11.x - bf_lo(ahi[kt][3]));
    }

    // GEMM1
    float acc[8][4];
    #pragma unroll
    for (int nt = 0; nt < 8; nt++) {
        acc[nt][0] = acc[nt][1] = acc[nt][2] = acc[nt][3] = 0.0f;
        #pragma unroll
        for (int kt = 0; kt < 4; kt++) {
            uint2 bh = W1H[(kt * 8 + nt) * 32 + lane];
            uint2 bl = W1L[(kt * 8 + nt) * 32 + lane];
            mma_bf16(acc[nt], ahi[kt], bh.x, bh.y);
            mma_bf16(acc[nt], ahi[kt], bl.x, bl.y);
            mma_bf16(acc[nt], alo[kt], bh.x, bh.y);
        }
    }

    // epilogue1: bias (+special), relu, repack as A2 fragments
    int spa = g_special[(size_t)b * Rn + r0 + ra];
    int spb = g_special[(size_t)b * Rn + r0 + rb];
    const float* pa = (spa < 0) ? g_c1 : g_q1 + (((size_t)b * En + spa) << 6);
    const float* pb = (spb < 0) ? g_c1 : g_q1 + (((size_t)b * En + spb) << 6);

    uint32_t yhi[4][4], ylo[4][4];
    #pragma unroll
    for (int kt2 = 0; kt2 < 4; kt2++) {
        #pragma unroll
        for (int half = 0; half < 2; half++) {
            int nt = kt2 * 2 + half;
            int col = nt * 8 + 2 * tig;
            float2 ba = *(const float2*)(pa + col);
            float2 bb = *(const float2*)(pb + col);
            float y0 = fmaxf(acc[nt][0] + ba.x, 0.0f);
            float y1 = fmaxf(acc[nt][1] + ba.y, 0.0f);
            float y2 = fmaxf(acc[nt][2] + bb.x, 0.0f);
            float y3 = fmaxf(acc[nt][3] + bb.y, 0.0f);
            uint32_t h0 = cvt_bf16x2(y1, y0);
            uint32_t h1 = cvt_bf16x2(y3, y2);
            yhi[kt2][half * 2 + 0] = h0;
            yhi[kt2][half * 2 + 1] = h1;
            ylo[kt2][half * 2 + 0] = cvt_bf16x2(y1 - bf_hi(h0), y0 - bf_lo(h0));
            ylo[kt2][half * 2 + 1] = cvt_bf16x2(y3 - bf_hi(h1), y2 - bf_lo(h1));
        }
    }

    // GEMM2
    float acc2[8][4];
    #pragma unroll
    for (int nt = 0; nt < 8; nt++) {
        acc2[nt][0] = acc2[nt][1] = acc2[nt][2] = acc2[nt][3] = 0.0f;
        #pragma unroll
        for (int kt = 0; kt < 4; kt++) {
            uint2 bh = W2H[(kt * 8 + nt) * 32 + lane];
            uint2 bl = W2L[(kt * 8 + nt) * 32 + lane];
            mma_bf16(acc2[nt], yhi[kt], bh.x, bh.y);
            mma_bf16(acc2[nt], yhi[kt], bl.x, bl.y);
            mma_bf16(acc2[nt], ylo[kt], bh.x, bh.y);
        }
    }

    // epilogue2: f = D2 + b2; out = x + g*(f - x); blend into XF
    {
        float ga = 1.0f / (1.0f + __expf(-GZ[ra]));
        float gb = 1.0f / (1.0f + __expf(-GZ[rb]));
        #pragma unroll
        for (int nt = 0; nt < 8; nt++) {
            int col = nt * 8 + 2 * tig;
            float2 b2v = *(const float2*)(B2S + col);
            float2 xa = *(const float2*)(XF + ra * XPAD + col);
            float2 xb = *(const float2*)(XF + rb * XPAD + col);
            float f0 = acc2[nt][0] + b2v.x;
            float f1 = acc2[nt][1] + b2v.y;
            float f2 = acc2[nt][2] + b2v.x;
            float f3 = acc2[nt][3] + b2v.y;
            xa.x += ga * (f0 - xa.x);
            xa.y += ga * (f1 - xa.y);
            xb.x += gb * (f2 - xb.x);
            xb.y += gb * (f3 - xb.y);
            *(float2*)(XF + ra * XPAD + col) = xa;
            *(float2*)(XF + rb * XPAD + col) = xb;
        }
    }
    __syncthreads();

    // coalesced store
    {
        float4* dst = (float4*)(out + ((size_t)(b * Rn + r0)) * Hn);
        #pragma unroll
        for (int s = 0; s < 8; s++) {
            int idx = tid + s * NTHR;
            dst[idx] = ((const float4*)XF)[(idx >> 4) * 17 + (idx & 15)];
        }
    }
}

// ---------------------------------------------------------------------------
extern "C" void kernel_launch(void* const* d_in, const int* in_sizes, int n_in,
                              void* d_out, int out_size) {
    const int*   qrel   = (const int*)  d_in[0];
    const int*   etype  = (const int*)  d_in[1];
    const float* base   = (const float*)d_in[2];
    const float* noise  = (const float*)d_in[3];
    const float* msg_W  = (const float*)d_in[4];
    const float* msg_b  = (const float*)d_in[5];
    const float* upd_W  = (const float*)d_in[6];
    const float* upd_b  = (const float*)d_in[7];
    const float* ln_g   = (const float*)d_in[8];
    const float* ln_b   = (const float*)d_in[9];
    const float* fus_W1 = (const float*)d_in[10];
    const float* fus_b1 = (const float*)d_in[11];
    const float* fus_W2 = (const float*)d_in[12];
    const float* fus_b2 = (const float*)d_in[13];
    const float* gate_W = (const float*)d_in[14];
    const float* gate_b = (const float*)d_in[15];
    float* out = (float*)d_out;

    prep_kernel<<<Bn + 1, Hn>>>(qrel, etype, noise, msg_W, msg_b, upd_W, upd_b,
                                ln_g, ln_b, fus_W1, fus_b1, fus_W2, gate_W, gate_b);

    cudaFuncSetAttribute(kB_mma, cudaFuncAttributeMaxDynamicSharedMemorySize,
                         SMEM_TOTAL);
    kB_mma<<<Bn * (Rn / TILE_M), NTHR, SMEM_TOTAL>>>(base, fus_b2, gate_W, out);
}

// round 8
// speedup vs baseline: 2.4567x; 1.1830x over previous
#include <cuda_runtime.h>
#include <cuda_bf16.h>
#include <math.h>
#include <stdint.h>

#define Bn 256
#define Rn 2048
#define Hn 64
#define En 20
#define LN_EPSF 1e-5f

// device scratch (no allocs allowed)
__device__ __align__(16) float g_c1[Hn];
__device__ float g_cg;
__device__ signed char g_special[Bn * Rn];
__device__ __align__(16) float g_q1[Bn * En * Hn];
__device__ float g_qg[Bn * En];
// W1a / W2 pre-packed as mma.sync B fragments (hi/lo bf16 split)
__device__ __align__(16) uint2 g_W1fh[1024];
__device__ __align__(16) uint2 g_W1fl[1024];
__device__ __align__(16) uint2 g_W2fh[1024];
__device__ __align__(16) uint2 g_W2fl[1024];

static __device__ __forceinline__ uint32_t cvt_bf16x2(float e1, float e0) {
    uint32_t r;
    asm("cvt.rn.bf16x2.f32 %0, %1, %2;" : "=r"(r) : "f"(e1), "f"(e0));
    return r;
}
static __device__ __forceinline__ float bf_lo(uint32_t r) {
    return __uint_as_float(r << 16);
}
static __device__ __forceinline__ float bf_hi(uint32_t r) {
    return __uint_as_float(r & 0xFFFF0000u);
}
static __device__ __forceinline__ void mma_bf16(float* c, const uint32_t* a,
                                                uint32_t b0, uint32_t b1) {
    asm volatile(
        "mma.sync.aligned.m16n8k16.row.col.f32.bf16.bf16.f32 "
        "{%0,%1,%2,%3}, {%4,%5,%6,%7}, {%8,%9}, {%0,%1,%2,%3};"
        : "+f"(c[0]), "+f"(c[1]), "+f"(c[2]), "+f"(c[3])
        : "r"(a[0]), "r"(a[1]), "r"(a[2]), "r"(a[3]), "r"(b0), "r"(b1));
}

// ---------------------------------------------------------------------------
// PREP (256 threads/block): blocks 0..255 = per-sample prompts -> q1/qg/special.
// block 256 = constants c1/cg + W fragment packing.
// Edge loops 4-way parallel (eg = tid>>6); LN/gate reductions per-warp.
// ---------------------------------------------------------------------------
__global__ __launch_bounds__(256)
void prep_kernel(const int* __restrict__ qrel,
                 const int* __restrict__ etype,
                 const float* __restrict__ noise,
                 const float* __restrict__ msg_W,
                 const float* __restrict__ msg_b,
                 const float* __restrict__ upd_W,
                 const float* __restrict__ upd_b,
                 const float* __restrict__ ln_g,
                 const float* __restrict__ ln_b,
                 const float* __restrict__ fus_W1,
                 const float* __restrict__ fus_b1,
                 const float* __restrict__ fus_W2,
                 const float* __restrict__ gate_W,
                 const float* __restrict__ gate_b) {
    __shared__ __align__(16) float Wsum[Hn * Hn];
    __shared__ __align__(16) float Wupd[Hn * Hn];
    __shared__ __align__(16) float hs[En][Hn];
    __shared__ __align__(16) float ms[En][Hn];
    __shared__ int   er[En];
    __shared__ __align__(16) float p0s[Hn];

    const int b   = blockIdx.x;
    const int tid = threadIdx.x;
    const int j   = tid & 63;      // 0..63 (H dim)
    const int eg  = tid >> 6;      // 0..3 (edge group)
    const int w   = tid >> 5, lane = tid & 31;

    if (b == Bn) {
        // p0 = LN(upd_b)*g+b, computed by warp 0 (2 values per lane)
        if (w == 0) {
            float v0 = upd_b[lane], v1 = upd_b[lane + 32];
            float s = v0 + v1;
            #pragma unroll
            for (int o = 16; o > 0; o >>= 1) s += __shfl_xor_sync(~0u, s, o);
            float mu = s * (1.0f / Hn);
            float d0 = v0 - mu, d1 = v1 - mu;
            s = d0 * d0 + d1 * d1;
            #pragma unroll
            for (int o = 16; o > 0; o >>= 1) s += __shfl_xor_sync(~0u, s, o);
            float inv = rsqrtf(s * (1.0f / Hn) + LN_EPSF);
            p0s[lane]      = d0 * inv * ln_g[lane] + ln_b[lane];
            p0s[lane + 32] = d1 * inv * ln_g[lane + 32] + ln_b[lane + 32];
        }
        __syncthreads();

        if (tid < Hn) {
            float c = fus_b1[tid];
            #pragma unroll 8
            for (int k = 0; k < Hn; k++)
                c = fmaf(p0s[k], fus_W1[(Hn + k) * Hn + tid], c);
            g_c1[tid] = c;
        }
        if (w == 0) {
            float s = p0s[lane] * gate_W[Hn + lane]
                    + p0s[lane + 32] * gate_W[Hn + lane + 32];
            #pragma unroll
            for (int o = 16; o > 0; o >>= 1) s += __shfl_xor_sync(~0u, s, o);
            if (lane == 0) g_cg = s + gate_b[0];
        }

        // pack W1a / W2 into B-fragment order, bf16 hi/lo
        for (int idx = tid; idx < 1024; idx += 256) {
            int l = idx & 31;
            int tile = idx >> 5;
            int nt = tile & 7, kt = tile >> 3;
            int n  = nt * 8 + (l >> 2);
            int k0 = kt * 16 + (l & 3) * 2;
            {
                float w00 = fus_W1[k0 * Hn + n];
                float w01 = fus_W1[(k0 + 1) * Hn + n];
                float w08 = fus_W1[(k0 + 8) * Hn + n];
                float w09 = fus_W1[(k0 + 9) * Hn + n];
                uint32_t hx = cvt_bf16x2(w01, w00);
                uint32_t hy = cvt_bf16x2(w09, w08);
                g_W1fh[idx] = make_uint2(hx, hy);
                g_W1fl[idx] = make_uint2(
                    cvt_bf16x2(w01 - bf_hi(hx), w00 - bf_lo(hx)),
                    cvt_bf16x2(w09 - bf_hi(hy), w08 - bf_lo(hy)));
            }
            {
                float w00 = fus_W2[k0 * Hn + n];
                float w01 = fus_W2[(k0 + 1) * Hn + n];
                float w08 = fus_W2[(k0 + 8) * Hn + n];
                float w09 = fus_W2[(k0 + 9) * Hn + n];
                uint32_t hx = cvt_bf16x2(w01, w00);
                uint32_t hy = cvt_bf16x2(w09, w08);
                g_W2fh[idx] = make_uint2(hx, hy);
                g_W2fl[idx] = make_uint2(
                    cvt_bf16x2(w01 - bf_hi(hx), w00 - bf_lo(hx)),
                    cvt_bf16x2(w09 - bf_hi(hy), w08 - bf_lo(hy)));
            }
        }
        return;
    }

    // ---- per-sample prompt pipeline (4-way edge parallel) ----
    for (int idx = tid; idx < Hn * Hn; idx += 256) {
        Wsum[idx] = msg_W[idx] + msg_W[Hn * Hn + idx];
        Wupd[idx] = upd_W[idx];
    }
    if (tid < En) er[tid] = etype[b * En + tid];
    {
        int* sp = (int*)(g_special + (size_t)b * Rn);
        for (int idx = tid; idx < Rn / 4; idx += 256) sp[idx] = -1;
    }
    __syncthreads();
    if (tid < En) g_special[(size_t)b * Rn + er[tid]] = (signed char)tid;

    int qr = qrel[b];
    for (int e = eg; e < En; e += 4) {
        int r = er[e];
        hs[e][j] = (r == qr) ? 1.0f : noise[((size_t)b * Rn + r) * Hn + j] * 0.1f;
    }
    __syncthreads();

    // msg = relu(h @ Wsum + msg_b)
    for (int e = eg; e < En; e += 4) {
        float m = msg_b[j];
        #pragma unroll 8
        for (int k = 0; k < Hn; k++) m = fmaf(hs[e][k], Wsum[k * Hn + j], m);
        ms[e][j] = fmaxf(m, 0.0f);
    }
    __syncthreads();

    // agg (reads ms, writes hs); restage Wsum <- W1b for later q1 use
    for (int e = eg; e < En; e += 4) {
        float a = 0.0f;
        int re = er[e];
        #pragma unroll
        for (int e2 = 0; e2 < En; e2++)
            if (er[e2] == re) a += ms[e2][j];
        hs[e][j] = a;
    }
    for (int idx = tid; idx < Hn * Hn; idx += 256)
        Wsum[idx] = fus_W1[Hn * Hn + idx];
    __syncthreads();

    // upd = agg @ Wupd + upd_b  (reads hs, writes ms)
    for (int e = eg; e < En; e += 4) {
        float u = upd_b[j];
        #pragma unroll 8
        for (int k = 0; k < Hn; k++) u = fmaf(hs[e][k], Wupd[k * Hn + j], u);
        ms[e][j] = u;
    }
    __syncthreads();

    // LayerNorm per edge, one warp per edge (2 values per lane), in place
    for (int e = w; e < En; e += 8) {
        float v0 = ms[e][lane], v1 = ms[e][lane + 32];
        float s = v0 + v1;
        #pragma unroll
        for (int o = 16; o > 0; o >>= 1) s += __shfl_xor_sync(~0u, s, o);
        float mu = s * (1.0f / Hn);
        float d0 = v0 - mu, d1 = v1 - mu;
        s = d0 * d0 + d1 * d1;
        #pragma unroll
        for (int o = 16; o > 0; o >>= 1) s += __shfl_xor_sync(~0u, s, o);
        float inv = rsqrtf(s * (1.0f / Hn) + LN_EPSF);
        ms[e][lane]      = d0 * inv * ln_g[lane] + ln_b[lane];
        ms[e][lane + 32] = d1 * inv * ln_g[lane + 32] + ln_b[lane + 32];
    }
    __syncthreads();

    // q1 = fus_b1 + prompt @ W1b ; qg = prompt . gWb + gate_b
    for (int e = eg; e < En; e += 4) {
        float q = fus_b1[j];
        #pragma unroll 8
        for (int k = 0; k < Hn; k++) q = fmaf(ms[e][k], Wsum[k * Hn + j], q);
        g_q1[((size_t)b * En + e) * Hn + j] = q;
    }
    for (int e = w; e < En; e += 8) {
        float s = ms[e][lane] * gate_W[Hn + lane]
                + ms[e][lane + 32] * gate_W[Hn + lane + 32];
        #pragma unroll
        for (int o = 16; o > 0; o >>= 1) s += __shfl_xor_sync(~0u, s, o);
        if (lane == 0) g_qg[b * En + e] = s + gate_b[0];
    }
}

// ---------------------------------------------------------------------------
// KB: mma.sync fused MLP. One CTA = 128 rows; 4 warps, 32 rows (2 m16 slabs)
// each. Each W-fragment LDS feeds 6 MMAs (3-way hi/lo split x 2 slabs).
// ---------------------------------------------------------------------------
#define TILE_M 128
#define NTHR   128
#define XPAD   68
#define OFF_XF   0
#define OFF_W1H  34816
#define OFF_W1L  43008
#define OFF_W2H  51200
#define OFF_W2L  59392
#define OFF_GZ   67584
#define OFF_GWA  68096
#define OFF_B2   68352
#define SMEM_TOTAL 68608

__global__ __launch_bounds__(NTHR)
void kB_mma(const float* __restrict__ base,
            const float* __restrict__ fus_b2,
            const float* __restrict__ gate_W,
            float* __restrict__ out) {
    extern __shared__ __align__(16) char sm[];
    float* XF  = (float*)(sm + OFF_XF);
    const uint2* W1H = (const uint2*)(sm + OFF_W1H);
    const uint2* W1L = (const uint2*)(sm + OFF_W1L);
    const uint2* W2H = (const uint2*)(sm + OFF_W2H);
    const uint2* W2L = (const uint2*)(sm + OFF_W2L);
    float* GZ  = (float*)(sm + OFF_GZ);
    float* GWA = (float*)(sm + OFF_GWA);
    float* B2S = (float*)(sm + OFF_B2);

    const int tid = threadIdx.x;
    const int b   = blockIdx.x >> 4;
    const int r0  = (blockIdx.x & 15) * TILE_M;
    const int w = tid >> 5, lane = tid & 31;
    const int g = lane >> 2, tig = lane & 3;

    // stage x tile (coalesced)
    {
        const float4* xin = (const float4*)(base + ((size_t)(b * Rn + r0)) * Hn);
        #pragma unroll
        for (int s = 0; s < 16; s++) {
            int idx = tid + s * NTHR;
            ((float4*)XF)[(idx >> 4) * 17 + (idx & 15)] = xin[idx];
        }
    }
    // stage W fragments (L2-resident)
    {
        #pragma unroll
        for (int s = 0; s < 4; s++) {
            int idx = tid + s * NTHR;
            ((uint4*)(sm + OFF_W1H))[idx] = ((const uint4*)g_W1fh)[idx];
            ((uint4*)(sm + OFF_W1L))[idx] = ((const uint4*)g_W1fl)[idx];
            ((uint4*)(sm + OFF_W2H))[idx] = ((const uint4*)g_W2fh)[idx];
            ((uint4*)(sm + OFF_W2L))[idx] = ((const uint4*)g_W2fl)[idx];
        }
    }
    if (tid < 16) ((float4*)GWA)[tid] = ((const float4*)gate_W)[tid];
    if (tid >= 16 && tid < 32) ((float4*)B2S)[tid - 16] = ((const float4*)fus_b2)[tid - 16];
    __syncthreads();

    // gate dot: one thread per row
    {
        int row = tid;
        const float4* xr = (const float4*)(XF + row * XPAD);
        const float4* gw = (const float4*)GWA;
        float s = 0.0f;
        #pragma unroll
        for (int jj = 0; jj < 16; jj++) {
            float4 xv = xr[jj], wv = gw[jj];
            s += xv.x * wv.x + xv.y * wv.y + xv.z * wv.z + xv.w * wv.w;
        }
        int sp = g_special[(size_t)b * Rn + r0 + row];
        GZ[row] = s + ((sp < 0) ? g_cg : g_qg[b * En + sp]);
    }
    __syncthreads();

    const int ra = (w << 5) + g;   // slab0 rows: ra, ra+8; slab1: ra+16, ra+24

    // A1 fragments (hi/lo split), 2 slabs
    uint32_t ahi[2][4][4], alo[2][4][4];
    #pragma unroll
    for (int s2 = 0; s2 < 2; s2++) {
        int rA = ra + s2 * 16, rB = rA + 8;
        #pragma unroll
        for (int kt = 0; kt < 4; kt++) {
            int c0 = kt * 16 + 2 * tig;
            float2 p00 = *(const float2*)(XF + rA * XPAD + c0);
            float2 p10 = *(const float2*)(XF + rB * XPAD + c0);
            float2 p01 = *(const float2*)(XF + rA * XPAD + c0 + 8);
            float2 p11 = *(const float2*)(XF + rB * XPAD + c0 + 8);
            uint32_t h0 = cvt_bf16x2(p00.y, p00.x);
            uint32_t h1 = cvt_bf16x2(p10.y, p10.x);
            uint32_t h2 = cvt_bf16x2(p01.y, p01.x);
            uint32_t h3 = cvt_bf16x2(p11.y, p11.x);
            ahi[s2][kt][0] = h0; ahi[s2][kt][1] = h1;
            ahi[s2][kt][2] = h2; ahi[s2][kt][3] = h3;
            alo[s2][kt][0] = cvt_bf16x2(p00.y - bf_hi(h0), p00.x - bf_lo(h0));
            alo[s2][kt][1] = cvt_bf16x2(p10.y - bf_hi(h1), p10.x - bf_lo(h1));
            alo[s2][kt][2] = cvt_bf16x2(p01.y - bf_hi(h2), p01.x - bf_lo(h2));
            alo[s2][kt][3] = cvt_bf16x2(p11.y - bf_hi(h3), p11.x - bf_lo(h3));
        }
    }

    // GEMM1: each W load feeds 6 MMAs
    float acc[2][8][4];
    #pragma unroll
    for (int s2 = 0; s2 < 2; s2++)
        #pragma unroll
        for (int nt = 0; nt < 8; nt++)
            acc[s2][nt][0] = acc[s2][nt][1] = acc[s2][nt][2] = acc[s2][nt][3] = 0.0f;
    #pragma unroll
    for (int nt = 0; nt < 8; nt++) {
        #pragma unroll
        for (int kt = 0; kt < 4; kt++) {
            uint2 bh = W1H[(kt * 8 + nt) * 32 + lane];
            uint2 bl = W1L[(kt * 8 + nt) * 32 + lane];
            #pragma unroll
            for (int s2 = 0; s2 < 2; s2++) {
                mma_bf16(acc[s2][nt], ahi[s2][kt], bh.x, bh.y);
                mma_bf16(acc[s2][nt], ahi[s2][kt], bl.x, bl.y);
                mma_bf16(acc[s2][nt], alo[s2][kt], bh.x, bh.y);
            }
        }
    }

    // epilogue1: bias (+special), relu, repack as A2 fragments
    uint32_t yhi[2][4][4], ylo[2][4][4];
    #pragma unroll
    for (int s2 = 0; s2 < 2; s2++) {
        int rA = ra + s2 * 16, rB = rA + 8;
        int spa = g_special[(size_t)b * Rn + r0 + rA];
        int spb = g_special[(size_t)b * Rn + r0 + rB];
        const float* pa = (spa < 0) ? g_c1 : g_q1 + (((size_t)b * En + spa) << 6);
        const float* pb = (spb < 0) ? g_c1 : g_q1 + (((size_t)b * En + spb) << 6);
        #pragma unroll
        for (int kt2 = 0; kt2 < 4; kt2++) {
            #pragma unroll
            for (int half = 0; half < 2; half++) {
                int nt = kt2 * 2 + half;
                int col = nt * 8 + 2 * tig;
                float2 ba = *(const float2*)(pa + col);
                float2 bb = *(const float2*)(pb + col);
                float y0 = fmaxf(acc[s2][nt][0] + ba.x, 0.0f);
                float y1 = fmaxf(acc[s2][nt][1] + ba.y, 0.0f);
                float y2 = fmaxf(acc[s2][nt][2] + bb.x, 0.0f);
                float y3 = fmaxf(acc[s2][nt][3] + bb.y, 0.0f);
                uint32_t h0 = cvt_bf16x2(y1, y0);
                uint32_t h1 = cvt_bf16x2(y3, y2);
                yhi[s2][kt2][half * 2 + 0] = h0;
                yhi[s2][kt2][half * 2 + 1] = h1;
                ylo[s2][kt2][half * 2 + 0] = cvt_bf16x2(y1 - bf_hi(h0), y0 - bf_lo(h0));
                ylo[s2][kt2][half * 2 + 1] = cvt_bf16x2(y3 - bf_hi(h1), y2 - bf_lo(h1));
            }
        }
    }

    // GEMM2
    float acc2[2][8][4];
    #pragma unroll
    for (int s2 = 0; s2 < 2; s2++)
        #pragma unroll
        for (int nt = 0; nt < 8; nt++)
            acc2[s2][nt][0] = acc2[s2][nt][1] = acc2[s2][nt][2] = acc2[s2][nt][3] = 0.0f;
    #pragma unroll
    for (int nt = 0; nt < 8; nt++) {
        #pragma unroll
        for (int kt = 0; kt < 4; kt++) {
            uint2 bh = W2H[(kt * 8 + nt) * 32 + lane];
            uint2 bl = W2L[(kt * 8 + nt) * 32 + lane];
            #pragma unroll
            for (int s2 = 0; s2 < 2; s2++) {
                mma_bf16(acc2[s2][nt], yhi[s2][kt], bh.x, bh.y);
                mma_bf16(acc2[s2][nt], yhi[s2][kt], bl.x, bl.y);
                mma_bf16(acc2[s2][nt], ylo[s2][kt], bh.x, bh.y);
            }
        }
    }

    // epilogue2: f = D2 + b2; out = x + g*(f - x); blend into XF (warp-local rows)
    #pragma unroll
    for (int s2 = 0; s2 < 2; s2++) {
        int rA = ra + s2 * 16, rB = rA + 8;
        float ga = 1.0f / (1.0f + __expf(-GZ[rA]));
        float gb = 1.0f / (1.0f + __expf(-GZ[rB]));
        #pragma unroll
        for (int nt = 0; nt < 8; nt++) {
            int col = nt * 8 + 2 * tig;
            float2 b2v = *(const float2*)(B2S + col);
            float2 xa = *(const float2*)(XF + rA * XPAD + col);
            float2 xb = *(const float2*)(XF + rB * XPAD + col);
            float f0 = acc2[s2][nt][0] + b2v.x;
            float f1 = acc2[s2][nt][1] + b2v.y;
            float f2 = acc2[s2][nt][2] + b2v.x;
            float f3 = acc2[s2][nt][3] + b2v.y;
            xa.x += ga * (f0 - xa.x);
            xa.y += ga * (f1 - xa.y);
            xb.x += gb * (f2 - xb.x);
            xb.y += gb * (f3 - xb.y);
            *(float2*)(XF + rA * XPAD + col) = xa;
            *(float2*)(XF + rB * XPAD + col) = xb;
        }
    }
    __syncthreads();

    // coalesced store
    {
        float4* dst = (float4*)(out + ((size_t)(b * Rn + r0)) * Hn);
        #pragma unroll
        for (int s = 0; s < 16; s++) {
            int idx = tid + s * NTHR;
            dst[idx] = ((const float4*)XF)[(idx >> 4) * 17 + (idx & 15)];
        }
    }
}

// ---------------------------------------------------------------------------
extern "C" void kernel_launch(void* const* d_in, const int* in_sizes, int n_in,
                              void* d_out, int out_size) {
    const int*   qrel   = (const int*)  d_in[0];
    const int*   etype  = (const int*)  d_in[1];
    const float* base   = (const float*)d_in[2];
    const float* noise  = (const float*)d_in[3];
    const float* msg_W  = (const float*)d_in[4];
    const float* msg_b  = (const float*)d_in[5];
    const float* upd_W  = (const float*)d_in[6];
    const float* upd_b  = (const float*)d_in[7];
    const float* ln_g   = (const float*)d_in[8];
    const float* ln_b   = (const float*)d_in[9];
    const float* fus_W1 = (const float*)d_in[10];
    const float* fus_b1 = (const float*)d_in[11];
    const float* fus_W2 = (const float*)d_in[12];
    const float* fus_b2 = (const float*)d_in[13];
    const float* gate_W = (const float*)d_in[14];
    const float* gate_b = (const float*)d_in[15];
    float* out = (float*)d_out;

    prep_kernel<<<Bn + 1, 256>>>(qrel, etype, noise, msg_W, msg_b, upd_W, upd_b,
                                 ln_g, ln_b, fus_W1, fus_b1, fus_W2, gate_W, gate_b);

    cudaFuncSetAttribute(kB_mma, cudaFuncAttributeMaxDynamicSharedMemorySize,
                         SMEM_TOTAL);
    kB_mma<<<Bn * (Rn / TILE_M), NTHR, SMEM_TOTAL>>>(base, fus_b2, gate_W, out);
}

// round 9
// speedup vs baseline: 2.4690x; 1.0050x over previous
#include <cuda_runtime.h>
#include <cuda_bf16.h>
#include <math.h>
#include <stdint.h>

#define Bn 256
#define Rn 2048
#define Hn 64
#define En 20
#define LN_EPSF 1e-5f

// device scratch (no allocs allowed)
__device__ __align__(16) float g_c1[Hn];
__device__ float g_cg;
__device__ __align__(16) float g_q1[Bn * En * Hn];
__device__ float g_qg[Bn * En];
__device__ __align__(16) uint2 g_W1fh[1024];
__device__ __align__(16) uint2 g_W1fl[1024];
__device__ __align__(16) uint2 g_W2fh[1024];
__device__ __align__(16) uint2 g_W2fl[1024];

static __device__ __forceinline__ uint32_t cvt_bf16x2(float e1, float e0) {
    uint32_t r;
    asm("cvt.rn.bf16x2.f32 %0, %1, %2;" : "=r"(r) : "f"(e1), "f"(e0));
    return r;
}
static __device__ __forceinline__ float bf_lo(uint32_t r) {
    return __uint_as_float(r << 16);
}
static __device__ __forceinline__ float bf_hi(uint32_t r) {
    return __uint_as_float(r & 0xFFFF0000u);
}
static __device__ __forceinline__ void mma_bf16(float* c, const uint32_t* a,
                                                uint32_t b0, uint32_t b1) {
    asm volatile(
        "mma.sync.aligned.m16n8k16.row.col.f32.bf16.bf16.f32 "
        "{%0,%1,%2,%3}, {%4,%5,%6,%7}, {%8,%9}, {%0,%1,%2,%3};"
        : "+f"(c[0]), "+f"(c[1]), "+f"(c[2]), "+f"(c[3])
        : "r"(a[0]), "r"(a[1]), "r"(a[2]), "r"(a[3]), "r"(b0), "r"(b1));
}

// ---------------------------------------------------------------------------
// K1: constants c1/cg + W fragment packing. 1 block x 256 threads, ~4us.
// ---------------------------------------------------------------------------
__global__ void k1_const(const float* __restrict__ upd_b,
                         const float* __restrict__ ln_g,
                         const float* __restrict__ ln_b,
                         const float* __restrict__ fus_W1,
                         const float* __restrict__ fus_b1,
                         const float* __restrict__ gate_W,
                         const float* __restrict__ gate_b,
                         const float* __restrict__ fus_W2) {
    __shared__ __align__(16) float p0s[Hn];
    const int tid = threadIdx.x, w = tid >> 5, lane = tid & 31;

    if (w == 0) {
        float v0 = upd_b[lane], v1 = upd_b[lane + 32];
        float s = v0 + v1;
        #pragma unroll
        for (int o = 16; o > 0; o >>= 1) s += __shfl_xor_sync(~0u, s, o);
        float mu = s * (1.0f / Hn);
        float d0 = v0 - mu, d1 = v1 - mu;
        s = d0 * d0 + d1 * d1;
        #pragma unroll
        for (int o = 16; o > 0; o >>= 1) s += __shfl_xor_sync(~0u, s, o);
        float inv = rsqrtf(s * (1.0f / Hn) + LN_EPSF);
        p0s[lane]      = d0 * inv * ln_g[lane] + ln_b[lane];
        p0s[lane + 32] = d1 * inv * ln_g[lane + 32] + ln_b[lane + 32];
    }
    __syncthreads();

    if (tid < Hn) {
        float c = fus_b1[tid];
        #pragma unroll 8
        for (int k = 0; k < Hn; k++)
            c = fmaf(p0s[k], fus_W1[(Hn + k) * Hn + tid], c);
        g_c1[tid] = c;
    }
    if (w == 0) {
        float s = p0s[lane] * gate_W[Hn + lane]
                + p0s[lane + 32] * gate_W[Hn + lane + 32];
        #pragma unroll
        for (int o = 16; o > 0; o >>= 1) s += __shfl_xor_sync(~0u, s, o);
        if (lane == 0) g_cg = s + gate_b[0];
    }

    for (int idx = tid; idx < 1024; idx += 256) {
        int l = idx & 31;
        int tile = idx >> 5;
        int nt = tile & 7, kt = tile >> 3;
        int n  = nt * 8 + (l >> 2);
        int k0 = kt * 16 + (l & 3) * 2;
        {
            float w00 = fus_W1[k0 * Hn + n];
            float w01 = fus_W1[(k0 + 1) * Hn + n];
            float w08 = fus_W1[(k0 + 8) * Hn + n];
            float w09 = fus_W1[(k0 + 9) * Hn + n];
            uint32_t hx = cvt_bf16x2(w01, w00);
            uint32_t hy = cvt_bf16x2(w09, w08);
            g_W1fh[idx] = make_uint2(hx, hy);
            g_W1fl[idx] = make_uint2(
                cvt_bf16x2(w01 - bf_hi(hx), w00 - bf_lo(hx)),
                cvt_bf16x2(w09 - bf_hi(hy), w08 - bf_lo(hy)));
        }
        {
            float w00 = fus_W2[k0 * Hn + n];
            float w01 = fus_W2[(k0 + 1) * Hn + n];
            float w08 = fus_W2[(k0 + 8) * Hn + n];
            float w09 = fus_W2[(k0 + 9) * Hn + n];
            uint32_t hx = cvt_bf16x2(w01, w00);
            uint32_t hy = cvt_bf16x2(w09, w08);
            g_W2fh[idx] = make_uint2(hx, hy);
            g_W2fl[idx] = make_uint2(
                cvt_bf16x2(w01 - bf_hi(hx), w00 - bf_lo(hx)),
                cvt_bf16x2(w09 - bf_hi(hy), w08 - bf_lo(hy)));
        }
    }
}

// ---------------------------------------------------------------------------
// K2: fused. blocks [0,256) = per-sample prompt pipeline (hidden under kB);
// blocks [256, 256+4096) = default fusion (uniform c1/cg bias, no specials).
// ---------------------------------------------------------------------------
#define TILE_M 128
#define NTHR   128
// kB smem layout
#define OW1H 0
#define OW1L 8192
#define OW2H 16384
#define OW2L 24576
#define OGWA 32768
#define OC1  33024
#define OB2  33280
// prompt smem layout (aliases the same buffer)
#define P_WSUM 0
#define P_WUPD 16384
#define P_HS   32768
#define P_MS   37888
#define P_ER   43008
#define SMEM_K2 43136

__global__ __launch_bounds__(NTHR, 3)
void k2_fused(const int* __restrict__ qrel,
              const int* __restrict__ etype,
              const float* __restrict__ noise,
              const float* __restrict__ msg_W,
              const float* __restrict__ msg_b,
              const float* __restrict__ upd_W,
              const float* __restrict__ upd_b,
              const float* __restrict__ ln_g,
              const float* __restrict__ ln_b,
              const float* __restrict__ fus_W1,
              const float* __restrict__ fus_b1,
              const float* __restrict__ gate_W,
              const float* __restrict__ gate_b,
              const float* __restrict__ base,
              const float* __restrict__ fus_b2,
              float* __restrict__ out) {
    extern __shared__ __align__(16) char sm[];
    const int tid = threadIdx.x;
    const int w = tid >> 5, lane = tid & 31;

    if (blockIdx.x < Bn) {
        // ================= prompt pipeline (128 threads) =================
        const int b  = blockIdx.x;
        const int j  = tid & 63;
        const int eg = tid >> 6;      // 0..1
        float* Wsum = (float*)(sm + P_WSUM);
        float* Wupd = (float*)(sm + P_WUPD);
        float (*hs)[Hn] = (float(*)[Hn])(sm + P_HS);
        float (*ms)[Hn] = (float(*)[Hn])(sm + P_MS);
        int* er = (int*)(sm + P_ER);

        for (int idx = tid; idx < Hn * Hn; idx += NTHR) {
            Wsum[idx] = msg_W[idx] + msg_W[Hn * Hn + idx];
            Wupd[idx] = upd_W[idx];
        }
        if (tid < En) er[tid] = etype[b * En + tid];
        __syncthreads();

        int qr = qrel[b];
        for (int e = eg; e < En; e += 2) {
            int r = er[e];
            hs[e][j] = (r == qr) ? 1.0f
                                 : noise[((size_t)b * Rn + r) * Hn + j] * 0.1f;
        }
        __syncthreads();

        for (int e = eg; e < En; e += 2) {
            float m = msg_b[j];
            #pragma unroll 8
            for (int k = 0; k < Hn; k++) m = fmaf(hs[e][k], Wsum[k * Hn + j], m);
            ms[e][j] = fmaxf(m, 0.0f);
        }
        __syncthreads();

        for (int e = eg; e < En; e += 2) {
            float a = 0.0f;
            int re = er[e];
            #pragma unroll
            for (int e2 = 0; e2 < En; e2++)
                if (er[e2] == re) a += ms[e2][j];
            hs[e][j] = a;
        }
        for (int idx = tid; idx < Hn * Hn; idx += NTHR)
            Wsum[idx] = fus_W1[Hn * Hn + idx];   // W1b for q1
        __syncthreads();

        for (int e = eg; e < En; e += 2) {
            float u = upd_b[j];
            #pragma unroll 8
            for (int k = 0; k < Hn; k++) u = fmaf(hs[e][k], Wupd[k * Hn + j], u);
            ms[e][j] = u;
        }
        __syncthreads();

        for (int e = w; e < En; e += 4) {
            float v0 = ms[e][lane], v1 = ms[e][lane + 32];
            float s = v0 + v1;
            #pragma unroll
            for (int o = 16; o > 0; o >>= 1) s += __shfl_xor_sync(~0u, s, o);
            float mu = s * (1.0f / Hn);
            float d0 = v0 - mu, d1 = v1 - mu;
            s = d0 * d0 + d1 * d1;
            #pragma unroll
            for (int o = 16; o > 0; o >>= 1) s += __shfl_xor_sync(~0u, s, o);
            float inv = rsqrtf(s * (1.0f / Hn) + LN_EPSF);
            ms[e][lane]      = d0 * inv * ln_g[lane] + ln_b[lane];
            ms[e][lane + 32] = d1 * inv * ln_g[lane + 32] + ln_b[lane + 32];
        }
        __syncthreads();

        for (int e = eg; e < En; e += 2) {
            float q = fus_b1[j];
            #pragma unroll 8
            for (int k = 0; k < Hn; k++) q = fmaf(ms[e][k], Wsum[k * Hn + j], q);
            g_q1[((size_t)b * En + e) * Hn + j] = q;
        }
        for (int e = w; e < En; e += 4) {
            float s = ms[e][lane] * gate_W[Hn + lane]
                    + ms[e][lane + 32] * gate_W[Hn + lane + 32];
            #pragma unroll
            for (int o = 16; o > 0; o >>= 1) s += __shfl_xor_sync(~0u, s, o);
            if (lane == 0) g_qg[b * En + e] = s + gate_b[0];
        }
        return;
    }

    // ================= default fusion (kB) =================
    const int bidx = blockIdx.x - Bn;
    const int b  = bidx >> 4;
    const int r0 = (bidx & 15) * TILE_M;
    const int g = lane >> 2, tig = lane & 3;
    const uint2* W1H = (const uint2*)(sm + OW1H);
    const uint2* W1L = (const uint2*)(sm + OW1L);
    const uint2* W2H = (const uint2*)(sm + OW2H);
    const uint2* W2L = (const uint2*)(sm + OW2L);
    float* GWA = (float*)(sm + OGWA);
    float* C1S = (float*)(sm + OC1);
    float* B2S = (float*)(sm + OB2);

    // stage W fragments + constants
    #pragma unroll
    for (int s = 0; s < 4; s++) {
        int idx = tid + s * NTHR;
        ((uint4*)(sm + OW1H))[idx] = ((const uint4*)g_W1fh)[idx];
        ((uint4*)(sm + OW1L))[idx] = ((const uint4*)g_W1fl)[idx];
        ((uint4*)(sm + OW2H))[idx] = ((const uint4*)g_W2fh)[idx];
        ((uint4*)(sm + OW2L))[idx] = ((const uint4*)g_W2fl)[idx];
    }
    if (tid < 16) ((float4*)GWA)[tid] = ((const float4*)gate_W)[tid];
    else if (tid < 32) ((float4*)C1S)[tid - 16] = ((const float4*)g_c1)[tid - 16];
    else if (tid < 48) ((float4*)B2S)[tid - 32] = ((const float4*)fus_b2)[tid - 32];
    __syncthreads();

    const float* xb = base + ((size_t)(b * Rn + r0)) * Hn;
    float* op = out + ((size_t)(b * Rn + r0)) * Hn;
    const int ra = (w << 5) + g;   // rows: ra, ra+8 (slab0); +16, +24 (slab1)

    // x fragments straight from gmem + fused gate partials
    uint32_t ahi[2][4][4], alo[2][4][4];
    float gd[4] = {0.0f, 0.0f, 0.0f, 0.0f};
    #pragma unroll
    for (int s2 = 0; s2 < 2; s2++) {
        int rA = ra + s2 * 16, rB = rA + 8;
        #pragma unroll
        for (int kt = 0; kt < 4; kt++) {
            int c0 = kt * 16 + 2 * tig;
            float2 p00 = *(const float2*)(xb + rA * Hn + c0);
            float2 p10 = *(const float2*)(xb + rB * Hn + c0);
            float2 p01 = *(const float2*)(xb + rA * Hn + c0 + 8);
            float2 p11 = *(const float2*)(xb + rB * Hn + c0 + 8);
            float2 gw0 = *(const float2*)(GWA + c0);
            float2 gw8 = *(const float2*)(GWA + c0 + 8);
            gd[s2 * 2 + 0] += p00.x * gw0.x + p00.y * gw0.y
                            + p01.x * gw8.x + p01.y * gw8.y;
            gd[s2 * 2 + 1] += p10.x * gw0.x + p10.y * gw0.y
                            + p11.x * gw8.x + p11.y * gw8.y;
            uint32_t h0 = cvt_bf16x2(p00.y, p00.x);
            uint32_t h1 = cvt_bf16x2(p10.y, p10.x);
            uint32_t h2 = cvt_bf16x2(p01.y, p01.x);
            uint32_t h3 = cvt_bf16x2(p11.y, p11.x);
            ahi[s2][kt][0] = h0; ahi[s2][kt][1] = h1;
            ahi[s2][kt][2] = h2; ahi[s2][kt][3] = h3;
            alo[s2][kt][0] = cvt_bf16x2(p00.y - bf_hi(h0), p00.x - bf_lo(h0));
            alo[s2][kt][1] = cvt_bf16x2(p10.y - bf_hi(h1), p10.x - bf_lo(h1));
            alo[s2][kt][2] = cvt_bf16x2(p01.y - bf_hi(h2), p01.x - bf_lo(h2));
            alo[s2][kt][3] = cvt_bf16x2(p11.y - bf_hi(h3), p11.x - bf_lo(h3));
        }
    }
    // complete row dots across the 4 tig lanes (all lanes get the sum)
    #pragma unroll
    for (int i = 0; i < 4; i++) {
        gd[i] += __shfl_xor_sync(~0u, gd[i], 1);
        gd[i] += __shfl_xor_sync(~0u, gd[i], 2);
    }
    const float cgv = g_cg;

    // GEMM1
    float acc[2][8][4];
    #pragma unroll
    for (int s2 = 0; s2 < 2; s2++)
        #pragma unroll
        for (int nt = 0; nt < 8; nt++)
            acc[s2][nt][0] = acc[s2][nt][1] = acc[s2][nt][2] = acc[s2][nt][3] = 0.0f;
    #pragma unroll
    for (int nt = 0; nt < 8; nt++) {
        #pragma unroll
        for (int kt = 0; kt < 4; kt++) {
            uint2 bh = W1H[(kt * 8 + nt) * 32 + lane];
            uint2 bl = W1L[(kt * 8 + nt) * 32 + lane];
            #pragma unroll
            for (int s2 = 0; s2 < 2; s2++) {
                mma_bf16(acc[s2][nt], ahi[s2][kt], bh.x, bh.y);
                mma_bf16(acc[s2][nt], ahi[s2][kt], bl.x, bl.y);
                mma_bf16(acc[s2][nt], alo[s2][kt], bh.x, bh.y);
            }
        }
    }

    // epilogue1: uniform bias c1, relu, repack as A2 fragments
    uint32_t yhi[2][4][4], ylo[2][4][4];
    #pragma unroll
    for (int kt2 = 0; kt2 < 4; kt2++) {
        #pragma unroll
        for (int half = 0; half < 2; half++) {
            int nt = kt2 * 2 + half;
            int col = nt * 8 + 2 * tig;
            float2 cb = *(const float2*)(C1S + col);
            #pragma unroll
            for (int s2 = 0; s2 < 2; s2++) {
                float y0 = fmaxf(acc[s2][nt][0] + cb.x, 0.0f);
                float y1 = fmaxf(acc[s2][nt][1] + cb.y, 0.0f);
                float y2 = fmaxf(acc[s2][nt][2] + cb.x, 0.0f);
                float y3 = fmaxf(acc[s2][nt][3] + cb.y, 0.0f);
                uint32_t h0 = cvt_bf16x2(y1, y0);
                uint32_t h1 = cvt_bf16x2(y3, y2);
                yhi[s2][kt2][half * 2 + 0] = h0;
                yhi[s2][kt2][half * 2 + 1] = h1;
                ylo[s2][kt2][half * 2 + 0] = cvt_bf16x2(y1 - bf_hi(h0), y0 - bf_lo(h0));
                ylo[s2][kt2][half * 2 + 1] = cvt_bf16x2(y3 - bf_hi(h1), y2 - bf_lo(h1));
            }
        }
    }

    // GEMM2 (reuse acc storage)
    #pragma unroll
    for (int s2 = 0; s2 < 2; s2++)
        #pragma unroll
        for (int nt = 0; nt < 8; nt++)
            acc[s2][nt][0] = acc[s2][nt][1] = acc[s2][nt][2] = acc[s2][nt][3] = 0.0f;
    #pragma unroll
    for (int nt = 0; nt < 8; nt++) {
        #pragma unroll
        for (int kt = 0; kt < 4; kt++) {
            uint2 bh = W2H[(kt * 8 + nt) * 32 + lane];
            uint2 bl = W2L[(kt * 8 + nt) * 32 + lane];
            #pragma unroll
            for (int s2 = 0; s2 < 2; s2++) {
                mma_bf16(acc[s2][nt], yhi[s2][kt], bh.x, bh.y);
                mma_bf16(acc[s2][nt], yhi[s2][kt], bl.x, bl.y);
                mma_bf16(acc[s2][nt], ylo[s2][kt], bh.x, bh.y);
            }
        }
    }

    // epilogue2: f = D2 + b2; out = x + g*(f - x); store direct to gmem
    #pragma unroll
    for (int s2 = 0; s2 < 2; s2++) {
        int rA = ra + s2 * 16, rB = rA + 8;
        float ga = 1.0f / (1.0f + __expf(-(gd[2 * s2 + 0] + cgv)));
        float gb = 1.0f / (1.0f + __expf(-(gd[2 * s2 + 1] + cgv)));
        #pragma unroll
        for (int nt = 0; nt < 8; nt++) {
            int col = nt * 8 + 2 * tig;
            float2 b2v = *(const float2*)(B2S + col);
            float2 xa = *(const float2*)(xb + rA * Hn + col);
            float2 xv = *(const float2*)(xb + rB * Hn + col);
            float f0 = acc[s2][nt][0] + b2v.x;
            float f1 = acc[s2][nt][1] + b2v.y;
            float f2 = acc[s2][nt][2] + b2v.x;
            float f3 = acc[s2][nt][3] + b2v.y;
            float2 oa, ob;
            oa.x = xa.x + ga * (f0 - xa.x);
            oa.y = xa.y + ga * (f1 - xa.y);
            ob.x = xv.x + gb * (f2 - xv.x);
            ob.y = xv.y + gb * (f3 - xv.y);
            *(float2*)(op + rA * Hn + col) = oa;
            *(float2*)(op + rB * Hn + col) = ob;
        }
    }
}

// ---------------------------------------------------------------------------
// K3: fixup the <=20 special rows per sample using prompt-derived q1/qg.
// 256 blocks x 128 threads, fp32 GEMVs from smem-staged W.
// ---------------------------------------------------------------------------
#define F_W1 0
#define F_W2 16384
#define F_XS 32768
#define F_YS 33280
#define F_GW 33792
#define F_B2 34048
#define F_ZR 34304
#define F_ER 34320
#define SMEM_K3 34432

__global__ __launch_bounds__(128)
void k3_fix(const int* __restrict__ etype,
            const float* __restrict__ base,
            const float* __restrict__ fus_W1,
            const float* __restrict__ fus_W2,
            const float* __restrict__ fus_b2,
            const float* __restrict__ gate_W,
            float* __restrict__ out) {
    extern __shared__ __align__(16) char sm[];
    float* W1s = (float*)(sm + F_W1);
    float* W2s = (float*)(sm + F_W2);
    float (*xs)[Hn] = (float(*)[Hn])(sm + F_XS);
    float (*ys)[Hn] = (float(*)[Hn])(sm + F_YS);
    float* gws = (float*)(sm + F_GW);
    float* b2s = (float*)(sm + F_B2);
    float* zr  = (float*)(sm + F_ZR);
    int*   er  = (int*)(sm + F_ER);

    const int b = blockIdx.x;
    const int tid = threadIdx.x;
    const int h = tid >> 6, j = tid & 63, w2 = tid >> 5;

    for (int idx = tid; idx < Hn * Hn; idx += 128) {
        W1s[idx] = fus_W1[idx];       // W1a rows 0..63
        W2s[idx] = fus_W2[idx];
    }
    if (tid < En) er[tid] = etype[b * En + tid];
    if (tid >= 32 && tid < 96) gws[tid - 32] = gate_W[tid - 32];
    if (tid >= 96 && tid < 128) { b2s[tid - 96] = fus_b2[tid - 96];
                                  b2s[tid - 64] = fus_b2[tid - 64]; }
    __syncthreads();

    for (int ep = 0; ep < En; ep += 2) {
        int e = ep + h;
        int r = er[e];
        float xv = base[((size_t)(b * Rn + r)) * Hn + j];
        xs[h][j] = xv;
        float zp = xv * gws[j];
        #pragma unroll
        for (int o = 16; o > 0; o >>= 1) zp += __shfl_xor_sync(~0u, zp, o);
        if ((tid & 31) == 0) zr[w2] = zp;
        __syncthreads();

        float y = g_q1[((size_t)b * En + e) * Hn + j];
        #pragma unroll 8
        for (int k = 0; k < Hn; k++) y = fmaf(xs[h][k], W1s[k * Hn + j], y);
        ys[h][j] = fmaxf(y, 0.0f);
        __syncthreads();

        float f = b2s[j];
        #pragma unroll 8
        for (int k = 0; k < Hn; k++) f = fmaf(ys[h][k], W2s[k * Hn + j], f);
        float z = zr[2 * h] + zr[2 * h + 1] + g_qg[b * En + e];
        float gg = 1.0f / (1.0f + __expf(-z));
        out[((size_t)(b * Rn + r)) * Hn + j] = xv + gg * (f - xv);
        __syncthreads();
    }
}

// ---------------------------------------------------------------------------
extern "C" void kernel_launch(void* const* d_in, const int* in_sizes, int n_in,
                              void* d_out, int out_size) {
    const int*   qrel   = (const int*)  d_in[0];
    const int*   etype  = (const int*)  d_in[1];
    const float* base   = (const float*)d_in[2];
    const float* noise  = (const float*)d_in[3];
    const float* msg_W  = (const float*)d_in[4];
    const float* msg_b  = (const float*)d_in[5];
    const float* upd_W  = (const float*)d_in[6];
    const float* upd_b  = (const float*)d_in[7];
    const float* ln_g   = (const float*)d_in[8];
    const float* ln_b   = (const float*)d_in[9];
    const float* fus_W1 = (const float*)d_in[10];
    const float* fus_b1 = (const float*)d_in[11];
    const float* fus_W2 = (const float*)d_in[12];
    const float* fus_b2 = (const float*)d_in[13];
    const float* gate_W = (const float*)d_in[14];
    const float* gate_b = (const float*)d_in[15];
    float* out = (float*)d_out;

    k1_const<<<1, 256>>>(upd_b, ln_g, ln_b, fus_W1, fus_b1, gate_W, gate_b,
                         fus_W2);

    cudaFuncSetAttribute(k2_fused, cudaFuncAttributeMaxDynamicSharedMemorySize,
                         SMEM_K2);
    k2_fused<<<Bn + Bn * (Rn / TILE_M), NTHR, SMEM_K2>>>(
        qrel, etype, noise, msg_W, msg_b, upd_W, upd_b, ln_g, ln_b,
        fus_W1, fus_b1, gate_W, gate_b, base, fus_b2, out);

    cudaFuncSetAttribute(k3_fix, cudaFuncAttributeMaxDynamicSharedMemorySize,
                         SMEM_K3);
    k3_fix<<<Bn, 128, SMEM_K3>>>(etype, base, fus_W1, fus_W2, fus_b2,
                                 gate_W, out);
}

// round 10
// speedup vs baseline: 2.5577x; 1.0359x over previous
#include <cuda_runtime.h>
#include <cuda_bf16.h>
#include <math.h>
#include <stdint.h>

#define Bn 256
#define Rn 2048
#define Hn 64
#define En 20
#define LN_EPSF 1e-5f

// device scratch (no allocs allowed)
__device__ __align__(16) float g_c1[Hn];
__device__ float g_cg;
__device__ __align__(16) float g_q1[Bn * En * Hn];
__device__ float g_qg[Bn * En];
__device__ __align__(16) uint2 g_W1fh[1024];
__device__ __align__(16) uint2 g_W1fl[1024];
__device__ __align__(16) uint2 g_W2fh[1024];
__device__ __align__(16) uint2 g_W2fl[1024];

static __device__ __forceinline__ uint32_t cvt_bf16x2(float e1, float e0) {
    uint32_t r;
    asm("cvt.rn.bf16x2.f32 %0, %1, %2;" : "=r"(r) : "f"(e1), "f"(e0));
    return r;
}
static __device__ __forceinline__ float bf_lo(uint32_t r) {
    return __uint_as_float(r << 16);
}
static __device__ __forceinline__ float bf_hi(uint32_t r) {
    return __uint_as_float(r & 0xFFFF0000u);
}
static __device__ __forceinline__ void mma_bf16(float* c, const uint32_t* a,
                                                uint32_t b0, uint32_t b1) {
    asm volatile(
        "mma.sync.aligned.m16n8k16.row.col.f32.bf16.bf16.f32 "
        "{%0,%1,%2,%3}, {%4,%5,%6,%7}, {%8,%9}, {%0,%1,%2,%3};"
        : "+f"(c[0]), "+f"(c[1]), "+f"(c[2]), "+f"(c[3])
        : "r"(a[0]), "r"(a[1]), "r"(a[2]), "r"(a[3]), "r"(b0), "r"(b1));
}

// ---------------------------------------------------------------------------
// K1: constants c1/cg (block 0) + W fragment packing (8 blocks, 128 items ea).
// ---------------------------------------------------------------------------
__global__ void k1_const(const float* __restrict__ upd_b,
                         const float* __restrict__ ln_g,
                         const float* __restrict__ ln_b,
                         const float* __restrict__ fus_W1,
                         const float* __restrict__ fus_b1,
                         const float* __restrict__ gate_W,
                         const float* __restrict__ gate_b,
                         const float* __restrict__ fus_W2) {
    __shared__ __align__(16) float p0s[Hn];
    const int tid = threadIdx.x, w = tid >> 5, lane = tid & 31;

    if (blockIdx.x == 0) {
        if (w == 0) {
            float v0 = upd_b[lane], v1 = upd_b[lane + 32];
            float s = v0 + v1;
            #pragma unroll
            for (int o = 16; o > 0; o >>= 1) s += __shfl_xor_sync(~0u, s, o);
            float mu = s * (1.0f / Hn);
            float d0 = v0 - mu, d1 = v1 - mu;
            s = d0 * d0 + d1 * d1;
            #pragma unroll
            for (int o = 16; o > 0; o >>= 1) s += __shfl_xor_sync(~0u, s, o);
            float inv = rsqrtf(s * (1.0f / Hn) + LN_EPSF);
            p0s[lane]      = d0 * inv * ln_g[lane] + ln_b[lane];
            p0s[lane + 32] = d1 * inv * ln_g[lane + 32] + ln_b[lane + 32];
        }
        __syncthreads();

        if (tid < Hn) {
            float c = fus_b1[tid];
            #pragma unroll 8
            for (int k = 0; k < Hn; k++)
                c = fmaf(p0s[k], fus_W1[(Hn + k) * Hn + tid], c);
            g_c1[tid] = c;
        }
        if (w == 0) {
            float s = p0s[lane] * gate_W[Hn + lane]
                    + p0s[lane + 32] * gate_W[Hn + lane + 32];
            #pragma unroll
            for (int o = 16; o > 0; o >>= 1) s += __shfl_xor_sync(~0u, s, o);
            if (lane == 0) g_cg = s + gate_b[0];
        }
    }

    if (tid < 128) {
        int idx = blockIdx.x * 128 + tid;
        int l = idx & 31;
        int tile = idx >> 5;
        int nt = tile & 7, kt = tile >> 3;
        int n  = nt * 8 + (l >> 2);
        int k0 = kt * 16 + (l & 3) * 2;
        {
            float w00 = fus_W1[k0 * Hn + n];
            float w01 = fus_W1[(k0 + 1) * Hn + n];
            float w08 = fus_W1[(k0 + 8) * Hn + n];
            float w09 = fus_W1[(k0 + 9) * Hn + n];
            uint32_t hx = cvt_bf16x2(w01, w00);
            uint32_t hy = cvt_bf16x2(w09, w08);
            g_W1fh[idx] = make_uint2(hx, hy);
            g_W1fl[idx] = make_uint2(
                cvt_bf16x2(w01 - bf_hi(hx), w00 - bf_lo(hx)),
                cvt_bf16x2(w09 - bf_hi(hy), w08 - bf_lo(hy)));
        }
        {
            float w00 = fus_W2[k0 * Hn + n];
            float w01 = fus_W2[(k0 + 1) * Hn + n];
            float w08 = fus_W2[(k0 + 8) * Hn + n];
            float w09 = fus_W2[(k0 + 9) * Hn + n];
            uint32_t hx = cvt_bf16x2(w01, w00);
            uint32_t hy = cvt_bf16x2(w09, w08);
            g_W2fh[idx] = make_uint2(hx, hy);
            g_W2fl[idx] = make_uint2(
                cvt_bf16x2(w01 - bf_hi(hx), w00 - bf_lo(hx)),
                cvt_bf16x2(w09 - bf_hi(hy), w08 - bf_lo(hy)));
        }
    }
}

// ---------------------------------------------------------------------------
// K2: fused. blocks [0,256) = prompt pipeline; [256, 4352) = default fusion.
// Fusion uses 2-MMA split: A plain bf16, W split hi/lo (precomputed).
// ---------------------------------------------------------------------------
#define TILE_M 128
#define NTHR   128
#define OW1H 0
#define OW1L 8192
#define OW2H 16384
#define OW2L 24576
#define OGWA 32768
#define OC1  33024
#define OB2  33280
#define P_WSUM 0
#define P_WUPD 16384
#define P_HS   32768
#define P_MS   37888
#define P_ER   43008
#define SMEM_K2 43136

__global__ __launch_bounds__(NTHR, 4)
void k2_fused(const int* __restrict__ qrel,
              const int* __restrict__ etype,
              const float* __restrict__ noise,
              const float* __restrict__ msg_W,
              const float* __restrict__ msg_b,
              const float* __restrict__ upd_W,
              const float* __restrict__ upd_b,
              const float* __restrict__ ln_g,
              const float* __restrict__ ln_b,
              const float* __restrict__ fus_W1,
              const float* __restrict__ fus_b1,
              const float* __restrict__ gate_W,
              const float* __restrict__ gate_b,
              const float* __restrict__ base,
              const float* __restrict__ fus_b2,
              float* __restrict__ out) {
    extern __shared__ __align__(16) char sm[];
    const int tid = threadIdx.x;
    const int w = tid >> 5, lane = tid & 31;

    if (blockIdx.x < Bn) {
        // ================= prompt pipeline =================
        const int b  = blockIdx.x;
        const int j  = tid & 63;
        const int eg = tid >> 6;
        float* Wsum = (float*)(sm + P_WSUM);
        float* Wupd = (float*)(sm + P_WUPD);
        float (*hs)[Hn] = (float(*)[Hn])(sm + P_HS);
        float (*ms)[Hn] = (float(*)[Hn])(sm + P_MS);
        int* er = (int*)(sm + P_ER);

        for (int idx = tid; idx < Hn * Hn; idx += NTHR) {
            Wsum[idx] = msg_W[idx] + msg_W[Hn * Hn + idx];
            Wupd[idx] = upd_W[idx];
        }
        if (tid < En) er[tid] = etype[b * En + tid];
        __syncthreads();

        int qr = qrel[b];
        for (int e = eg; e < En; e += 2) {
            int r = er[e];
            hs[e][j] = (r == qr) ? 1.0f
                                 : noise[((size_t)b * Rn + r) * Hn + j] * 0.1f;
        }
        __syncthreads();

        for (int e = eg; e < En; e += 2) {
            float m = msg_b[j];
            #pragma unroll 8
            for (int k = 0; k < Hn; k++) m = fmaf(hs[e][k], Wsum[k * Hn + j], m);
            ms[e][j] = fmaxf(m, 0.0f);
        }
        __syncthreads();

        for (int e = eg; e < En; e += 2) {
            float a = 0.0f;
            int re = er[e];
            #pragma unroll
            for (int e2 = 0; e2 < En; e2++)
                if (er[e2] == re) a += ms[e2][j];
            hs[e][j] = a;
        }
        for (int idx = tid; idx < Hn * Hn; idx += NTHR)
            Wsum[idx] = fus_W1[Hn * Hn + idx];   // W1b for q1
        __syncthreads();

        for (int e = eg; e < En; e += 2) {
            float u = upd_b[j];
            #pragma unroll 8
            for (int k = 0; k < Hn; k++) u = fmaf(hs[e][k], Wupd[k * Hn + j], u);
            ms[e][j] = u;
        }
        __syncthreads();

        for (int e = w; e < En; e += 4) {
            float v0 = ms[e][lane], v1 = ms[e][lane + 32];
            float s = v0 + v1;
            #pragma unroll
            for (int o = 16; o > 0; o >>= 1) s += __shfl_xor_sync(~0u, s, o);
            float mu = s * (1.0f / Hn);
            float d0 = v0 - mu, d1 = v1 - mu;
            s = d0 * d0 + d1 * d1;
            #pragma unroll
            for (int o = 16; o > 0; o >>= 1) s += __shfl_xor_sync(~0u, s, o);
            float inv = rsqrtf(s * (1.0f / Hn) + LN_EPSF);
            ms[e][lane]      = d0 * inv * ln_g[lane] + ln_b[lane];
            ms[e][lane + 32] = d1 * inv * ln_g[lane + 32] + ln_b[lane + 32];
        }
        __syncthreads();

        for (int e = eg; e < En; e += 2) {
            float q = fus_b1[j];
            #pragma unroll 8
            for (int k = 0; k < Hn; k++) q = fmaf(ms[e][k], Wsum[k * Hn + j], q);
            g_q1[((size_t)b * En + e) * Hn + j] = q;
        }
        for (int e = w; e < En; e += 4) {
            float s = ms[e][lane] * gate_W[Hn + lane]
                    + ms[e][lane + 32] * gate_W[Hn + lane + 32];
            #pragma unroll
            for (int o = 16; o > 0; o >>= 1) s += __shfl_xor_sync(~0u, s, o);
            if (lane == 0) g_qg[b * En + e] = s + gate_b[0];
        }
        return;
    }

    // ================= default fusion (2-MMA split) =================
    const int bidx = blockIdx.x - Bn;
    const int b  = bidx >> 4;
    const int r0 = (bidx & 15) * TILE_M;
    const int g = lane >> 2, tig = lane & 3;
    const uint2* W1H = (const uint2*)(sm + OW1H);
    const uint2* W1L = (const uint2*)(sm + OW1L);
    const uint2* W2H = (const uint2*)(sm + OW2H);
    const uint2* W2L = (const uint2*)(sm + OW2L);
    float* GWA = (float*)(sm + OGWA);
    float* C1S = (float*)(sm + OC1);
    float* B2S = (float*)(sm + OB2);

    #pragma unroll
    for (int s = 0; s < 4; s++) {
        int idx = tid + s * NTHR;
        ((uint4*)(sm + OW1H))[idx] = ((const uint4*)g_W1fh)[idx];
        ((uint4*)(sm + OW1L))[idx] = ((const uint4*)g_W1fl)[idx];
        ((uint4*)(sm + OW2H))[idx] = ((const uint4*)g_W2fh)[idx];
        ((uint4*)(sm + OW2L))[idx] = ((const uint4*)g_W2fl)[idx];
    }
    if (tid < 16) ((float4*)GWA)[tid] = ((const float4*)gate_W)[tid];
    else if (tid < 32) ((float4*)C1S)[tid - 16] = ((const float4*)g_c1)[tid - 16];
    else if (tid < 48) ((float4*)B2S)[tid - 32] = ((const float4*)fus_b2)[tid - 32];
    __syncthreads();

    const float* xb = base + ((size_t)(b * Rn + r0)) * Hn;
    float* op = out + ((size_t)(b * Rn + r0)) * Hn;
    const int ra = (w << 5) + g;

    // A fragments (plain bf16) + fused gate partials
    uint32_t ahi[2][4][4];
    float gd[4] = {0.0f, 0.0f, 0.0f, 0.0f};
    #pragma unroll
    for (int s2 = 0; s2 < 2; s2++) {
        int rA = ra + s2 * 16, rB = rA + 8;
        #pragma unroll
        for (int kt = 0; kt < 4; kt++) {
            int c0 = kt * 16 + 2 * tig;
            float2 p00 = *(const float2*)(xb + rA * Hn + c0);
            float2 p10 = *(const float2*)(xb + rB * Hn + c0);
            float2 p01 = *(const float2*)(xb + rA * Hn + c0 + 8);
            float2 p11 = *(const float2*)(xb + rB * Hn + c0 + 8);
            float2 gw0 = *(const float2*)(GWA + c0);
            float2 gw8 = *(const float2*)(GWA + c0 + 8);
            gd[s2 * 2 + 0] += p00.x * gw0.x + p00.y * gw0.y
                            + p01.x * gw8.x + p01.y * gw8.y;
            gd[s2 * 2 + 1] += p10.x * gw0.x + p10.y * gw0.y
                            + p11.x * gw8.x + p11.y * gw8.y;
            ahi[s2][kt][0] = cvt_bf16x2(p00.y, p00.x);
            ahi[s2][kt][1] = cvt_bf16x2(p10.y, p10.x);
            ahi[s2][kt][2] = cvt_bf16x2(p01.y, p01.x);
            ahi[s2][kt][3] = cvt_bf16x2(p11.y, p11.x);
        }
    }
    #pragma unroll
    for (int i = 0; i < 4; i++) {
        gd[i] += __shfl_xor_sync(~0u, gd[i], 1);
        gd[i] += __shfl_xor_sync(~0u, gd[i], 2);
    }
    const float cgv = g_cg;

    // GEMM1: A @ (W1hi + W1lo)
    float acc[2][8][4];
    #pragma unroll
    for (int s2 = 0; s2 < 2; s2++)
        #pragma unroll
        for (int nt = 0; nt < 8; nt++)
            acc[s2][nt][0] = acc[s2][nt][1] = acc[s2][nt][2] = acc[s2][nt][3] = 0.0f;
    #pragma unroll
    for (int nt = 0; nt < 8; nt++) {
        #pragma unroll
        for (int kt = 0; kt < 4; kt++) {
            uint2 bh = W1H[(kt * 8 + nt) * 32 + lane];
            uint2 bl = W1L[(kt * 8 + nt) * 32 + lane];
            #pragma unroll
            for (int s2 = 0; s2 < 2; s2++) {
                mma_bf16(acc[s2][nt], ahi[s2][kt], bh.x, bh.y);
                mma_bf16(acc[s2][nt], ahi[s2][kt], bl.x, bl.y);
            }
        }
    }

    // epilogue1: bias c1, relu, repack as A2 (plain bf16)
    uint32_t yhi[2][4][4];
    #pragma unroll
    for (int kt2 = 0; kt2 < 4; kt2++) {
        #pragma unroll
        for (int half = 0; half < 2; half++) {
            int nt = kt2 * 2 + half;
            int col = nt * 8 + 2 * tig;
            float2 cb = *(const float2*)(C1S + col);
            #pragma unroll
            for (int s2 = 0; s2 < 2; s2++) {
                float y0 = fmaxf(acc[s2][nt][0] + cb.x, 0.0f);
                float y1 = fmaxf(acc[s2][nt][1] + cb.y, 0.0f);
                float y2 = fmaxf(acc[s2][nt][2] + cb.x, 0.0f);
                float y3 = fmaxf(acc[s2][nt][3] + cb.y, 0.0f);
                yhi[s2][kt2][half * 2 + 0] = cvt_bf16x2(y1, y0);
                yhi[s2][kt2][half * 2 + 1] = cvt_bf16x2(y3, y2);
            }
        }
    }

    // GEMM2: Y @ (W2hi + W2lo), reuse acc
    #pragma unroll
    for (int s2 = 0; s2 < 2; s2++)
        #pragma unroll
        for (int nt = 0; nt < 8; nt++)
            acc[s2][nt][0] = acc[s2][nt][1] = acc[s2][nt][2] = acc[s2][nt][3] = 0.0f;
    #pragma unroll
    for (int nt = 0; nt < 8; nt++) {
        #pragma unroll
        for (int kt = 0; kt < 4; kt++) {
            uint2 bh = W2H[(kt * 8 + nt) * 32 + lane];
            uint2 bl = W2L[(kt * 8 + nt) * 32 + lane];
            #pragma unroll
            for (int s2 = 0; s2 < 2; s2++) {
                mma_bf16(acc[s2][nt], yhi[s2][kt], bh.x, bh.y);
                mma_bf16(acc[s2][nt], yhi[s2][kt], bl.x, bl.y);
            }
        }
    }

    // epilogue2: f = D2 + b2; out = x + g*(f - x); x re-read (L1-hot)
    #pragma unroll
    for (int s2 = 0; s2 < 2; s2++) {
        int rA = ra + s2 * 16, rB = rA + 8;
        float ga = 1.0f / (1.0f + __expf(-(gd[2 * s2 + 0] + cgv)));
        float gb = 1.0f / (1.0f + __expf(-(gd[2 * s2 + 1] + cgv)));
        #pragma unroll
        for (int nt = 0; nt < 8; nt++) {
            int col = nt * 8 + 2 * tig;
            float2 b2v = *(const float2*)(B2S + col);
            float2 xa = *(const float2*)(xb + rA * Hn + col);
            float2 xv = *(const float2*)(xb + rB * Hn + col);
            float f0 = acc[s2][nt][0] + b2v.x;
            float f1 = acc[s2][nt][1] + b2v.y;
            float f2 = acc[s2][nt][2] + b2v.x;
            float f3 = acc[s2][nt][3] + b2v.y;
            float2 oa, ob;
            oa.x = xa.x + ga * (f0 - xa.x);
            oa.y = xa.y + ga * (f1 - xa.y);
            ob.x = xv.x + gb * (f2 - xv.x);
            ob.y = xv.y + gb * (f3 - xv.y);
            *(float2*)(op + rA * Hn + col) = oa;
            *(float2*)(op + rB * Hn + col) = ob;
        }
    }
}

// ---------------------------------------------------------------------------
// K3: fixup special rows. grid = Bn*5, each block handles 4 edges (2 rounds).
// Duplicate relations produce bitwise-identical writes (benign).
// ---------------------------------------------------------------------------
#define F_W1 0
#define F_W2 16384
#define F_XS 32768
#define F_YS 33280
#define F_GW 33792
#define F_B2 34048
#define F_ZR 34304
#define F_ER 34320
#define SMEM_K3 34432

__global__ __launch_bounds__(128)
void k3_fix(const int* __restrict__ etype,
            const float* __restrict__ base,
            const float* __restrict__ fus_W1,
            const float* __restrict__ fus_W2,
            const float* __restrict__ fus_b2,
            const float* __restrict__ gate_W,
            float* __restrict__ out) {
    extern __shared__ __align__(16) char sm[];
    float* W1s = (float*)(sm + F_W1);
    float* W2s = (float*)(sm + F_W2);
    float (*xs)[Hn] = (float(*)[Hn])(sm + F_XS);
    float (*ys)[Hn] = (float(*)[Hn])(sm + F_YS);
    float* gws = (float*)(sm + F_GW);
    float* b2s = (float*)(sm + F_B2);
    float* zr  = (float*)(sm + F_ZR);
    int*   er  = (int*)(sm + F_ER);

    const int b = blockIdx.x / 5;
    const int chunk = blockIdx.x % 5;
    const int tid = threadIdx.x;
    const int h = tid >> 6, j = tid & 63, w2 = tid >> 5;

    for (int idx = tid; idx < Hn * Hn; idx += 128) {
        W1s[idx] = fus_W1[idx];       // W1a rows 0..63
        W2s[idx] = fus_W2[idx];
    }
    if (tid < 4) er[tid] = etype[b * En + chunk * 4 + tid];
    if (tid >= 32 && tid < 96) gws[tid - 32] = gate_W[tid - 32];
    if (tid >= 96 && tid < 128) { b2s[tid - 96] = fus_b2[tid - 96];
                                  b2s[tid - 64] = fus_b2[tid - 64]; }
    __syncthreads();

    for (int it = 0; it < 2; it++) {
        int el = it * 2 + h;                 // local 0..3
        int e  = chunk * 4 + el;             // global edge index
        int r  = er[el];
        float xv = base[((size_t)(b * Rn + r)) * Hn + j];
        xs[h][j] = xv;
        float zp = xv * gws[j];
        #pragma unroll
        for (int o = 16; o > 0; o >>= 1) zp += __shfl_xor_sync(~0u, zp, o);
        if ((tid & 31) == 0) zr[w2] = zp;
        __syncthreads();

        float y = g_q1[((size_t)b * En + e) * Hn + j];
        #pragma unroll 8
        for (int k = 0; k < Hn; k++) y = fmaf(xs[h][k], W1s[k * Hn + j], y);
        ys[h][j] = fmaxf(y, 0.0f);
        __syncthreads();

        float f = b2s[j];
        #pragma unroll 8
        for (int k = 0; k < Hn; k++) f = fmaf(ys[h][k], W2s[k * Hn + j], f);
        float z = zr[2 * h] + zr[2 * h + 1] + g_qg[b * En + e];
        float gg = 1.0f / (1.0f + __expf(-z));
        out[((size_t)(b * Rn + r)) * Hn + j] = xv + gg * (f - xv);
        __syncthreads();
    }
}

// ---------------------------------------------------------------------------
extern "C" void kernel_launch(void* const* d_in, const int* in_sizes, int n_in,
                              void* d_out, int out_size) {
    const int*   qrel   = (const int*)  d_in[0];
    const int*   etype  = (const int*)  d_in[1];
    const float* base   = (const float*)d_in[2];
    const float* noise  = (const float*)d_in[3];
    const float* msg_W  = (const float*)d_in[4];
    const float* msg_b  = (const float*)d_in[5];
    const float* upd_W  = (const float*)d_in[6];
    const float* upd_b  = (const float*)d_in[7];
    const float* ln_g   = (const float*)d_in[8];
    const float* ln_b   = (const float*)d_in[9];
    const float* fus_W1 = (const float*)d_in[10];
    const float* fus_b1 = (const float*)d_in[11];
    const float* fus_W2 = (const float*)d_in[12];
    const float* fus_b2 = (const float*)d_in[13];
    const float* gate_W = (const float*)d_in[14];
    const float* gate_b = (const float*)d_in[15];
    float* out = (float*)d_out;

    k1_const<<<8, 256>>>(upd_b, ln_g, ln_b, fus_W1, fus_b1, gate_W, gate_b,
                         fus_W2);

    cudaFuncSetAttribute(k2_fused, cudaFuncAttributeMaxDynamicSharedMemorySize,
                         SMEM_K2);
    k2_fused<<<Bn + Bn * (Rn / TILE_M), NTHR, SMEM_K2>>>(
        qrel, etype, noise, msg_W, msg_b, upd_W, upd_b, ln_g, ln_b,
        fus_W1, fus_b1, gate_W, gate_b, base, fus_b2, out);

    cudaFuncSetAttribute(k3_fix, cudaFuncAttributeMaxDynamicSharedMemorySize,
                         SMEM_K3);
    k3_fix<<<Bn * 5, 128, SMEM_K3>>>(etype, base, fus_W1, fus_W2, fus_b2,
                                     gate_W, out);
}

// round 11
// speedup vs baseline: 2.5982x; 1.0158x over previous
#include <cuda_runtime.h>
#include <cuda_bf16.h>
#include <math.h>
#include <stdint.h>

#define Bn 256
#define Rn 2048
#define Hn 64
#define En 20
#define LN_EPSF 1e-5f
#define NTILES (Bn * (Rn / 128))   // 4096
#define NWORK  592                 // 4 CTAs/SM * 148 SMs

// device scratch (no allocs allowed)
__device__ __align__(16) float g_q1[Bn * En * Hn];
__device__ float g_qg[Bn * En];
__device__ int g_tile_ctr;          // zero-init; reset by k3 each launch

static __device__ __forceinline__ uint32_t cvt_bf16x2(float e1, float e0) {
    uint32_t r;
    asm("cvt.rn.bf16x2.f32 %0, %1, %2;" : "=r"(r) : "f"(e1), "f"(e0));
    return r;
}
static __device__ __forceinline__ float bf_lo(uint32_t r) {
    return __uint_as_float(r << 16);
}
static __device__ __forceinline__ float bf_hi(uint32_t r) {
    return __uint_as_float(r & 0xFFFF0000u);
}
static __device__ __forceinline__ void mma_bf16(float* c, const uint32_t* a,
                                                uint32_t b0, uint32_t b1) {
    asm volatile(
        "mma.sync.aligned.m16n8k16.row.col.f32.bf16.bf16.f32 "
        "{%0,%1,%2,%3}, {%4,%5,%6,%7}, {%8,%9}, {%0,%1,%2,%3};"
        : "+f"(c[0]), "+f"(c[1]), "+f"(c[2]), "+f"(c[3])
        : "r"(a[0]), "r"(a[1]), "r"(a[2]), "r"(a[3]), "r"(b0), "r"(b1));
}

// ---------------------------------------------------------------------------
// K2: single fused kernel, 592 persistent CTAs.
//   blocks [0,256): per-sample prompt pipeline first, then join worker pool.
//   all blocks: self-stage W fragments + c1/cg, then claim tiles dynamically.
// ---------------------------------------------------------------------------
#define NTHR 128
// fusion smem
#define OW1H 0
#define OW1L 8192
#define OW2H 16384
#define OW2L 24576
#define OGWA 32768
#define OC1  33024
#define OB2  33280
#define OP0  33536
#define OCG  33792
#define OTIL 33808
// prompt smem (aliases; used before fusion staging)
#define P_WSUM 0
#define P_WUPD 16384
#define P_HS   32768
#define P_MS   37888
#define P_ER   43008
#define SMEM_K2 43136

__global__ __launch_bounds__(NTHR, 4)
void k2_fused(const int* __restrict__ qrel,
              const int* __restrict__ etype,
              const float* __restrict__ noise,
              const float* __restrict__ msg_W,
              const float* __restrict__ msg_b,
              const float* __restrict__ upd_W,
              const float* __restrict__ upd_b,
              const float* __restrict__ ln_g,
              const float* __restrict__ ln_b,
              const float* __restrict__ fus_W1,
              const float* __restrict__ fus_b1,
              const float* __restrict__ gate_W,
              const float* __restrict__ gate_b,
              const float* __restrict__ base,
              const float* __restrict__ fus_W2,
              const float* __restrict__ fus_b2,
              float* __restrict__ out) {
    extern __shared__ __align__(16) char sm[];
    const int tid = threadIdx.x;
    const int w = tid >> 5, lane = tid & 31;

    if (blockIdx.x < Bn) {
        // ================= prompt pipeline =================
        const int b  = blockIdx.x;
        const int j  = tid & 63;
        const int eg = tid >> 6;
        float* Wsum = (float*)(sm + P_WSUM);
        float* Wupd = (float*)(sm + P_WUPD);
        float (*hs)[Hn] = (float(*)[Hn])(sm + P_HS);
        float (*ms)[Hn] = (float(*)[Hn])(sm + P_MS);
        int* er = (int*)(sm + P_ER);

        for (int idx = tid; idx < Hn * Hn; idx += NTHR) {
            Wsum[idx] = msg_W[idx] + msg_W[Hn * Hn + idx];
            Wupd[idx] = upd_W[idx];
        }
        if (tid < En) er[tid] = etype[b * En + tid];
        __syncthreads();

        int qr = qrel[b];
        for (int e = eg; e < En; e += 2) {
            int r = er[e];
            hs[e][j] = (r == qr) ? 1.0f
                                 : noise[((size_t)b * Rn + r) * Hn + j] * 0.1f;
        }
        __syncthreads();

        for (int e = eg; e < En; e += 2) {
            float m = msg_b[j];
            #pragma unroll 8
            for (int k = 0; k < Hn; k++) m = fmaf(hs[e][k], Wsum[k * Hn + j], m);
            ms[e][j] = fmaxf(m, 0.0f);
        }
        __syncthreads();

        for (int e = eg; e < En; e += 2) {
            float a = 0.0f;
            int re = er[e];
            #pragma unroll
            for (int e2 = 0; e2 < En; e2++)
                if (er[e2] == re) a += ms[e2][j];
            hs[e][j] = a;
        }
        for (int idx = tid; idx < Hn * Hn; idx += NTHR)
            Wsum[idx] = fus_W1[Hn * Hn + idx];   // W1b for q1
        __syncthreads();

        for (int e = eg; e < En; e += 2) {
            float u = upd_b[j];
            #pragma unroll 8
            for (int k = 0; k < Hn; k++) u = fmaf(hs[e][k], Wupd[k * Hn + j], u);
            ms[e][j] = u;
        }
        __syncthreads();

        for (int e = w; e < En; e += 4) {
            float v0 = ms[e][lane], v1 = ms[e][lane + 32];
            float s = v0 + v1;
            #pragma unroll
            for (int o = 16; o > 0; o >>= 1) s += __shfl_xor_sync(~0u, s, o);
            float mu = s * (1.0f / Hn);
            float d0 = v0 - mu, d1 = v1 - mu;
            s = d0 * d0 + d1 * d1;
            #pragma unroll
            for (int o = 16; o > 0; o >>= 1) s += __shfl_xor_sync(~0u, s, o);
            float inv = rsqrtf(s * (1.0f / Hn) + LN_EPSF);
            ms[e][lane]      = d0 * inv * ln_g[lane] + ln_b[lane];
            ms[e][lane + 32] = d1 * inv * ln_g[lane + 32] + ln_b[lane + 32];
        }
        __syncthreads();

        for (int e = eg; e < En; e += 2) {
            float q = fus_b1[j];
            #pragma unroll 8
            for (int k = 0; k < Hn; k++) q = fmaf(ms[e][k], Wsum[k * Hn + j], q);
            g_q1[((size_t)b * En + e) * Hn + j] = q;
        }
        for (int e = w; e < En; e += 4) {
            float s = ms[e][lane] * gate_W[Hn + lane]
                    + ms[e][lane + 32] * gate_W[Hn + lane + 32];
            #pragma unroll
            for (int o = 16; o > 0; o >>= 1) s += __shfl_xor_sync(~0u, s, o);
            if (lane == 0) g_qg[b * En + e] = s + gate_b[0];
        }
        __syncthreads();   // prompt done; smem now reused for fusion
    }

    // ================= fusion worker setup =================
    uint2* W1H = (uint2*)(sm + OW1H);
    uint2* W1L = (uint2*)(sm + OW1L);
    uint2* W2H = (uint2*)(sm + OW2H);
    uint2* W2L = (uint2*)(sm + OW2L);
    float* GWA = (float*)(sm + OGWA);
    float* C1S = (float*)(sm + OC1);
    float* B2S = (float*)(sm + OB2);
    float* P0S = (float*)(sm + OP0);
    float* CGS = (float*)(sm + OCG);
    int*   TIL = (int*)(sm + OTIL);

    // W fragments from raw fp32 (L2-hot after first wave)
    #pragma unroll
    for (int s = 0; s < 8; s++) {
        int idx = tid + s * NTHR;
        int l = idx & 31;
        int t2 = idx >> 5;
        int nt = t2 & 7, kt = t2 >> 3;
        int n  = nt * 8 + (l >> 2);
        int k0 = kt * 16 + (l & 3) * 2;
        {
            float w00 = fus_W1[k0 * Hn + n];
            float w01 = fus_W1[(k0 + 1) * Hn + n];
            float w08 = fus_W1[(k0 + 8) * Hn + n];
            float w09 = fus_W1[(k0 + 9) * Hn + n];
            uint32_t hx = cvt_bf16x2(w01, w00);
            uint32_t hy = cvt_bf16x2(w09, w08);
            W1H[idx] = make_uint2(hx, hy);
            W1L[idx] = make_uint2(
                cvt_bf16x2(w01 - bf_hi(hx), w00 - bf_lo(hx)),
                cvt_bf16x2(w09 - bf_hi(hy), w08 - bf_lo(hy)));
        }
        {
            float w00 = fus_W2[k0 * Hn + n];
            float w01 = fus_W2[(k0 + 1) * Hn + n];
            float w08 = fus_W2[(k0 + 8) * Hn + n];
            float w09 = fus_W2[(k0 + 9) * Hn + n];
            uint32_t hx = cvt_bf16x2(w01, w00);
            uint32_t hy = cvt_bf16x2(w09, w08);
            W2H[idx] = make_uint2(hx, hy);
            W2L[idx] = make_uint2(
                cvt_bf16x2(w01 - bf_hi(hx), w00 - bf_lo(hx)),
                cvt_bf16x2(w09 - bf_hi(hy), w08 - bf_lo(hy)));
        }
    }
    // p0 = LN(upd_b)*g + b (warp 0)
    if (w == 0) {
        float v0 = upd_b[lane], v1 = upd_b[lane + 32];
        float s = v0 + v1;
        #pragma unroll
        for (int o = 16; o > 0; o >>= 1) s += __shfl_xor_sync(~0u, s, o);
        float mu = s * (1.0f / Hn);
        float d0 = v0 - mu, d1 = v1 - mu;
        s = d0 * d0 + d1 * d1;
        #pragma unroll
        for (int o = 16; o > 0; o >>= 1) s += __shfl_xor_sync(~0u, s, o);
        float inv = rsqrtf(s * (1.0f / Hn) + LN_EPSF);
        P0S[lane]      = d0 * inv * ln_g[lane] + ln_b[lane];
        P0S[lane + 32] = d1 * inv * ln_g[lane + 32] + ln_b[lane + 32];
    }
    __syncthreads();

    // c1 (warps 0-1), cg (warp 2), GWA/B2 staging (warp 3)
    if (tid < Hn) {
        float c = fus_b1[tid];
        #pragma unroll 8
        for (int k = 0; k < Hn; k++)
            c = fmaf(P0S[k], fus_W1[(Hn + k) * Hn + tid], c);
        C1S[tid] = c;
    }
    if (w == 2) {
        float s = P0S[lane] * gate_W[Hn + lane]
                + P0S[lane + 32] * gate_W[Hn + lane + 32];
        #pragma unroll
        for (int o = 16; o > 0; o >>= 1) s += __shfl_xor_sync(~0u, s, o);
        if (lane == 0) CGS[0] = s + gate_b[0];
    }
    if (w == 3) {
        if (lane < 16) ((float4*)GWA)[lane] = ((const float4*)gate_W)[lane];
        else ((float4*)B2S)[lane - 16] = ((const float4*)fus_b2)[lane - 16];
    }
    __syncthreads();

    const float cgv = CGS[0];
    const int g = lane >> 2, tig = lane & 3;
    const int ra = (w << 5) + g;

    // ================= persistent tile loop =================
    for (;;) {
        if (tid == 0) TIL[0] = atomicAdd(&g_tile_ctr, 1);
        __syncthreads();
        const int t = TIL[0];
        __syncthreads();          // protect TIL before next claim
        if (t >= NTILES) break;

        const int b  = t >> 4;
        const int r0 = (t & 15) << 7;
        const float* xb = base + ((size_t)(b * Rn + r0)) * Hn;
        float* op = out + ((size_t)(b * Rn + r0)) * Hn;

        // A fragments (plain bf16) + fused gate partials
        uint32_t ahi[2][4][4];
        float gd[4] = {0.0f, 0.0f, 0.0f, 0.0f};
        #pragma unroll
        for (int s2 = 0; s2 < 2; s2++) {
            int rA = ra + s2 * 16, rB = rA + 8;
            #pragma unroll
            for (int kt = 0; kt < 4; kt++) {
                int c0 = kt * 16 + 2 * tig;
                float2 p00 = *(const float2*)(xb + rA * Hn + c0);
                float2 p10 = *(const float2*)(xb + rB * Hn + c0);
                float2 p01 = *(const float2*)(xb + rA * Hn + c0 + 8);
                float2 p11 = *(const float2*)(xb + rB * Hn + c0 + 8);
                float2 gw0 = *(const float2*)(GWA + c0);
                float2 gw8 = *(const float2*)(GWA + c0 + 8);
                gd[s2 * 2 + 0] += p00.x * gw0.x + p00.y * gw0.y
                                + p01.x * gw8.x + p01.y * gw8.y;
                gd[s2 * 2 + 1] += p10.x * gw0.x + p10.y * gw0.y
                                + p11.x * gw8.x + p11.y * gw8.y;
                ahi[s2][kt][0] = cvt_bf16x2(p00.y, p00.x);
                ahi[s2][kt][1] = cvt_bf16x2(p10.y, p10.x);
                ahi[s2][kt][2] = cvt_bf16x2(p01.y, p01.x);
                ahi[s2][kt][3] = cvt_bf16x2(p11.y, p11.x);
            }
        }
        #pragma unroll
        for (int i = 0; i < 4; i++) {
            gd[i] += __shfl_xor_sync(~0u, gd[i], 1);
            gd[i] += __shfl_xor_sync(~0u, gd[i], 2);
        }

        // GEMM1: A @ (W1hi + W1lo)
        float acc[2][8][4];
        #pragma unroll
        for (int s2 = 0; s2 < 2; s2++)
            #pragma unroll
            for (int nt = 0; nt < 8; nt++)
                acc[s2][nt][0] = acc[s2][nt][1] = acc[s2][nt][2] = acc[s2][nt][3] = 0.0f;
        #pragma unroll
        for (int nt = 0; nt < 8; nt++) {
            #pragma unroll
            for (int kt = 0; kt < 4; kt++) {
                uint2 bh = W1H[(kt * 8 + nt) * 32 + lane];
                uint2 bl = W1L[(kt * 8 + nt) * 32 + lane];
                #pragma unroll
                for (int s2 = 0; s2 < 2; s2++) {
                    mma_bf16(acc[s2][nt], ahi[s2][kt], bh.x, bh.y);
                    mma_bf16(acc[s2][nt], ahi[s2][kt], bl.x, bl.y);
                }
            }
        }

        // epilogue1: bias c1, relu, repack as A2
        uint32_t yhi[2][4][4];
        #pragma unroll
        for (int kt2 = 0; kt2 < 4; kt2++) {
            #pragma unroll
            for (int half = 0; half < 2; half++) {
                int nt = kt2 * 2 + half;
                int col = nt * 8 + 2 * tig;
                float2 cb = *(const float2*)(C1S + col);
                #pragma unroll
                for (int s2 = 0; s2 < 2; s2++) {
                    float y0 = fmaxf(acc[s2][nt][0] + cb.x, 0.0f);
                    float y1 = fmaxf(acc[s2][nt][1] + cb.y, 0.0f);
                    float y2 = fmaxf(acc[s2][nt][2] + cb.x, 0.0f);
                    float y3 = fmaxf(acc[s2][nt][3] + cb.y, 0.0f);
                    yhi[s2][kt2][half * 2 + 0] = cvt_bf16x2(y1, y0);
                    yhi[s2][kt2][half * 2 + 1] = cvt_bf16x2(y3, y2);
                }
            }
        }

        // GEMM2: Y @ (W2hi + W2lo)
        #pragma unroll
        for (int s2 = 0; s2 < 2; s2++)
            #pragma unroll
            for (int nt = 0; nt < 8; nt++)
                acc[s2][nt][0] = acc[s2][nt][1] = acc[s2][nt][2] = acc[s2][nt][3] = 0.0f;
        #pragma unroll
        for (int nt = 0; nt < 8; nt++) {
            #pragma unroll
            for (int kt = 0; kt < 4; kt++) {
                uint2 bh = W2H[(kt * 8 + nt) * 32 + lane];
                uint2 bl = W2L[(kt * 8 + nt) * 32 + lane];
                #pragma unroll
                for (int s2 = 0; s2 < 2; s2++) {
                    mma_bf16(acc[s2][nt], yhi[s2][kt], bh.x, bh.y);
                    mma_bf16(acc[s2][nt], yhi[s2][kt], bl.x, bl.y);
                }
            }
        }

        // epilogue2: f = D2 + b2; out = x + g*(f - x)
        #pragma unroll
        for (int s2 = 0; s2 < 2; s2++) {
            int rA = ra + s2 * 16, rB = rA + 8;
            float ga = 1.0f / (1.0f + __expf(-(gd[2 * s2 + 0] + cgv)));
            float gb = 1.0f / (1.0f + __expf(-(gd[2 * s2 + 1] + cgv)));
            #pragma unroll
            for (int nt = 0; nt < 8; nt++) {
                int col = nt * 8 + 2 * tig;
                float2 b2v = *(const float2*)(B2S + col);
                float2 xa = *(const float2*)(xb + rA * Hn + col);
                float2 xv = *(const float2*)(xb + rB * Hn + col);
                float f0 = acc[s2][nt][0] + b2v.x;
                float f1 = acc[s2][nt][1] + b2v.y;
                float f2 = acc[s2][nt][2] + b2v.x;
                float f3 = acc[s2][nt][3] + b2v.y;
                float2 oa, ob;
                oa.x = xa.x + ga * (f0 - xa.x);
                oa.y = xa.y + ga * (f1 - xa.y);
                ob.x = xv.x + gb * (f2 - xv.x);
                ob.y = xv.y + gb * (f3 - xv.y);
                *(float2*)(op + rA * Hn + col) = oa;
                *(float2*)(op + rB * Hn + col) = ob;
            }
        }
    }
}

// ---------------------------------------------------------------------------
// K3: fixup special rows + reset tile counter for next graph replay.
// grid = Bn*5, each block handles 4 edges (2 rounds of 2).
// ---------------------------------------------------------------------------
#define F_W1 0
#define F_W2 16384
#define F_XS 32768
#define F_YS 33280
#define F_GW 33792
#define F_B2 34048
#define F_ZR 34304
#define F_ER 34320
#define SMEM_K3 34432

__global__ __launch_bounds__(128)
void k3_fix(const int* __restrict__ etype,
            const float* __restrict__ base,
            const float* __restrict__ fus_W1,
            const float* __restrict__ fus_W2,
            const float* __restrict__ fus_b2,
            const float* __restrict__ gate_W,
            float* __restrict__ out) {
    extern __shared__ __align__(16) char sm[];
    float* W1s = (float*)(sm + F_W1);
    float* W2s = (float*)(sm + F_W2);
    float (*xs)[Hn] = (float(*)[Hn])(sm + F_XS);
    float (*ys)[Hn] = (float(*)[Hn])(sm + F_YS);
    float* gws = (float*)(sm + F_GW);
    float* b2s = (float*)(sm + F_B2);
    float* zr  = (float*)(sm + F_ZR);
    int*   er  = (int*)(sm + F_ER);

    const int b = blockIdx.x / 5;
    const int chunk = blockIdx.x % 5;
    const int tid = threadIdx.x;
    const int h = tid >> 6, j = tid & 63, w2 = tid >> 5;

    if (tid == 0) g_tile_ctr = 0;   // reset for next replay (race-free: same value)

    for (int idx = tid; idx < Hn * Hn; idx += 128) {
        W1s[idx] = fus_W1[idx];
        W2s[idx] = fus_W2[idx];
    }
    if (tid < 4) er[tid] = etype[b * En + chunk * 4 + tid];
    if (tid >= 32 && tid < 96) gws[tid - 32] = gate_W[tid - 32];
    if (tid >= 96 && tid < 128) { b2s[tid - 96] = fus_b2[tid - 96];
                                  b2s[tid - 64] = fus_b2[tid - 64]; }
    __syncthreads();

    for (int it = 0; it < 2; it++) {
        int el = it * 2 + h;
        int e  = chunk * 4 + el;
        int r  = er[el];
        float xv = base[((size_t)(b * Rn + r)) * Hn + j];
        xs[h][j] = xv;
        float zp = xv * gws[j];
        #pragma unroll
        for (int o = 16; o > 0; o >>= 1) zp += __shfl_xor_sync(~0u, zp, o);
        if ((tid & 31) == 0) zr[w2] = zp;
        __syncthreads();

        float y = g_q1[((size_t)b * En + e) * Hn + j];
        #pragma unroll 8
        for (int k = 0; k < Hn; k++) y = fmaf(xs[h][k], W1s[k * Hn + j], y);
        ys[h][j] = fmaxf(y, 0.0f);
        __syncthreads();

        float f = b2s[j];
        #pragma unroll 8
        for (int k = 0; k < Hn; k++) f = fmaf(ys[h][k], W2s[k * Hn + j], f);
        float z = zr[2 * h] + zr[2 * h + 1] + g_qg[b * En + e];
        float gg = 1.0f / (1.0f + __expf(-z));
        out[((size_t)(b * Rn + r)) * Hn + j] = xv + gg * (f - xv);
        __syncthreads();
    }
}

// ---------------------------------------------------------------------------
extern "C" void kernel_launch(void* const* d_in, const int* in_sizes, int n_in,
                              void* d_out, int out_size) {
    const int*   qrel   = (const int*)  d_in[0];
    const int*   etype  = (const int*)  d_in[1];
    const float* base   = (const float*)d_in[2];
    const float* noise  = (const float*)d_in[3];
    const float* msg_W  = (const float*)d_in[4];
    const float* msg_b  = (const float*)d_in[5];
    const float* upd_W  = (const float*)d_in[6];
    const float* upd_b  = (const float*)d_in[7];
    const float* ln_g   = (const float*)d_in[8];
    const float* ln_b   = (const float*)d_in[9];
    const float* fus_W1 = (const float*)d_in[10];
    const float* fus_b1 = (const float*)d_in[11];
    const float* fus_W2 = (const float*)d_in[12];
    const float* fus_b2 = (const float*)d_in[13];
    const float* gate_W = (const float*)d_in[14];
    const float* gate_b = (const float*)d_in[15];
    float* out = (float*)d_out;

    cudaFuncSetAttribute(k2_fused, cudaFuncAttributeMaxDynamicSharedMemorySize,
                         SMEM_K2);
    k2_fused<<<NWORK, NTHR, SMEM_K2>>>(
        qrel, etype, noise, msg_W, msg_b, upd_W, upd_b, ln_g, ln_b,
        fus_W1, fus_b1, gate_W, gate_b, base, fus_W2, fus_b2, out);

    cudaFuncSetAttribute(k3_fix, cudaFuncAttributeMaxDynamicSharedMemorySize,
                         SMEM_K3);
    k3_fix<<<Bn * 5, 128, SMEM_K3>>>(etype, base, fus_W1, fus_W2, fus_b2,
                                     gate_W, out);
}

// round 12
// speedup vs baseline: 2.9554x; 1.1375x over previous
#include <cuda_runtime.h>
#include <cuda_bf16.h>
#include <math.h>
#include <stdint.h>

#define Bn 256
#define Rn 2048
#define Hn 64
#define En 20
#define LN_EPSF 1e-5f
#define NTILES (Bn * (Rn / 128))   // 4096
#define NWORK  592                 // 4 CTAs/SM * 148 SMs
#define NFIXB  80                  // fixup blocks (80*4 warps = 320 slabs)

// device scratch (no allocs allowed)
__device__ __align__(16) float g_q1[Bn * En * Hn];
__device__ float g_qg[Bn * En];
__device__ int g_tile_ctr;          // reset by k_reset each launch
__device__ int g_done;              // reset by k_reset each launch

static __device__ __forceinline__ uint32_t cvt_bf16x2(float e1, float e0) {
    uint32_t r;
    asm("cvt.rn.bf16x2.f32 %0, %1, %2;" : "=r"(r) : "f"(e1), "f"(e0));
    return r;
}
static __device__ __forceinline__ float bf_lo(uint32_t r) {
    return __uint_as_float(r << 16);
}
static __device__ __forceinline__ float bf_hi(uint32_t r) {
    return __uint_as_float(r & 0xFFFF0000u);
}
static __device__ __forceinline__ void mma_bf16(float* c, const uint32_t* a,
                                                uint32_t b0, uint32_t b1) {
    asm volatile(
        "mma.sync.aligned.m16n8k16.row.col.f32.bf16.bf16.f32 "
        "{%0,%1,%2,%3}, {%4,%5,%6,%7}, {%8,%9}, {%0,%1,%2,%3};"
        : "+f"(c[0]), "+f"(c[1]), "+f"(c[2]), "+f"(c[3])
        : "r"(a[0]), "r"(a[1]), "r"(a[2]), "r"(a[3]), "r"(b0), "r"(b1));
}

// ---------------------------------------------------------------------------
// K2: single persistent kernel (592 CTAs, 1 wave).
//   blocks [0,256): per-sample prompt pipeline first, then join worker pool.
//   all blocks: self-stage W fragments + c1/cg, claim tiles dynamically.
//   after pool drain: blocks [0,80) fix the special rows via mma + q1/qg.
// ---------------------------------------------------------------------------
#define NTHR 128
// fusion smem
#define OW1H 0
#define OW1L 8192
#define OW2H 16384
#define OW2L 24576
#define OGWA 32768
#define OC1  33024
#define OB2  33280
#define OP0  33536
#define OCG  33792
#define OTIL 33808
// prompt smem (aliases; used before fusion staging)
#define P_WSUM 0
#define P_WUPD 16384
#define P_HS   32768
#define P_MS   37888
#define P_ER   43008
#define SMEM_K2 43136

__global__ __launch_bounds__(NTHR, 4)
void k2_fused(const int* __restrict__ qrel,
              const int* __restrict__ etype,
              const float* __restrict__ noise,
              const float* __restrict__ msg_W,
              const float* __restrict__ msg_b,
              const float* __restrict__ upd_W,
              const float* __restrict__ upd_b,
              const float* __restrict__ ln_g,
              const float* __restrict__ ln_b,
              const float* __restrict__ fus_W1,
              const float* __restrict__ fus_b1,
              const float* __restrict__ gate_W,
              const float* __restrict__ gate_b,
              const float* __restrict__ base,
              const float* __restrict__ fus_W2,
              const float* __restrict__ fus_b2,
              float* __restrict__ out) {
    extern __shared__ __align__(16) char sm[];
    const int tid = threadIdx.x;
    const int w = tid >> 5, lane = tid & 31;

    if (blockIdx.x < Bn) {
        // ================= prompt pipeline =================
        const int b  = blockIdx.x;
        const int j  = tid & 63;
        const int eg = tid >> 6;
        float* Wsum = (float*)(sm + P_WSUM);
        float* Wupd = (float*)(sm + P_WUPD);
        float (*hs)[Hn] = (float(*)[Hn])(sm + P_HS);
        float (*ms)[Hn] = (float(*)[Hn])(sm + P_MS);
        int* er = (int*)(sm + P_ER);

        for (int idx = tid; idx < Hn * Hn; idx += NTHR) {
            Wsum[idx] = msg_W[idx] + msg_W[Hn * Hn + idx];
            Wupd[idx] = upd_W[idx];
        }
        if (tid < En) er[tid] = etype[b * En + tid];
        __syncthreads();

        int qr = qrel[b];
        for (int e = eg; e < En; e += 2) {
            int r = er[e];
            hs[e][j] = (r == qr) ? 1.0f
                                 : noise[((size_t)b * Rn + r) * Hn + j] * 0.1f;
        }
        __syncthreads();

        for (int e = eg; e < En; e += 2) {
            float m = msg_b[j];
            #pragma unroll 8
            for (int k = 0; k < Hn; k++) m = fmaf(hs[e][k], Wsum[k * Hn + j], m);
            ms[e][j] = fmaxf(m, 0.0f);
        }
        __syncthreads();

        for (int e = eg; e < En; e += 2) {
            float a = 0.0f;
            int re = er[e];
            #pragma unroll
            for (int e2 = 0; e2 < En; e2++)
                if (er[e2] == re) a += ms[e2][j];
            hs[e][j] = a;
        }
        for (int idx = tid; idx < Hn * Hn; idx += NTHR)
            Wsum[idx] = fus_W1[Hn * Hn + idx];   // W1b for q1
        __syncthreads();

        for (int e = eg; e < En; e += 2) {
            float u = upd_b[j];
            #pragma unroll 8
            for (int k = 0; k < Hn; k++) u = fmaf(hs[e][k], Wupd[k * Hn + j], u);
            ms[e][j] = u;
        }
        __syncthreads();

        for (int e = w; e < En; e += 4) {
            float v0 = ms[e][lane], v1 = ms[e][lane + 32];
            float s = v0 + v1;
            #pragma unroll
            for (int o = 16; o > 0; o >>= 1) s += __shfl_xor_sync(~0u, s, o);
            float mu = s * (1.0f / Hn);
            float d0 = v0 - mu, d1 = v1 - mu;
            s = d0 * d0 + d1 * d1;
            #pragma unroll
            for (int o = 16; o > 0; o >>= 1) s += __shfl_xor_sync(~0u, s, o);
            float inv = rsqrtf(s * (1.0f / Hn) + LN_EPSF);
            ms[e][lane]      = d0 * inv * ln_g[lane] + ln_b[lane];
            ms[e][lane + 32] = d1 * inv * ln_g[lane + 32] + ln_b[lane + 32];
        }
        __syncthreads();

        for (int e = eg; e < En; e += 2) {
            float q = fus_b1[j];
            #pragma unroll 8
            for (int k = 0; k < Hn; k++) q = fmaf(ms[e][k], Wsum[k * Hn + j], q);
            g_q1[((size_t)b * En + e) * Hn + j] = q;
        }
        for (int e = w; e < En; e += 4) {
            float s = ms[e][lane] * gate_W[Hn + lane]
                    + ms[e][lane + 32] * gate_W[Hn + lane + 32];
            #pragma unroll
            for (int o = 16; o > 0; o >>= 1) s += __shfl_xor_sync(~0u, s, o);
            if (lane == 0) g_qg[b * En + e] = s + gate_b[0];
        }
        __syncthreads();   // prompt done; smem reused for fusion
    }

    // ================= fusion worker setup =================
    uint2* W1H = (uint2*)(sm + OW1H);
    uint2* W1L = (uint2*)(sm + OW1L);
    uint2* W2H = (uint2*)(sm + OW2H);
    uint2* W2L = (uint2*)(sm + OW2L);
    float* GWA = (float*)(sm + OGWA);
    float* C1S = (float*)(sm + OC1);
    float* B2S = (float*)(sm + OB2);
    float* P0S = (float*)(sm + OP0);
    float* CGS = (float*)(sm + OCG);
    int*   TIL = (int*)(sm + OTIL);

    #pragma unroll
    for (int s = 0; s < 8; s++) {
        int idx = tid + s * NTHR;
        int l = idx & 31;
        int t2 = idx >> 5;
        int nt = t2 & 7, kt = t2 >> 3;
        int n  = nt * 8 + (l >> 2);
        int k0 = kt * 16 + (l & 3) * 2;
        {
            float w00 = fus_W1[k0 * Hn + n];
            float w01 = fus_W1[(k0 + 1) * Hn + n];
            float w08 = fus_W1[(k0 + 8) * Hn + n];
            float w09 = fus_W1[(k0 + 9) * Hn + n];
            uint32_t hx = cvt_bf16x2(w01, w00);
            uint32_t hy = cvt_bf16x2(w09, w08);
            W1H[idx] = make_uint2(hx, hy);
            W1L[idx] = make_uint2(
                cvt_bf16x2(w01 - bf_hi(hx), w00 - bf_lo(hx)),
                cvt_bf16x2(w09 - bf_hi(hy), w08 - bf_lo(hy)));
        }
        {
            float w00 = fus_W2[k0 * Hn + n];
            float w01 = fus_W2[(k0 + 1) * Hn + n];
            float w08 = fus_W2[(k0 + 8) * Hn + n];
            float w09 = fus_W2[(k0 + 9) * Hn + n];
            uint32_t hx = cvt_bf16x2(w01, w00);
            uint32_t hy = cvt_bf16x2(w09, w08);
            W2H[idx] = make_uint2(hx, hy);
            W2L[idx] = make_uint2(
                cvt_bf16x2(w01 - bf_hi(hx), w00 - bf_lo(hx)),
                cvt_bf16x2(w09 - bf_hi(hy), w08 - bf_lo(hy)));
        }
    }
    if (w == 0) {
        float v0 = upd_b[lane], v1 = upd_b[lane + 32];
        float s = v0 + v1;
        #pragma unroll
        for (int o = 16; o > 0; o >>= 1) s += __shfl_xor_sync(~0u, s, o);
        float mu = s * (1.0f / Hn);
        float d0 = v0 - mu, d1 = v1 - mu;
        s = d0 * d0 + d1 * d1;
        #pragma unroll
        for (int o = 16; o > 0; o >>= 1) s += __shfl_xor_sync(~0u, s, o);
        float inv = rsqrtf(s * (1.0f / Hn) + LN_EPSF);
        P0S[lane]      = d0 * inv * ln_g[lane] + ln_b[lane];
        P0S[lane + 32] = d1 * inv * ln_g[lane + 32] + ln_b[lane + 32];
    }
    __syncthreads();

    if (tid < Hn) {
        float c = fus_b1[tid];
        #pragma unroll 8
        for (int k = 0; k < Hn; k++)
            c = fmaf(P0S[k], fus_W1[(Hn + k) * Hn + tid], c);
        C1S[tid] = c;
    }
    if (w == 2) {
        float s = P0S[lane] * gate_W[Hn + lane]
                + P0S[lane + 32] * gate_W[Hn + lane + 32];
        #pragma unroll
        for (int o = 16; o > 0; o >>= 1) s += __shfl_xor_sync(~0u, s, o);
        if (lane == 0) CGS[0] = s + gate_b[0];
    }
    if (w == 3) {
        if (lane < 16) ((float4*)GWA)[lane] = ((const float4*)gate_W)[lane];
        else ((float4*)B2S)[lane - 16] = ((const float4*)fus_b2)[lane - 16];
    }
    __syncthreads();

    const float cgv = CGS[0];
    const int g = lane >> 2, tig = lane & 3;
    const int ra = (w << 5) + g;

    // ================= persistent tile loop =================
    for (;;) {
        if (tid == 0) TIL[0] = atomicAdd(&g_tile_ctr, 1);
        __syncthreads();
        const int t = TIL[0];
        __syncthreads();
        if (t >= NTILES) break;

        const int b  = t >> 4;
        const int r0 = (t & 15) << 7;
        const float* xb = base + ((size_t)(b * Rn + r0)) * Hn;
        float* op = out + ((size_t)(b * Rn + r0)) * Hn;

        uint32_t ahi[2][4][4];
        float gd[4] = {0.0f, 0.0f, 0.0f, 0.0f};
        #pragma unroll
        for (int s2 = 0; s2 < 2; s2++) {
            int rA = ra + s2 * 16, rB = rA + 8;
            #pragma unroll
            for (int kt = 0; kt < 4; kt++) {
                int c0 = kt * 16 + 2 * tig;
                float2 p00 = *(const float2*)(xb + rA * Hn + c0);
                float2 p10 = *(const float2*)(xb + rB * Hn + c0);
                float2 p01 = *(const float2*)(xb + rA * Hn + c0 + 8);
                float2 p11 = *(const float2*)(xb + rB * Hn + c0 + 8);
                float2 gw0 = *(const float2*)(GWA + c0);
                float2 gw8 = *(const float2*)(GWA + c0 + 8);
                gd[s2 * 2 + 0] += p00.x * gw0.x + p00.y * gw0.y
                                + p01.x * gw8.x + p01.y * gw8.y;
                gd[s2 * 2 + 1] += p10.x * gw0.x + p10.y * gw0.y
                                + p11.x * gw8.x + p11.y * gw8.y;
                ahi[s2][kt][0] = cvt_bf16x2(p00.y, p00.x);
                ahi[s2][kt][1] = cvt_bf16x2(p10.y, p10.x);
                ahi[s2][kt][2] = cvt_bf16x2(p01.y, p01.x);
                ahi[s2][kt][3] = cvt_bf16x2(p11.y, p11.x);
            }
        }
        #pragma unroll
        for (int i = 0; i < 4; i++) {
            gd[i] += __shfl_xor_sync(~0u, gd[i], 1);
            gd[i] += __shfl_xor_sync(~0u, gd[i], 2);
        }

        // GEMM1: kt outer, nt inner (RAW distance 32)
        float acc[2][8][4];
        #pragma unroll
        for (int s2 = 0; s2 < 2; s2++)
            #pragma unroll
            for (int nt = 0; nt < 8; nt++)
                acc[s2][nt][0] = acc[s2][nt][1] = acc[s2][nt][2] = acc[s2][nt][3] = 0.0f;
        #pragma unroll
        for (int kt = 0; kt < 4; kt++) {
            #pragma unroll
            for (int nt = 0; nt < 8; nt++) {
                uint2 bh = W1H[(kt * 8 + nt) * 32 + lane];
                uint2 bl = W1L[(kt * 8 + nt) * 32 + lane];
                #pragma unroll
                for (int s2 = 0; s2 < 2; s2++) {
                    mma_bf16(acc[s2][nt], ahi[s2][kt], bh.x, bh.y);
                    mma_bf16(acc[s2][nt], ahi[s2][kt], bl.x, bl.y);
                }
            }
        }

        // epilogue1: bias c1, relu, repack as A2
        uint32_t yhi[2][4][4];
        #pragma unroll
        for (int kt2 = 0; kt2 < 4; kt2++) {
            #pragma unroll
            for (int half = 0; half < 2; half++) {
                int nt = kt2 * 2 + half;
                int col = nt * 8 + 2 * tig;
                float2 cb = *(const float2*)(C1S + col);
                #pragma unroll
                for (int s2 = 0; s2 < 2; s2++) {
                    float y0 = fmaxf(acc[s2][nt][0] + cb.x, 0.0f);
                    float y1 = fmaxf(acc[s2][nt][1] + cb.y, 0.0f);
                    float y2 = fmaxf(acc[s2][nt][2] + cb.x, 0.0f);
                    float y3 = fmaxf(acc[s2][nt][3] + cb.y, 0.0f);
                    yhi[s2][kt2][half * 2 + 0] = cvt_bf16x2(y1, y0);
                    yhi[s2][kt2][half * 2 + 1] = cvt_bf16x2(y3, y2);
                }
            }
        }

        // GEMM2: kt outer, nt inner
        #pragma unroll
        for (int s2 = 0; s2 < 2; s2++)
            #pragma unroll
            for (int nt = 0; nt < 8; nt++)
                acc[s2][nt][0] = acc[s2][nt][1] = acc[s2][nt][2] = acc[s2][nt][3] = 0.0f;
        #pragma unroll
        for (int kt = 0; kt < 4; kt++) {
            #pragma unroll
            for (int nt = 0; nt < 8; nt++) {
                uint2 bh = W2H[(kt * 8 + nt) * 32 + lane];
                uint2 bl = W2L[(kt * 8 + nt) * 32 + lane];
                #pragma unroll
                for (int s2 = 0; s2 < 2; s2++) {
                    mma_bf16(acc[s2][nt], yhi[s2][kt], bh.x, bh.y);
                    mma_bf16(acc[s2][nt], yhi[s2][kt], bl.x, bl.y);
                }
            }
        }

        // epilogue2
        #pragma unroll
        for (int s2 = 0; s2 < 2; s2++) {
            int rA = ra + s2 * 16, rB = rA + 8;
            float ga = 1.0f / (1.0f + __expf(-(gd[2 * s2 + 0] + cgv)));
            float gb = 1.0f / (1.0f + __expf(-(gd[2 * s2 + 1] + cgv)));
            #pragma unroll
            for (int nt = 0; nt < 8; nt++) {
                int col = nt * 8 + 2 * tig;
                float2 b2v = *(const float2*)(B2S + col);
                float2 xa = *(const float2*)(xb + rA * Hn + col);
                float2 xv = *(const float2*)(xb + rB * Hn + col);
                float f0 = acc[s2][nt][0] + b2v.x;
                float f1 = acc[s2][nt][1] + b2v.y;
                float f2 = acc[s2][nt][2] + b2v.x;
                float f3 = acc[s2][nt][3] + b2v.y;
                float2 oa, ob;
                oa.x = xa.x + ga * (f0 - xa.x);
                oa.y = xa.y + ga * (f1 - xa.y);
                ob.x = xv.x + gb * (f2 - xv.x);
                ob.y = xv.y + gb * (f3 - xv.y);
                *(float2*)(op + rA * Hn + col) = oa;
                *(float2*)(op + rB * Hn + col) = ob;
            }
        }
    }

    // ================= drain barrier + special-row fixup =================
    if (tid == 0) {
        __threadfence();
        atomicAdd(&g_done, 1);
    }
    if (blockIdx.x >= NFIXB) return;

    if (tid == 0) {
        while (*(volatile int*)&g_done < NWORK) {}
    }
    __syncthreads();
    __threadfence();

    {
        const int slab = blockIdx.x * 4 + w;    // 0..319, 16 rows each
        const int f0 = slab * 16 + g;           // flat (b*En+e) indices
        const int f1 = f0 + 8;
        const int b0 = f0 / En, b1 = f1 / En;
        const int r0r = etype[f0], r1r = etype[f1];
        const float* x0 = base + ((size_t)(b0 * Rn + r0r)) * Hn;
        const float* x1 = base + ((size_t)(b1 * Rn + r1r)) * Hn;
        float* o0 = out + ((size_t)(b0 * Rn + r0r)) * Hn;
        float* o1 = out + ((size_t)(b1 * Rn + r1r)) * Hn;
        const float* q10 = g_q1 + (size_t)f0 * Hn;
        const float* q11 = g_q1 + (size_t)f1 * Hn;

        uint32_t ahi[4][4];
        float gd0 = 0.0f, gd1 = 0.0f;
        #pragma unroll
        for (int kt = 0; kt < 4; kt++) {
            int c0 = kt * 16 + 2 * tig;
            float2 p00 = *(const float2*)(x0 + c0);
            float2 p10 = *(const float2*)(x1 + c0);
            float2 p01 = *(const float2*)(x0 + c0 + 8);
            float2 p11 = *(const float2*)(x1 + c0 + 8);
            float2 gw0 = *(const float2*)(GWA + c0);
            float2 gw8 = *(const float2*)(GWA + c0 + 8);
            gd0 += p00.x * gw0.x + p00.y * gw0.y + p01.x * gw8.x + p01.y * gw8.y;
            gd1 += p10.x * gw0.x + p10.y * gw0.y + p11.x * gw8.x + p11.y * gw8.y;
            ahi[kt][0] = cvt_bf16x2(p00.y, p00.x);
            ahi[kt][1] = cvt_bf16x2(p10.y, p10.x);
            ahi[kt][2] = cvt_bf16x2(p01.y, p01.x);
            ahi[kt][3] = cvt_bf16x2(p11.y, p11.x);
        }
        gd0 += __shfl_xor_sync(~0u, gd0, 1);
        gd0 += __shfl_xor_sync(~0u, gd0, 2);
        gd1 += __shfl_xor_sync(~0u, gd1, 1);
        gd1 += __shfl_xor_sync(~0u, gd1, 2);

        float acc[8][4];
        #pragma unroll
        for (int nt = 0; nt < 8; nt++)
            acc[nt][0] = acc[nt][1] = acc[nt][2] = acc[nt][3] = 0.0f;
        #pragma unroll
        for (int kt = 0; kt < 4; kt++) {
            #pragma unroll
            for (int nt = 0; nt < 8; nt++) {
                uint2 bh = W1H[(kt * 8 + nt) * 32 + lane];
                uint2 bl = W1L[(kt * 8 + nt) * 32 + lane];
                mma_bf16(acc[nt], ahi[kt], bh.x, bh.y);
                mma_bf16(acc[nt], ahi[kt], bl.x, bl.y);
            }
        }

        uint32_t yhi[4][4];
        #pragma unroll
        for (int kt2 = 0; kt2 < 4; kt2++) {
            #pragma unroll
            for (int half = 0; half < 2; half++) {
                int nt = kt2 * 2 + half;
                int col = nt * 8 + 2 * tig;
                float2 ba = *(const float2*)(q10 + col);
                float2 bb = *(const float2*)(q11 + col);
                float y0 = fmaxf(acc[nt][0] + ba.x, 0.0f);
                float y1 = fmaxf(acc[nt][1] + ba.y, 0.0f);
                float y2 = fmaxf(acc[nt][2] + bb.x, 0.0f);
                float y3 = fmaxf(acc[nt][3] + bb.y, 0.0f);
                yhi[kt2][half * 2 + 0] = cvt_bf16x2(y1, y0);
                yhi[kt2][half * 2 + 1] = cvt_bf16x2(y3, y2);
            }
        }

        #pragma unroll
        for (int nt = 0; nt < 8; nt++)
            acc[nt][0] = acc[nt][1] = acc[nt][2] = acc[nt][3] = 0.0f;
        #pragma unroll
        for (int kt = 0; kt < 4; kt++) {
            #pragma unroll
            for (int nt = 0; nt < 8; nt++) {
                uint2 bh = W2H[(kt * 8 + nt) * 32 + lane];
                uint2 bl = W2L[(kt * 8 + nt) * 32 + lane];
                mma_bf16(acc[nt], yhi[kt], bh.x, bh.y);
                mma_bf16(acc[nt], yhi[kt], bl.x, bl.y);
            }
        }

        float ga = 1.0f / (1.0f + __expf(-(gd0 + g_qg[f0])));
        float gb = 1.0f / (1.0f + __expf(-(gd1 + g_qg[f1])));
        #pragma unroll
        for (int nt = 0; nt < 8; nt++) {
            int col = nt * 8 + 2 * tig;
            float2 b2v = *(const float2*)(B2S + col);
            float2 xa = *(const float2*)(x0 + col);
            float2 xv = *(const float2*)(x1 + col);
            float f0v = acc[nt][0] + b2v.x;
            float f1v = acc[nt][1] + b2v.y;
            float f2v = acc[nt][2] + b2v.x;
            float f3v = acc[nt][3] + b2v.y;
            float2 oa, ob;
            oa.x = xa.x + ga * (f0v - xa.x);
            oa.y = xa.y + ga * (f1v - xa.y);
            ob.x = xv.x + gb * (f2v - xv.x);
            ob.y = xv.y + gb * (f3v - xv.y);
            *(float2*)(o0 + col) = oa;
            *(float2*)(o1 + col) = ob;
        }
    }
}

// ---------------------------------------------------------------------------
// K_RESET: restore counters for next graph replay.
// ---------------------------------------------------------------------------
__global__ void k_reset() {
    g_tile_ctr = 0;
    g_done = 0;
}

// ---------------------------------------------------------------------------
extern "C" void kernel_launch(void* const* d_in, const int* in_sizes, int n_in,
                              void* d_out, int out_size) {
    const int*   qrel   = (const int*)  d_in[0];
    const int*   etype  = (const int*)  d_in[1];
    const float* base   = (const float*)d_in[2];
    const float* noise  = (const float*)d_in[3];
    const float* msg_W  = (const float*)d_in[4];
    const float* msg_b  = (const float*)d_in[5];
    const float* upd_W  = (const float*)d_in[6];
    const float* upd_b  = (const float*)d_in[7];
    const float* ln_g   = (const float*)d_in[8];
    const float* ln_b   = (const float*)d_in[9];
    const float* fus_W1 = (const float*)d_in[10];
    const float* fus_b1 = (const float*)d_in[11];
    const float* fus_W2 = (const float*)d_in[12];
    const float* fus_b2 = (const float*)d_in[13];
    const float* gate_W = (const float*)d_in[14];
    const float* gate_b = (const float*)d_in[15];
    float* out = (float*)d_out;

    cudaFuncSetAttribute(k2_fused, cudaFuncAttributeMaxDynamicSharedMemorySize,
                         SMEM_K2);
    k2_fused<<<NWORK, NTHR, SMEM_K2>>>(
        qrel, etype, noise, msg_W, msg_b, upd_W, upd_b, ln_g, ln_b,
        fus_W1, fus_b1, gate_W, gate_b, base, fus_W2, fus_b2, out);

    k_reset<<<1, 1>>>();
}

// round 13
// speedup vs baseline: 3.3886x; 1.1466x over previous
#include <cuda_runtime.h>
#include <cuda_bf16.h>
#include <math.h>
#include <stdint.h>

#define Bn 256
#define Rn 2048
#define Hn 64
#define En 20
#define LN_EPSF 1e-5f
#define NTILES (Bn * (Rn / 128))   // 4096
#define NWORK  592                 // 4 CTAs/SM x 148 SMs
#define NFIXB  80                  // fixup blocks (80*4 warps = 320 slabs)
#define CLAIMS_PER_EPOCH (NTILES + NWORK)

// device scratch (no allocs allowed); counters are monotonic (epoch arithmetic)
__device__ __align__(16) float g_q1[Bn * En * Hn];
__device__ float g_qg[Bn * En];
__device__ int g_tile_ctr;
__device__ int g_done;

static __device__ __forceinline__ uint32_t cvt_bf16x2(float e1, float e0) {
    uint32_t r;
    asm("cvt.rn.bf16x2.f32 %0, %1, %2;" : "=r"(r) : "f"(e1), "f"(e0));
    return r;
}
static __device__ __forceinline__ void mma_bf16(float* c, const uint32_t* a,
                                                uint32_t b0, uint32_t b1) {
    asm volatile(
        "mma.sync.aligned.m16n8k16.row.col.f32.bf16.bf16.f32 "
        "{%0,%1,%2,%3}, {%4,%5,%6,%7}, {%8,%9}, {%0,%1,%2,%3};"
        : "+f"(c[0]), "+f"(c[1]), "+f"(c[2]), "+f"(c[3])
        : "r"(a[0]), "r"(a[1]), "r"(a[2]), "r"(a[3]), "r"(b0), "r"(b1));
}

// ---------------------------------------------------------------------------
// K2: THE kernel. 592 persistent CTAs, one launch, no auxiliary kernels.
//   blocks [0,256): per-sample prompt pipeline first, then join worker pool.
//   all blocks: self-stage W fragments (plain bf16) + c1/cg, claim tiles.
//   after pool drain (epoch barrier): blocks [0,80) fix special rows.
// ---------------------------------------------------------------------------
#define NTHR 128
// fusion smem
#define OW1F 0
#define OW2F 8192
#define OGWA 16384
#define OC1  16640
#define OB2  16896
#define OP0  17152
#define OCG  17408
#define OTIL 17424
// prompt smem (aliases same buffer; used before fusion staging)
#define P_WSUM 0
#define P_HS   16384
#define P_MS   21504
#define P_ER   26624
#define SMEM_K2 26752

__global__ __launch_bounds__(NTHR, 4)
void k2_fused(const int* __restrict__ qrel,
              const int* __restrict__ etype,
              const float* __restrict__ noise,
              const float* __restrict__ msg_W,
              const float* __restrict__ msg_b,
              const float* __restrict__ upd_W,
              const float* __restrict__ upd_b,
              const float* __restrict__ ln_g,
              const float* __restrict__ ln_b,
              const float* __restrict__ fus_W1,
              const float* __restrict__ fus_b1,
              const float* __restrict__ gate_W,
              const float* __restrict__ gate_b,
              const float* __restrict__ base,
              const float* __restrict__ fus_W2,
              const float* __restrict__ fus_b2,
              float* __restrict__ out) {
    extern __shared__ __align__(16) char sm[];
    const int tid = threadIdx.x;
    const int w = tid >> 5, lane = tid & 31;

    if (blockIdx.x < Bn) {
        // ================= prompt pipeline =================
        const int b  = blockIdx.x;
        const int j  = tid & 63;
        const int eg = tid >> 6;
        float* Wsum = (float*)(sm + P_WSUM);
        float (*hs)[Hn] = (float(*)[Hn])(sm + P_HS);
        float (*ms)[Hn] = (float(*)[Hn])(sm + P_MS);
        int* er = (int*)(sm + P_ER);

        for (int idx = tid; idx < Hn * Hn; idx += NTHR)
            Wsum[idx] = msg_W[idx] + msg_W[Hn * Hn + idx];
        if (tid < En) er[tid] = etype[b * En + tid];
        __syncthreads();

        int qr = qrel[b];
        for (int e = eg; e < En; e += 2) {
            int r = er[e];
            hs[e][j] = (r == qr) ? 1.0f
                                 : noise[((size_t)b * Rn + r) * Hn + j] * 0.1f;
        }
        __syncthreads();

        for (int e = eg; e < En; e += 2) {
            float m = msg_b[j];
            #pragma unroll 8
            for (int k = 0; k < Hn; k++) m = fmaf(hs[e][k], Wsum[k * Hn + j], m);
            ms[e][j] = fmaxf(m, 0.0f);
        }
        __syncthreads();

        for (int e = eg; e < En; e += 2) {
            float a = 0.0f;
            int re = er[e];
            #pragma unroll
            for (int e2 = 0; e2 < En; e2++)
                if (er[e2] == re) a += ms[e2][j];
            hs[e][j] = a;
        }
        __syncthreads();

        // upd: read upd_W straight from gmem (L2-hot across all prompt blocks)
        for (int e = eg; e < En; e += 2) {
            float u = upd_b[j];
            #pragma unroll 8
            for (int k = 0; k < Hn; k++)
                u = fmaf(hs[e][k], upd_W[k * Hn + j], u);
            ms[e][j] = u;
        }
        // restage Wsum <- W1b for q1
        __syncthreads();
        for (int idx = tid; idx < Hn * Hn; idx += NTHR)
            Wsum[idx] = fus_W1[Hn * Hn + idx];
        __syncthreads();

        for (int e = w; e < En; e += 4) {
            float v0 = ms[e][lane], v1 = ms[e][lane + 32];
            float s = v0 + v1;
            #pragma unroll
            for (int o = 16; o > 0; o >>= 1) s += __shfl_xor_sync(~0u, s, o);
            float mu = s * (1.0f / Hn);
            float d0 = v0 - mu, d1 = v1 - mu;
            s = d0 * d0 + d1 * d1;
            #pragma unroll
            for (int o = 16; o > 0; o >>= 1) s += __shfl_xor_sync(~0u, s, o);
            float inv = rsqrtf(s * (1.0f / Hn) + LN_EPSF);
            ms[e][lane]      = d0 * inv * ln_g[lane] + ln_b[lane];
            ms[e][lane + 32] = d1 * inv * ln_g[lane + 32] + ln_b[lane + 32];
        }
        __syncthreads();

        for (int e = eg; e < En; e += 2) {
            float q = fus_b1[j];
            #pragma unroll 8
            for (int k = 0; k < Hn; k++) q = fmaf(ms[e][k], Wsum[k * Hn + j], q);
            g_q1[((size_t)b * En + e) * Hn + j] = q;
        }
        for (int e = w; e < En; e += 4) {
            float s = ms[e][lane] * gate_W[Hn + lane]
                    + ms[e][lane + 32] * gate_W[Hn + lane + 32];
            #pragma unroll
            for (int o = 16; o > 0; o >>= 1) s += __shfl_xor_sync(~0u, s, o);
            if (lane == 0) g_qg[b * En + e] = s + gate_b[0];
        }
        __syncthreads();   // prompt done; smem reused for fusion
    }

    // ================= fusion worker setup =================
    uint2* W1F = (uint2*)(sm + OW1F);
    uint2* W2F = (uint2*)(sm + OW2F);
    float* GWA = (float*)(sm + OGWA);
    float* C1S = (float*)(sm + OC1);
    float* B2S = (float*)(sm + OB2);
    float* P0S = (float*)(sm + OP0);
    float* CGS = (float*)(sm + OCG);
    int*   TIL = (int*)(sm + OTIL);

    // W fragments, plain bf16 (1-MMA path)
    #pragma unroll
    for (int s = 0; s < 8; s++) {
        int idx = tid + s * NTHR;
        int l = idx & 31;
        int t2 = idx >> 5;
        int nt = t2 & 7, kt = t2 >> 3;
        int n  = nt * 8 + (l >> 2);
        int k0 = kt * 16 + (l & 3) * 2;
        W1F[idx] = make_uint2(
            cvt_bf16x2(fus_W1[(k0 + 1) * Hn + n], fus_W1[k0 * Hn + n]),
            cvt_bf16x2(fus_W1[(k0 + 9) * Hn + n], fus_W1[(k0 + 8) * Hn + n]));
        W2F[idx] = make_uint2(
            cvt_bf16x2(fus_W2[(k0 + 1) * Hn + n], fus_W2[k0 * Hn + n]),
            cvt_bf16x2(fus_W2[(k0 + 9) * Hn + n], fus_W2[(k0 + 8) * Hn + n]));
    }
    if (w == 0) {
        float v0 = upd_b[lane], v1 = upd_b[lane + 32];
        float s = v0 + v1;
        #pragma unroll
        for (int o = 16; o > 0; o >>= 1) s += __shfl_xor_sync(~0u, s, o);
        float mu = s * (1.0f / Hn);
        float d0 = v0 - mu, d1 = v1 - mu;
        s = d0 * d0 + d1 * d1;
        #pragma unroll
        for (int o = 16; o > 0; o >>= 1) s += __shfl_xor_sync(~0u, s, o);
        float inv = rsqrtf(s * (1.0f / Hn) + LN_EPSF);
        P0S[lane]      = d0 * inv * ln_g[lane] + ln_b[lane];
        P0S[lane + 32] = d1 * inv * ln_g[lane + 32] + ln_b[lane + 32];
    }
    __syncthreads();

    if (tid < Hn) {
        float c = fus_b1[tid];
        #pragma unroll 8
        for (int k = 0; k < Hn; k++)
            c = fmaf(P0S[k], fus_W1[(Hn + k) * Hn + tid], c);
        C1S[tid] = c;
    }
    if (w == 2) {
        float s = P0S[lane] * gate_W[Hn + lane]
                + P0S[lane + 32] * gate_W[Hn + lane + 32];
        #pragma unroll
        for (int o = 16; o > 0; o >>= 1) s += __shfl_xor_sync(~0u, s, o);
        if (lane == 0) CGS[0] = s + gate_b[0];
    }
    if (w == 3) {
        if (lane < 16) ((float4*)GWA)[lane] = ((const float4*)gate_W)[lane];
        else ((float4*)B2S)[lane - 16] = ((const float4*)fus_b2)[lane - 16];
    }
    __syncthreads();

    const float cgv = CGS[0];
    const int g = lane >> 2, tig = lane & 3;
    const int ra = (w << 5) + g;

    // ================= persistent tile loop (epoch-claimed) =================
    for (;;) {
        if (tid == 0) TIL[0] = atomicAdd(&g_tile_ctr, 1) % CLAIMS_PER_EPOCH;
        __syncthreads();
        const int t = TIL[0];
        __syncthreads();
        if (t >= NTILES) break;

        const int b  = t >> 4;
        const int r0 = (t & 15) << 7;
        const float* xb = base + ((size_t)(b * Rn + r0)) * Hn;
        float* op = out + ((size_t)(b * Rn + r0)) * Hn;

        uint32_t ahi[2][4][4];
        float gd[4] = {0.0f, 0.0f, 0.0f, 0.0f};
        #pragma unroll
        for (int s2 = 0; s2 < 2; s2++) {
            int rA = ra + s2 * 16, rB = rA + 8;
            #pragma unroll
            for (int kt = 0; kt < 4; kt++) {
                int c0 = kt * 16 + 2 * tig;
                float2 p00 = *(const float2*)(xb + rA * Hn + c0);
                float2 p10 = *(const float2*)(xb + rB * Hn + c0);
                float2 p01 = *(const float2*)(xb + rA * Hn + c0 + 8);
                float2 p11 = *(const float2*)(xb + rB * Hn + c0 + 8);
                float2 gw0 = *(const float2*)(GWA + c0);
                float2 gw8 = *(const float2*)(GWA + c0 + 8);
                gd[s2 * 2 + 0] += p00.x * gw0.x + p00.y * gw0.y
                                + p01.x * gw8.x + p01.y * gw8.y;
                gd[s2 * 2 + 1] += p10.x * gw0.x + p10.y * gw0.y
                                + p11.x * gw8.x + p11.y * gw8.y;
                ahi[s2][kt][0] = cvt_bf16x2(p00.y, p00.x);
                ahi[s2][kt][1] = cvt_bf16x2(p10.y, p10.x);
                ahi[s2][kt][2] = cvt_bf16x2(p01.y, p01.x);
                ahi[s2][kt][3] = cvt_bf16x2(p11.y, p11.x);
            }
        }
        #pragma unroll
        for (int i = 0; i < 4; i++) {
            gd[i] += __shfl_xor_sync(~0u, gd[i], 1);
            gd[i] += __shfl_xor_sync(~0u, gd[i], 2);
        }

        // GEMM1 (kt outer, nt inner; 1 MMA per step)
        float acc[2][8][4];
        #pragma unroll
        for (int s2 = 0; s2 < 2; s2++)
            #pragma unroll
            for (int nt = 0; nt < 8; nt++)
                acc[s2][nt][0] = acc[s2][nt][1] = acc[s2][nt][2] = acc[s2][nt][3] = 0.0f;
        #pragma unroll
        for (int kt = 0; kt < 4; kt++) {
            #pragma unroll
            for (int nt = 0; nt < 8; nt++) {
                uint2 bh = W1F[(kt * 8 + nt) * 32 + lane];
                #pragma unroll
                for (int s2 = 0; s2 < 2; s2++)
                    mma_bf16(acc[s2][nt], ahi[s2][kt], bh.x, bh.y);
            }
        }

        // epilogue1: bias c1, relu, repack as A2
        uint32_t yhi[2][4][4];
        #pragma unroll
        for (int kt2 = 0; kt2 < 4; kt2++) {
            #pragma unroll
            for (int half = 0; half < 2; half++) {
                int nt = kt2 * 2 + half;
                int col = nt * 8 + 2 * tig;
                float2 cb = *(const float2*)(C1S + col);
                #pragma unroll
                for (int s2 = 0; s2 < 2; s2++) {
                    float y0 = fmaxf(acc[s2][nt][0] + cb.x, 0.0f);
                    float y1 = fmaxf(acc[s2][nt][1] + cb.y, 0.0f);
                    float y2 = fmaxf(acc[s2][nt][2] + cb.x, 0.0f);
                    float y3 = fmaxf(acc[s2][nt][3] + cb.y, 0.0f);
                    yhi[s2][kt2][half * 2 + 0] = cvt_bf16x2(y1, y0);
                    yhi[s2][kt2][half * 2 + 1] = cvt_bf16x2(y3, y2);
                }
            }
        }

        // GEMM2
        #pragma unroll
        for (int s2 = 0; s2 < 2; s2++)
            #pragma unroll
            for (int nt = 0; nt < 8; nt++)
                acc[s2][nt][0] = acc[s2][nt][1] = acc[s2][nt][2] = acc[s2][nt][3] = 0.0f;
        #pragma unroll
        for (int kt = 0; kt < 4; kt++) {
            #pragma unroll
            for (int nt = 0; nt < 8; nt++) {
                uint2 bh = W2F[(kt * 8 + nt) * 32 + lane];
                #pragma unroll
                for (int s2 = 0; s2 < 2; s2++)
                    mma_bf16(acc[s2][nt], yhi[s2][kt], bh.x, bh.y);
            }
        }

        // epilogue2 (x re-read: L1-hot with 27KB smem carveout)
        #pragma unroll
        for (int s2 = 0; s2 < 2; s2++) {
            int rA = ra + s2 * 16, rB = rA + 8;
            float ga = 1.0f / (1.0f + __expf(-(gd[2 * s2 + 0] + cgv)));
            float gb = 1.0f / (1.0f + __expf(-(gd[2 * s2 + 1] + cgv)));
            #pragma unroll
            for (int nt = 0; nt < 8; nt++) {
                int col = nt * 8 + 2 * tig;
                float2 b2v = *(const float2*)(B2S + col);
                float2 xa = *(const float2*)(xb + rA * Hn + col);
                float2 xv = *(const float2*)(xb + rB * Hn + col);
                float f0 = acc[s2][nt][0] + b2v.x;
                float f1 = acc[s2][nt][1] + b2v.y;
                float f2 = acc[s2][nt][2] + b2v.x;
                float f3 = acc[s2][nt][3] + b2v.y;
                float2 oa, ob;
                oa.x = xa.x + ga * (f0 - xa.x);
                oa.y = xa.y + ga * (f1 - xa.y);
                ob.x = xv.x + gb * (f2 - xv.x);
                ob.y = xv.y + gb * (f3 - xv.y);
                *(float2*)(op + rA * Hn + col) = oa;
                *(float2*)(op + rB * Hn + col) = ob;
            }
        }
    }

    // ================= epoch drain barrier + special-row fixup =================
    int myv;
    if (tid == 0) {
        __threadfence();
        myv = atomicAdd(&g_done, 1);
    }
    if (blockIdx.x >= NFIXB) return;

    if (tid == 0) {
        int target = (myv / NWORK + 1) * NWORK;
        while (*(volatile int*)&g_done < target) {}
    }
    __syncthreads();
    __threadfence();

    {
        const int slab = blockIdx.x * 4 + w;    // 0..319, 16 flat edges each
        const int f0 = slab * 16 + g;
        const int f1 = f0 + 8;
        const int b0 = f0 / En, b1 = f1 / En;
        const int r0r = etype[f0], r1r = etype[f1];
        const float* x0 = base + ((size_t)(b0 * Rn + r0r)) * Hn;
        const float* x1 = base + ((size_t)(b1 * Rn + r1r)) * Hn;
        float* o0 = out + ((size_t)(b0 * Rn + r0r)) * Hn;
        float* o1 = out + ((size_t)(b1 * Rn + r1r)) * Hn;
        const float* q10 = g_q1 + (size_t)f0 * Hn;
        const float* q11 = g_q1 + (size_t)f1 * Hn;

        uint32_t ahi[4][4];
        float gd0 = 0.0f, gd1 = 0.0f;
        #pragma unroll
        for (int kt = 0; kt < 4; kt++) {
            int c0 = kt * 16 + 2 * tig;
            float2 p00 = *(const float2*)(x0 + c0);
            float2 p10 = *(const float2*)(x1 + c0);
            float2 p01 = *(const float2*)(x0 + c0 + 8);
            float2 p11 = *(const float2*)(x1 + c0 + 8);
            float2 gw0 = *(const float2*)(GWA + c0);
            float2 gw8 = *(const float2*)(GWA + c0 + 8);
            gd0 += p00.x * gw0.x + p00.y * gw0.y + p01.x * gw8.x + p01.y * gw8.y;
            gd1 += p10.x * gw0.x + p10.y * gw0.y + p11.x * gw8.x + p11.y * gw8.y;
            ahi[kt][0] = cvt_bf16x2(p00.y, p00.x);
            ahi[kt][1] = cvt_bf16x2(p10.y, p10.x);
            ahi[kt][2] = cvt_bf16x2(p01.y, p01.x);
            ahi[kt][3] = cvt_bf16x2(p11.y, p11.x);
        }
        gd0 += __shfl_xor_sync(~0u, gd0, 1);
        gd0 += __shfl_xor_sync(~0u, gd0, 2);
        gd1 += __shfl_xor_sync(~0u, gd1, 1);
        gd1 += __shfl_xor_sync(~0u, gd1, 2);

        float acc[8][4];
        #pragma unroll
        for (int nt = 0; nt < 8; nt++)
            acc[nt][0] = acc[nt][1] = acc[nt][2] = acc[nt][3] = 0.0f;
        #pragma unroll
        for (int kt = 0; kt < 4; kt++) {
            #pragma unroll
            for (int nt = 0; nt < 8; nt++) {
                uint2 bh = W1F[(kt * 8 + nt) * 32 + lane];
                mma_bf16(acc[nt], ahi[kt], bh.x, bh.y);
            }
        }

        uint32_t yhi[4][4];
        #pragma unroll
        for (int kt2 = 0; kt2 < 4; kt2++) {
            #pragma unroll
            for (int half = 0; half < 2; half++) {
                int nt = kt2 * 2 + half;
                int col = nt * 8 + 2 * tig;
                float2 ba = *(const float2*)(q10 + col);
                float2 bb = *(const float2*)(q11 + col);
                float y0 = fmaxf(acc[nt][0] + ba.x, 0.0f);
                float y1 = fmaxf(acc[nt][1] + ba.y, 0.0f);
                float y2 = fmaxf(acc[nt][2] + bb.x, 0.0f);
                float y3 = fmaxf(acc[nt][3] + bb.y, 0.0f);
                yhi[kt2][half * 2 + 0] = cvt_bf16x2(y1, y0);
                yhi[kt2][half * 2 + 1] = cvt_bf16x2(y3, y2);
            }
        }

        #pragma unroll
        for (int nt = 0; nt < 8; nt++)
            acc[nt][0] = acc[nt][1] = acc[nt][2] = acc[nt][3] = 0.0f;
        #pragma unroll
        for (int kt = 0; kt < 4; kt++) {
            #pragma unroll
            for (int nt = 0; nt < 8; nt++) {
                uint2 bh = W2F[(kt * 8 + nt) * 32 + lane];
                mma_bf16(acc[nt], yhi[kt], bh.x, bh.y);
            }
        }

        float ga = 1.0f / (1.0f + __expf(-(gd0 + g_qg[f0])));
        float gb = 1.0f / (1.0f + __expf(-(gd1 + g_qg[f1])));
        #pragma unroll
        for (int nt = 0; nt < 8; nt++) {
            int col = nt * 8 + 2 * tig;
            float2 b2v = *(const float2*)(B2S + col);
            float2 xa = *(const float2*)(x0 + col);
            float2 xv = *(const float2*)(x1 + col);
            float f0v = acc[nt][0] + b2v.x;
            float f1v = acc[nt][1] + b2v.y;
            float f2v = acc[nt][2] + b2v.x;
            float f3v = acc[nt][3] + b2v.y;
            float2 oa, ob;
            oa.x = xa.x + ga * (f0v - xa.x);
            oa.y = xa.y + ga * (f1v - xa.y);
            ob.x = xv.x + gb * (f2v - xv.x);
            ob.y = xv.y + gb * (f3v - xv.y);
            *(float2*)(o0 + col) = oa;
            *(float2*)(o1 + col) = ob;
        }
    }
}

// ---------------------------------------------------------------------------
extern "C" void kernel_launch(void* const* d_in, const int* in_sizes, int n_in,
                              void* d_out, int out_size) {
    const int*   qrel   = (const int*)  d_in[0];
    const int*   etype  = (const int*)  d_in[1];
    const float* base   = (const float*)d_in[2];
    const float* noise  = (const float*)d_in[3];
    const float* msg_W  = (const float*)d_in[4];
    const float* msg_b  = (const float*)d_in[5];
    const float* upd_W  = (const float*)d_in[6];
    const float* upd_b  = (const float*)d_in[7];
    const float* ln_g   = (const float*)d_in[8];
    const float* ln_b   = (const float*)d_in[9];
    const float* fus_W1 = (const float*)d_in[10];
    const float* fus_b1 = (const float*)d_in[11];
    const float* fus_W2 = (const float*)d_in[12];
    const float* fus_b2 = (const float*)d_in[13];
    const float* gate_W = (const float*)d_in[14];
    const float* gate_b = (const float*)d_in[15];
    float* out = (float*)d_out;

    cudaFuncSetAttribute(k2_fused, cudaFuncAttributeMaxDynamicSharedMemorySize,
                         SMEM_K2);
    k2_fused<<<NWORK, NTHR, SMEM_K2>>>(
        qrel, etype, noise, msg_W, msg_b, upd_W, upd_b, ln_g, ln_b,
        fus_W1, fus_b1, gate_W, gate_b, base, fus_W2, fus_b2, out);
}

// round 14
// speedup vs baseline: 3.4558x; 1.0198x over previous
#include <cuda_runtime.h>
#include <cuda_bf16.h>
#include <math.h>
#include <stdint.h>

#define Bn 256
#define Rn 2048
#define Hn 64
#define En 20
#define LN_EPSF 1e-5f
#define NMICRO (Bn * (Rn / 32))      // 16384 32-row microtiles
#define NWORK  592                   // 4 CTAs/SM x 148 SMs
#define NWARPS (NWORK * 4)           // 2368 worker warps
#define NFIXB  80                    // fixup blocks (80*4 warps = 320 slabs)
#define CLAIMS_PER_EPOCH (NMICRO + NWARPS)

// device scratch (no allocs allowed); counters monotonic (epoch arithmetic)
__device__ __align__(16) float g_q1[Bn * En * Hn];
__device__ float g_qg[Bn * En];
__device__ int g_tile_ctr;
__device__ int g_done;

static __device__ __forceinline__ uint32_t cvt_bf16x2(float e1, float e0) {
    uint32_t r;
    asm("cvt.rn.bf16x2.f32 %0, %1, %2;" : "=r"(r) : "f"(e1), "f"(e0));
    return r;
}
static __device__ __forceinline__ void mma_bf16(float* c, const uint32_t* a,
                                                uint32_t b0, uint32_t b1) {
    asm volatile(
        "mma.sync.aligned.m16n8k16.row.col.f32.bf16.bf16.f32 "
        "{%0,%1,%2,%3}, {%4,%5,%6,%7}, {%8,%9}, {%0,%1,%2,%3};"
        : "+f"(c[0]), "+f"(c[1]), "+f"(c[2]), "+f"(c[3])
        : "r"(a[0]), "r"(a[1]), "r"(a[2]), "r"(a[3]), "r"(b0), "r"(b1));
}

// ---------------------------------------------------------------------------
// K2: single persistent kernel. Warps claim 32-row microtiles independently
// (no __syncthreads in the hot loop). blocks [0,256) run the prompt pipeline
// first; after a per-warp drain barrier, blocks [0,80) fix special rows.
// ---------------------------------------------------------------------------
#define NTHR 128
// fusion smem
#define OW1F 0
#define OW2F 8192
#define OGWA 16384
#define OC1  16640
#define OB2  16896
#define OP0  17152
#define OCG  17408
// prompt smem (aliases same buffer; used before fusion staging)
#define P_WSUM 0
#define P_HS   16384
#define P_MS   21504
#define P_ER   26624
#define SMEM_K2 26752

__global__ __launch_bounds__(NTHR, 4)
void k2_fused(const int* __restrict__ qrel,
              const int* __restrict__ etype,
              const float* __restrict__ noise,
              const float* __restrict__ msg_W,
              const float* __restrict__ msg_b,
              const float* __restrict__ upd_W,
              const float* __restrict__ upd_b,
              const float* __restrict__ ln_g,
              const float* __restrict__ ln_b,
              const float* __restrict__ fus_W1,
              const float* __restrict__ fus_b1,
              const float* __restrict__ gate_W,
              const float* __restrict__ gate_b,
              const float* __restrict__ base,
              const float* __restrict__ fus_W2,
              const float* __restrict__ fus_b2,
              float* __restrict__ out) {
    extern __shared__ __align__(16) char sm[];
    const int tid = threadIdx.x;
    const int w = tid >> 5, lane = tid & 31;

    if (blockIdx.x < Bn) {
        // ================= prompt pipeline =================
        const int b  = blockIdx.x;
        const int j  = tid & 63;
        const int eg = tid >> 6;
        float* Wsum = (float*)(sm + P_WSUM);
        float (*hs)[Hn] = (float(*)[Hn])(sm + P_HS);
        float (*ms)[Hn] = (float(*)[Hn])(sm + P_MS);
        int* er = (int*)(sm + P_ER);

        for (int idx = tid; idx < Hn * Hn; idx += NTHR)
            Wsum[idx] = msg_W[idx] + msg_W[Hn * Hn + idx];
        if (tid < En) er[tid] = etype[b * En + tid];
        __syncthreads();

        int qr = qrel[b];
        for (int e = eg; e < En; e += 2) {
            int r = er[e];
            hs[e][j] = (r == qr) ? 1.0f
                                 : noise[((size_t)b * Rn + r) * Hn + j] * 0.1f;
        }
        __syncthreads();

        for (int e = eg; e < En; e += 2) {
            float m = msg_b[j];
            #pragma unroll 8
            for (int k = 0; k < Hn; k++) m = fmaf(hs[e][k], Wsum[k * Hn + j], m);
            ms[e][j] = fmaxf(m, 0.0f);
        }
        __syncthreads();

        for (int e = eg; e < En; e += 2) {
            float a = 0.0f;
            int re = er[e];
            #pragma unroll
            for (int e2 = 0; e2 < En; e2++)
                if (er[e2] == re) a += ms[e2][j];
            hs[e][j] = a;
        }
        __syncthreads();

        for (int e = eg; e < En; e += 2) {
            float u = upd_b[j];
            #pragma unroll 8
            for (int k = 0; k < Hn; k++)
                u = fmaf(hs[e][k], upd_W[k * Hn + j], u);
            ms[e][j] = u;
        }
        __syncthreads();
        for (int idx = tid; idx < Hn * Hn; idx += NTHR)
            Wsum[idx] = fus_W1[Hn * Hn + idx];    // W1b for q1
        __syncthreads();

        for (int e = w; e < En; e += 4) {
            float v0 = ms[e][lane], v1 = ms[e][lane + 32];
            float s = v0 + v1;
            #pragma unroll
            for (int o = 16; o > 0; o >>= 1) s += __shfl_xor_sync(~0u, s, o);
            float mu = s * (1.0f / Hn);
            float d0 = v0 - mu, d1 = v1 - mu;
            s = d0 * d0 + d1 * d1;
            #pragma unroll
            for (int o = 16; o > 0; o >>= 1) s += __shfl_xor_sync(~0u, s, o);
            float inv = rsqrtf(s * (1.0f / Hn) + LN_EPSF);
            ms[e][lane]      = d0 * inv * ln_g[lane] + ln_b[lane];
            ms[e][lane + 32] = d1 * inv * ln_g[lane + 32] + ln_b[lane + 32];
        }
        __syncthreads();

        for (int e = eg; e < En; e += 2) {
            float q = fus_b1[j];
            #pragma unroll 8
            for (int k = 0; k < Hn; k++) q = fmaf(ms[e][k], Wsum[k * Hn + j], q);
            g_q1[((size_t)b * En + e) * Hn + j] = q;
        }
        for (int e = w; e < En; e += 4) {
            float s = ms[e][lane] * gate_W[Hn + lane]
                    + ms[e][lane + 32] * gate_W[Hn + lane + 32];
            #pragma unroll
            for (int o = 16; o > 0; o >>= 1) s += __shfl_xor_sync(~0u, s, o);
            if (lane == 0) g_qg[b * En + e] = s + gate_b[0];
        }
        __syncthreads();   // prompt done; smem reused for fusion
    }

    // ================= fusion worker setup =================
    uint2* W1F = (uint2*)(sm + OW1F);
    uint2* W2F = (uint2*)(sm + OW2F);
    float* GWA = (float*)(sm + OGWA);
    float* C1S = (float*)(sm + OC1);
    float* B2S = (float*)(sm + OB2);
    float* P0S = (float*)(sm + OP0);
    float* CGS = (float*)(sm + OCG);

    #pragma unroll
    for (int s = 0; s < 8; s++) {
        int idx = tid + s * NTHR;
        int l = idx & 31;
        int t2 = idx >> 5;
        int nt = t2 & 7, kt = t2 >> 3;
        int n  = nt * 8 + (l >> 2);
        int k0 = kt * 16 + (l & 3) * 2;
        W1F[idx] = make_uint2(
            cvt_bf16x2(fus_W1[(k0 + 1) * Hn + n], fus_W1[k0 * Hn + n]),
            cvt_bf16x2(fus_W1[(k0 + 9) * Hn + n], fus_W1[(k0 + 8) * Hn + n]));
        W2F[idx] = make_uint2(
            cvt_bf16x2(fus_W2[(k0 + 1) * Hn + n], fus_W2[k0 * Hn + n]),
            cvt_bf16x2(fus_W2[(k0 + 9) * Hn + n], fus_W2[(k0 + 8) * Hn + n]));
    }
    if (w == 0) {
        float v0 = upd_b[lane], v1 = upd_b[lane + 32];
        float s = v0 + v1;
        #pragma unroll
        for (int o = 16; o > 0; o >>= 1) s += __shfl_xor_sync(~0u, s, o);
        float mu = s * (1.0f / Hn);
        float d0 = v0 - mu, d1 = v1 - mu;
        s = d0 * d0 + d1 * d1;
        #pragma unroll
        for (int o = 16; o > 0; o >>= 1) s += __shfl_xor_sync(~0u, s, o);
        float inv = rsqrtf(s * (1.0f / Hn) + LN_EPSF);
        P0S[lane]      = d0 * inv * ln_g[lane] + ln_b[lane];
        P0S[lane + 32] = d1 * inv * ln_g[lane + 32] + ln_b[lane + 32];
    }
    __syncthreads();

    if (tid < Hn) {
        float c = fus_b1[tid];
        #pragma unroll 8
        for (int k = 0; k < Hn; k++)
            c = fmaf(P0S[k], fus_W1[(Hn + k) * Hn + tid], c);
        C1S[tid] = c;
    }
    if (w == 2) {
        float s = P0S[lane] * gate_W[Hn + lane]
                + P0S[lane + 32] * gate_W[Hn + lane + 32];
        #pragma unroll
        for (int o = 16; o > 0; o >>= 1) s += __shfl_xor_sync(~0u, s, o);
        if (lane == 0) CGS[0] = s + gate_b[0];
    }
    if (w == 3) {
        if (lane < 16) ((float4*)GWA)[lane] = ((const float4*)gate_W)[lane];
        else ((float4*)B2S)[lane - 16] = ((const float4*)fus_b2)[lane - 16];
    }
    __syncthreads();   // last block-wide sync; warps free-run from here

    const float cgv = CGS[0];
    const int g = lane >> 2, tig = lane & 3;

    // ================= per-warp microtile loop (no block syncs) ============
    for (;;) {
        int t;
        if (lane == 0) t = atomicAdd(&g_tile_ctr, 1) % CLAIMS_PER_EPOCH;
        t = __shfl_sync(~0u, t, 0);
        if (t >= NMICRO) break;

        const int b  = t >> 6;              // 64 microtiles per sample
        const int r0 = (t & 63) << 5;       // 32 rows each
        const float* xb = base + ((size_t)(b * Rn + r0)) * Hn;
        float* op = out + ((size_t)(b * Rn + r0)) * Hn;

        uint32_t ahi[2][4][4];
        float gd[4] = {0.0f, 0.0f, 0.0f, 0.0f};
        #pragma unroll
        for (int s2 = 0; s2 < 2; s2++) {
            int rA = g + s2 * 16, rB = rA + 8;
            #pragma unroll
            for (int kt = 0; kt < 4; kt++) {
                int c0 = kt * 16 + 2 * tig;
                float2 p00 = *(const float2*)(xb + rA * Hn + c0);
                float2 p10 = *(const float2*)(xb + rB * Hn + c0);
                float2 p01 = *(const float2*)(xb + rA * Hn + c0 + 8);
                float2 p11 = *(const float2*)(xb + rB * Hn + c0 + 8);
                float2 gw0 = *(const float2*)(GWA + c0);
                float2 gw8 = *(const float2*)(GWA + c0 + 8);
                gd[s2 * 2 + 0] += p00.x * gw0.x + p00.y * gw0.y
                                + p01.x * gw8.x + p01.y * gw8.y;
                gd[s2 * 2 + 1] += p10.x * gw0.x + p10.y * gw0.y
                                + p11.x * gw8.x + p11.y * gw8.y;
                ahi[s2][kt][0] = cvt_bf16x2(p00.y, p00.x);
                ahi[s2][kt][1] = cvt_bf16x2(p10.y, p10.x);
                ahi[s2][kt][2] = cvt_bf16x2(p01.y, p01.x);
                ahi[s2][kt][3] = cvt_bf16x2(p11.y, p11.x);
            }
        }
        #pragma unroll
        for (int i = 0; i < 4; i++) {
            gd[i] += __shfl_xor_sync(~0u, gd[i], 1);
            gd[i] += __shfl_xor_sync(~0u, gd[i], 2);
        }

        // GEMM1 (kt outer, nt inner)
        float acc[2][8][4];
        #pragma unroll
        for (int s2 = 0; s2 < 2; s2++)
            #pragma unroll
            for (int nt = 0; nt < 8; nt++)
                acc[s2][nt][0] = acc[s2][nt][1] = acc[s2][nt][2] = acc[s2][nt][3] = 0.0f;
        #pragma unroll
        for (int kt = 0; kt < 4; kt++) {
            #pragma unroll
            for (int nt = 0; nt < 8; nt++) {
                uint2 bh = W1F[(kt * 8 + nt) * 32 + lane];
                #pragma unroll
                for (int s2 = 0; s2 < 2; s2++)
                    mma_bf16(acc[s2][nt], ahi[s2][kt], bh.x, bh.y);
            }
        }

        // epilogue1: bias c1, relu, repack as A2
        uint32_t yhi[2][4][4];
        #pragma unroll
        for (int kt2 = 0; kt2 < 4; kt2++) {
            #pragma unroll
            for (int half = 0; half < 2; half++) {
                int nt = kt2 * 2 + half;
                int col = nt * 8 + 2 * tig;
                float2 cb = *(const float2*)(C1S + col);
                #pragma unroll
                for (int s2 = 0; s2 < 2; s2++) {
                    float y0 = fmaxf(acc[s2][nt][0] + cb.x, 0.0f);
                    float y1 = fmaxf(acc[s2][nt][1] + cb.y, 0.0f);
                    float y2 = fmaxf(acc[s2][nt][2] + cb.x, 0.0f);
                    float y3 = fmaxf(acc[s2][nt][3] + cb.y, 0.0f);
                    yhi[s2][kt2][half * 2 + 0] = cvt_bf16x2(y1, y0);
                    yhi[s2][kt2][half * 2 + 1] = cvt_bf16x2(y3, y2);
                }
            }
        }

        // GEMM2
        #pragma unroll
        for (int s2 = 0; s2 < 2; s2++)
            #pragma unroll
            for (int nt = 0; nt < 8; nt++)
                acc[s2][nt][0] = acc[s2][nt][1] = acc[s2][nt][2] = acc[s2][nt][3] = 0.0f;
        #pragma unroll
        for (int kt = 0; kt < 4; kt++) {
            #pragma unroll
            for (int nt = 0; nt < 8; nt++) {
                uint2 bh = W2F[(kt * 8 + nt) * 32 + lane];
                #pragma unroll
                for (int s2 = 0; s2 < 2; s2++)
                    mma_bf16(acc[s2][nt], yhi[s2][kt], bh.x, bh.y);
            }
        }

        // epilogue2 (x re-read: L1-hot, same warp loaded it)
        #pragma unroll
        for (int s2 = 0; s2 < 2; s2++) {
            int rA = g + s2 * 16, rB = rA + 8;
            float ga = 1.0f / (1.0f + __expf(-(gd[2 * s2 + 0] + cgv)));
            float gb = 1.0f / (1.0f + __expf(-(gd[2 * s2 + 1] + cgv)));
            #pragma unroll
            for (int nt = 0; nt < 8; nt++) {
                int col = nt * 8 + 2 * tig;
                float2 b2v = *(const float2*)(B2S + col);
                float2 xa = *(const float2*)(xb + rA * Hn + col);
                float2 xv = *(const float2*)(xb + rB * Hn + col);
                float f0 = acc[s2][nt][0] + b2v.x;
                float f1 = acc[s2][nt][1] + b2v.y;
                float f2 = acc[s2][nt][2] + b2v.x;
                float f3 = acc[s2][nt][3] + b2v.y;
                float2 oa, ob;
                oa.x = xa.x + ga * (f0 - xa.x);
                oa.y = xa.y + ga * (f1 - xa.y);
                ob.x = xv.x + gb * (f2 - xv.x);
                ob.y = xv.y + gb * (f3 - xv.y);
                *(float2*)(op + rA * Hn + col) = oa;
                *(float2*)(op + rB * Hn + col) = ob;
            }
        }
    }

    // ============== per-warp epoch drain barrier + special fixup ============
    int myv;
    if (lane == 0) {
        __threadfence();
        myv = atomicAdd(&g_done, 1);
    }
    if (blockIdx.x >= NFIXB) return;

    if (lane == 0) {
        int target = (myv / NWARPS + 1) * NWARPS;
        while (*(volatile int*)&g_done < target) {}
    }
    __syncwarp();
    __threadfence();

    {
        const int slab = blockIdx.x * 4 + w;    // 0..319, 16 flat edges each
        const int f0 = slab * 16 + g;
        const int f1 = f0 + 8;
        const int b0 = f0 / En, b1 = f1 / En;
        const int r0r = etype[f0], r1r = etype[f1];
        const float* x0 = base + ((size_t)(b0 * Rn + r0r)) * Hn;
        const float* x1 = base + ((size_t)(b1 * Rn + r1r)) * Hn;
        float* o0 = out + ((size_t)(b0 * Rn + r0r)) * Hn;
        float* o1 = out + ((size_t)(b1 * Rn + r1r)) * Hn;
        const float* q10 = g_q1 + (size_t)f0 * Hn;
        const float* q11 = g_q1 + (size_t)f1 * Hn;

        uint32_t ahi[4][4];
        float gd0 = 0.0f, gd1 = 0.0f;
        #pragma unroll
        for (int kt = 0; kt < 4; kt++) {
            int c0 = kt * 16 + 2 * tig;
            float2 p00 = *(const float2*)(x0 + c0);
            float2 p10 = *(const float2*)(x1 + c0);
            float2 p01 = *(const float2*)(x0 + c0 + 8);
            float2 p11 = *(const float2*)(x1 + c0 + 8);
            float2 gw0 = *(const float2*)(GWA + c0);
            float2 gw8 = *(const float2*)(GWA + c0 + 8);
            gd0 += p00.x * gw0.x + p00.y * gw0.y + p01.x * gw8.x + p01.y * gw8.y;
            gd1 += p10.x * gw0.x + p10.y * gw0.y + p11.x * gw8.x + p11.y * gw8.y;
            ahi[kt][0] = cvt_bf16x2(p00.y, p00.x);
            ahi[kt][1] = cvt_bf16x2(p10.y, p10.x);
            ahi[kt][2] = cvt_bf16x2(p01.y, p01.x);
            ahi[kt][3] = cvt_bf16x2(p11.y, p11.x);
        }
        gd0 += __shfl_xor_sync(~0u, gd0, 1);
        gd0 += __shfl_xor_sync(~0u, gd0, 2);
        gd1 += __shfl_xor_sync(~0u, gd1, 1);
        gd1 += __shfl_xor_sync(~0u, gd1, 2);

        float acc[8][4];
        #pragma unroll
        for (int nt = 0; nt < 8; nt++)
            acc[nt][0] = acc[nt][1] = acc[nt][2] = acc[nt][3] = 0.0f;
        #pragma unroll
        for (int kt = 0; kt < 4; kt++) {
            #pragma unroll
            for (int nt = 0; nt < 8; nt++) {
                uint2 bh = W1F[(kt * 8 + nt) * 32 + lane];
                mma_bf16(acc[nt], ahi[kt], bh.x, bh.y);
            }
        }

        uint32_t yhi[4][4];
        #pragma unroll
        for (int kt2 = 0; kt2 < 4; kt2++) {
            #pragma unroll
            for (int half = 0; half < 2; half++) {
                int nt = kt2 * 2 + half;
                int col = nt * 8 + 2 * tig;
                float2 ba = *(const float2*)(q10 + col);
                float2 bb = *(const float2*)(q11 + col);
                float y0 = fmaxf(acc[nt][0] + ba.x, 0.0f);
                float y1 = fmaxf(acc[nt][1] + ba.y, 0.0f);
                float y2 = fmaxf(acc[nt][2] + bb.x, 0.0f);
                float y3 = fmaxf(acc[nt][3] + bb.y, 0.0f);
                yhi[kt2][half * 2 + 0] = cvt_bf16x2(y1, y0);
                yhi[kt2][half * 2 + 1] = cvt_bf16x2(y3, y2);
            }
        }

        #pragma unroll
        for (int nt = 0; nt < 8; nt++)
            acc[nt][0] = acc[nt][1] = acc[nt][2] = acc[nt][3] = 0.0f;
        #pragma unroll
        for (int kt = 0; kt < 4; kt++) {
            #pragma unroll
            for (int nt = 0; nt < 8; nt++) {
                uint2 bh = W2F[(kt * 8 + nt) * 32 + lane];
                mma_bf16(acc[nt], yhi[kt], bh.x, bh.y);
            }
        }

        float ga = 1.0f / (1.0f + __expf(-(gd0 + g_qg[f0])));
        float gb = 1.0f / (1.0f + __expf(-(gd1 + g_qg[f1])));
        #pragma unroll
        for (int nt = 0; nt < 8; nt++) {
            int col = nt * 8 + 2 * tig;
            float2 b2v = *(const float2*)(B2S + col);
            float2 xa = *(const float2*)(x0 + col);
            float2 xv = *(const float2*)(x1 + col);
            float f0v = acc[nt][0] + b2v.x;
            float f1v = acc[nt][1] + b2v.y;
            float f2v = acc[nt][2] + b2v.x;
            float f3v = acc[nt][3] + b2v.y;
            float2 oa, ob;
            oa.x = xa.x + ga * (f0v - xa.x);
            oa.y = xa.y + ga * (f1v - xa.y);
            ob.x = xv.x + gb * (f2v - xv.x);
            ob.y = xv.y + gb * (f3v - xv.y);
            *(float2*)(o0 + col) = oa;
            *(float2*)(o1 + col) = ob;
        }
    }
}

// ---------------------------------------------------------------------------
extern "C" void kernel_launch(void* const* d_in, const int* in_sizes, int n_in,
                              void* d_out, int out_size) {
    const int*   qrel   = (const int*)  d_in[0];
    const int*   etype  = (const int*)  d_in[1];
    const float* base   = (const float*)d_in[2];
    const float* noise  = (const float*)d_in[3];
    const float* msg_W  = (const float*)d_in[4];
    const float* msg_b  = (const float*)d_in[5];
    const float* upd_W  = (const float*)d_in[6];
    const float* upd_b  = (const float*)d_in[7];
    const float* ln_g   = (const float*)d_in[8];
    const float* ln_b   = (const float*)d_in[9];
    const float* fus_W1 = (const float*)d_in[10];
    const float* fus_b1 = (const float*)d_in[11];
    const float* fus_W2 = (const float*)d_in[12];
    const float* fus_b2 = (const float*)d_in[13];
    const float* gate_W = (const float*)d_in[14];
    const float* gate_b = (const float*)d_in[15];
    float* out = (float*)d_out;

    cudaFuncSetAttribute(k2_fused, cudaFuncAttributeMaxDynamicSharedMemorySize,
                         SMEM_K2);
    k2_fused<<<NWORK, NTHR, SMEM_K2>>>(
        qrel, etype, noise, msg_W, msg_b, upd_W, upd_b, ln_g, ln_b,
        fus_W1, fus_b1, gate_W, gate_b, base, fus_W2, fus_b2, out);
}

// round 15
// speedup vs baseline: 4.0000x; 1.1575x over previous
#include <cuda_runtime.h>
#include <cuda_bf16.h>
#include <math.h>
#include <stdint.h>

#define Bn 256
#define Rn 2048
#define Hn 64
#define En 20
#define LN_EPSF 1e-5f
#define NMICRO (Bn * (Rn / 32))      // 16384 32-row microtiles
#define NWORK  296                   // 2 CTAs/SM x 148 SMs
#define NWARPS (NWORK * 4)           // 1184 worker warps
#define NFIXB  80                    // fixup blocks (80*4 warps = 320 slabs)
#define CLAIMS_PER_EPOCH (NMICRO + NWARPS)

// device scratch (no allocs allowed); counters monotonic (epoch arithmetic)
__device__ __align__(16) float g_q1[Bn * En * Hn];
__device__ float g_qg[Bn * En];
__device__ int g_tile_ctr;
__device__ int g_done;

static __device__ __forceinline__ uint32_t cvt_bf16x2(float e1, float e0) {
    uint32_t r;
    asm("cvt.rn.bf16x2.f32 %0, %1, %2;" : "=r"(r) : "f"(e1), "f"(e0));
    return r;
}
static __device__ __forceinline__ void mma_bf16(float* c, const uint32_t* a,
                                                uint32_t b0, uint32_t b1) {
    asm volatile(
        "mma.sync.aligned.m16n8k16.row.col.f32.bf16.bf16.f32 "
        "{%0,%1,%2,%3}, {%4,%5,%6,%7}, {%8,%9}, {%0,%1,%2,%3};"
        : "+f"(c[0]), "+f"(c[1]), "+f"(c[2]), "+f"(c[3])
        : "r"(a[0]), "r"(a[1]), "r"(a[2]), "r"(a[3]), "r"(b0), "r"(b1));
}

// ---------------------------------------------------------------------------
// K2: single persistent kernel, 296 CTAs, 2/SM, generous register budget.
// Warps claim 32-row microtiles independently; x stays in registers for the
// whole tile (no epilogue re-read). blocks [0,256) run prompts first; after
// a per-warp drain barrier, blocks [0,80) fix the special rows.
// ---------------------------------------------------------------------------
#define NTHR 128
// fusion smem
#define OW1F 0
#define OW2F 8192
#define OGWA 16384
#define OC1  16640
#define OB2  16896
#define OP0  17152
#define OCG  17408
// prompt smem (aliases same buffer; used before fusion staging)
#define P_WSUM 0
#define P_HS   16384
#define P_MS   21504
#define P_ER   26624
#define SMEM_K2 26752

__global__ __launch_bounds__(NTHR, 2)
void k2_fused(const int* __restrict__ qrel,
              const int* __restrict__ etype,
              const float* __restrict__ noise,
              const float* __restrict__ msg_W,
              const float* __restrict__ msg_b,
              const float* __restrict__ upd_W,
              const float* __restrict__ upd_b,
              const float* __restrict__ ln_g,
              const float* __restrict__ ln_b,
              const float* __restrict__ fus_W1,
              const float* __restrict__ fus_b1,
              const float* __restrict__ gate_W,
              const float* __restrict__ gate_b,
              const float* __restrict__ base,
              const float* __restrict__ fus_W2,
              const float* __restrict__ fus_b2,
              float* __restrict__ out) {
    extern __shared__ __align__(16) char sm[];
    const int tid = threadIdx.x;
    const int w = tid >> 5, lane = tid & 31;

    if (blockIdx.x < Bn) {
        // ================= prompt pipeline =================
        const int b  = blockIdx.x;
        const int j  = tid & 63;
        const int eg = tid >> 6;
        float* Wsum = (float*)(sm + P_WSUM);
        float (*hs)[Hn] = (float(*)[Hn])(sm + P_HS);
        float (*ms)[Hn] = (float(*)[Hn])(sm + P_MS);
        int* er = (int*)(sm + P_ER);

        for (int idx = tid; idx < Hn * Hn; idx += NTHR)
            Wsum[idx] = msg_W[idx] + msg_W[Hn * Hn + idx];
        if (tid < En) er[tid] = etype[b * En + tid];
        __syncthreads();

        int qr = qrel[b];
        for (int e = eg; e < En; e += 2) {
            int r = er[e];
            hs[e][j] = (r == qr) ? 1.0f
                                 : noise[((size_t)b * Rn + r) * Hn + j] * 0.1f;
        }
        __syncthreads();

        for (int e = eg; e < En; e += 2) {
            float m = msg_b[j];
            #pragma unroll 8
            for (int k = 0; k < Hn; k++) m = fmaf(hs[e][k], Wsum[k * Hn + j], m);
            ms[e][j] = fmaxf(m, 0.0f);
        }
        __syncthreads();

        for (int e = eg; e < En; e += 2) {
            float a = 0.0f;
            int re = er[e];
            #pragma unroll
            for (int e2 = 0; e2 < En; e2++)
                if (er[e2] == re) a += ms[e2][j];
            hs[e][j] = a;
        }
        __syncthreads();

        for (int e = eg; e < En; e += 2) {
            float u = upd_b[j];
            #pragma unroll 8
            for (int k = 0; k < Hn; k++)
                u = fmaf(hs[e][k], upd_W[k * Hn + j], u);
            ms[e][j] = u;
        }
        __syncthreads();
        for (int idx = tid; idx < Hn * Hn; idx += NTHR)
            Wsum[idx] = fus_W1[Hn * Hn + idx];    // W1b for q1
        __syncthreads();

        for (int e = w; e < En; e += 4) {
            float v0 = ms[e][lane], v1 = ms[e][lane + 32];
            float s = v0 + v1;
            #pragma unroll
            for (int o = 16; o > 0; o >>= 1) s += __shfl_xor_sync(~0u, s, o);
            float mu = s * (1.0f / Hn);
            float d0 = v0 - mu, d1 = v1 - mu;
            s = d0 * d0 + d1 * d1;
            #pragma unroll
            for (int o = 16; o > 0; o >>= 1) s += __shfl_xor_sync(~0u, s, o);
            float inv = rsqrtf(s * (1.0f / Hn) + LN_EPSF);
            ms[e][lane]      = d0 * inv * ln_g[lane] + ln_b[lane];
            ms[e][lane + 32] = d1 * inv * ln_g[lane + 32] + ln_b[lane + 32];
        }
        __syncthreads();

        for (int e = eg; e < En; e += 2) {
            float q = fus_b1[j];
            #pragma unroll 8
            for (int k = 0; k < Hn; k++) q = fmaf(ms[e][k], Wsum[k * Hn + j], q);
            g_q1[((size_t)b * En + e) * Hn + j] = q;
        }
        for (int e = w; e < En; e += 4) {
            float s = ms[e][lane] * gate_W[Hn + lane]
                    + ms[e][lane + 32] * gate_W[Hn + lane + 32];
            #pragma unroll
            for (int o = 16; o > 0; o >>= 1) s += __shfl_xor_sync(~0u, s, o);
            if (lane == 0) g_qg[b * En + e] = s + gate_b[0];
        }
        __syncthreads();   // prompt done; smem reused for fusion
    }

    // ================= fusion worker setup =================
    uint2* W1F = (uint2*)(sm + OW1F);
    uint2* W2F = (uint2*)(sm + OW2F);
    float* GWA = (float*)(sm + OGWA);
    float* C1S = (float*)(sm + OC1);
    float* B2S = (float*)(sm + OB2);
    float* P0S = (float*)(sm + OP0);
    float* CGS = (float*)(sm + OCG);

    #pragma unroll
    for (int s = 0; s < 8; s++) {
        int idx = tid + s * NTHR;
        int l = idx & 31;
        int t2 = idx >> 5;
        int nt = t2 & 7, kt = t2 >> 3;
        int n  = nt * 8 + (l >> 2);
        int k0 = kt * 16 + (l & 3) * 2;
        W1F[idx] = make_uint2(
            cvt_bf16x2(fus_W1[(k0 + 1) * Hn + n], fus_W1[k0 * Hn + n]),
            cvt_bf16x2(fus_W1[(k0 + 9) * Hn + n], fus_W1[(k0 + 8) * Hn + n]));
        W2F[idx] = make_uint2(
            cvt_bf16x2(fus_W2[(k0 + 1) * Hn + n], fus_W2[k0 * Hn + n]),
            cvt_bf16x2(fus_W2[(k0 + 9) * Hn + n], fus_W2[(k0 + 8) * Hn + n]));
    }
    if (w == 0) {
        float v0 = upd_b[lane], v1 = upd_b[lane + 32];
        float s = v0 + v1;
        #pragma unroll
        for (int o = 16; o > 0; o >>= 1) s += __shfl_xor_sync(~0u, s, o);
        float mu = s * (1.0f / Hn);
        float d0 = v0 - mu, d1 = v1 - mu;
        s = d0 * d0 + d1 * d1;
        #pragma unroll
        for (int o = 16; o > 0; o >>= 1) s += __shfl_xor_sync(~0u, s, o);
        float inv = rsqrtf(s * (1.0f / Hn) + LN_EPSF);
        P0S[lane]      = d0 * inv * ln_g[lane] + ln_b[lane];
        P0S[lane + 32] = d1 * inv * ln_g[lane + 32] + ln_b[lane + 32];
    }
    __syncthreads();

    if (tid < Hn) {
        float c = fus_b1[tid];
        #pragma unroll 8
        for (int k = 0; k < Hn; k++)
            c = fmaf(P0S[k], fus_W1[(Hn + k) * Hn + tid], c);
        C1S[tid] = c;
    }
    if (w == 2) {
        float s = P0S[lane] * gate_W[Hn + lane]
                + P0S[lane + 32] * gate_W[Hn + lane + 32];
        #pragma unroll
        for (int o = 16; o > 0; o >>= 1) s += __shfl_xor_sync(~0u, s, o);
        if (lane == 0) CGS[0] = s + gate_b[0];
    }
    if (w == 3) {
        if (lane < 16) ((float4*)GWA)[lane] = ((const float4*)gate_W)[lane];
        else ((float4*)B2S)[lane - 16] = ((const float4*)fus_b2)[lane - 16];
    }
    __syncthreads();   // last block-wide sync; warps free-run from here

    const float cgv = CGS[0];
    const int g = lane >> 2, tig = lane & 3;

    // ================= per-warp microtile loop (no block syncs) ============
    for (;;) {
        int t;
        if (lane == 0) t = atomicAdd(&g_tile_ctr, 1) % CLAIMS_PER_EPOCH;
        t = __shfl_sync(~0u, t, 0);
        if (t >= NMICRO) break;

        const int b  = t >> 6;              // 64 microtiles per sample
        const int r0 = (t & 63) << 5;       // 32 rows each
        const float* xb = base + ((size_t)(b * Rn + r0)) * Hn;
        float* op = out + ((size_t)(b * Rn + r0)) * Hn;

        // x fragments; keep fp32 x in registers for the epilogue (xk)
        uint32_t ahi[2][4][4];
        float2 xk[2][4][4];
        float gd[4] = {0.0f, 0.0f, 0.0f, 0.0f};
        #pragma unroll
        for (int s2 = 0; s2 < 2; s2++) {
            int rA = g + s2 * 16, rB = rA + 8;
            #pragma unroll
            for (int kt = 0; kt < 4; kt++) {
                int c0 = kt * 16 + 2 * tig;
                float2 p00 = *(const float2*)(xb + rA * Hn + c0);
                float2 p10 = *(const float2*)(xb + rB * Hn + c0);
                float2 p01 = *(const float2*)(xb + rA * Hn + c0 + 8);
                float2 p11 = *(const float2*)(xb + rB * Hn + c0 + 8);
                float2 gw0 = *(const float2*)(GWA + c0);
                float2 gw8 = *(const float2*)(GWA + c0 + 8);
                gd[s2 * 2 + 0] += p00.x * gw0.x + p00.y * gw0.y
                                + p01.x * gw8.x + p01.y * gw8.y;
                gd[s2 * 2 + 1] += p10.x * gw0.x + p10.y * gw0.y
                                + p11.x * gw8.x + p11.y * gw8.y;
                xk[s2][kt][0] = p00;
                xk[s2][kt][1] = p10;
                xk[s2][kt][2] = p01;
                xk[s2][kt][3] = p11;
                ahi[s2][kt][0] = cvt_bf16x2(p00.y, p00.x);
                ahi[s2][kt][1] = cvt_bf16x2(p10.y, p10.x);
                ahi[s2][kt][2] = cvt_bf16x2(p01.y, p01.x);
                ahi[s2][kt][3] = cvt_bf16x2(p11.y, p11.x);
            }
        }
        #pragma unroll
        for (int i = 0; i < 4; i++) {
            gd[i] += __shfl_xor_sync(~0u, gd[i], 1);
            gd[i] += __shfl_xor_sync(~0u, gd[i], 2);
        }

        // GEMM1 (kt outer, nt inner)
        float acc[2][8][4];
        #pragma unroll
        for (int s2 = 0; s2 < 2; s2++)
            #pragma unroll
            for (int nt = 0; nt < 8; nt++)
                acc[s2][nt][0] = acc[s2][nt][1] = acc[s2][nt][2] = acc[s2][nt][3] = 0.0f;
        #pragma unroll
        for (int kt = 0; kt < 4; kt++) {
            #pragma unroll
            for (int nt = 0; nt < 8; nt++) {
                uint2 bh = W1F[(kt * 8 + nt) * 32 + lane];
                #pragma unroll
                for (int s2 = 0; s2 < 2; s2++)
                    mma_bf16(acc[s2][nt], ahi[s2][kt], bh.x, bh.y);
            }
        }

        // epilogue1: bias c1, relu, repack as A2
        uint32_t yhi[2][4][4];
        #pragma unroll
        for (int kt2 = 0; kt2 < 4; kt2++) {
            #pragma unroll
            for (int half = 0; half < 2; half++) {
                int nt = kt2 * 2 + half;
                int col = nt * 8 + 2 * tig;
                float2 cb = *(const float2*)(C1S + col);
                #pragma unroll
                for (int s2 = 0; s2 < 2; s2++) {
                    float y0 = fmaxf(acc[s2][nt][0] + cb.x, 0.0f);
                    float y1 = fmaxf(acc[s2][nt][1] + cb.y, 0.0f);
                    float y2 = fmaxf(acc[s2][nt][2] + cb.x, 0.0f);
                    float y3 = fmaxf(acc[s2][nt][3] + cb.y, 0.0f);
                    yhi[s2][kt2][half * 2 + 0] = cvt_bf16x2(y1, y0);
                    yhi[s2][kt2][half * 2 + 1] = cvt_bf16x2(y3, y2);
                }
            }
        }

        // GEMM2
        #pragma unroll
        for (int s2 = 0; s2 < 2; s2++)
            #pragma unroll
            for (int nt = 0; nt < 8; nt++)
                acc[s2][nt][0] = acc[s2][nt][1] = acc[s2][nt][2] = acc[s2][nt][3] = 0.0f;
        #pragma unroll
        for (int kt = 0; kt < 4; kt++) {
            #pragma unroll
            for (int nt = 0; nt < 8; nt++) {
                uint2 bh = W2F[(kt * 8 + nt) * 32 + lane];
                #pragma unroll
                for (int s2 = 0; s2 < 2; s2++)
                    mma_bf16(acc[s2][nt], yhi[s2][kt], bh.x, bh.y);
            }
        }

        // epilogue2: blend with register-resident x (no gmem re-read)
        #pragma unroll
        for (int s2 = 0; s2 < 2; s2++) {
            int rA = g + s2 * 16, rB = rA + 8;
            float ga = 1.0f / (1.0f + __expf(-(gd[2 * s2 + 0] + cgv)));
            float gb = 1.0f / (1.0f + __expf(-(gd[2 * s2 + 1] + cgv)));
            #pragma unroll
            for (int kt = 0; kt < 4; kt++) {
                #pragma unroll
                for (int half = 0; half < 2; half++) {
                    int nt = kt * 2 + half;
                    int col = nt * 8 + 2 * tig;
                    float2 b2v = *(const float2*)(B2S + col);
                    float2 xa = xk[s2][kt][half * 2 + 0];
                    float2 xv = xk[s2][kt][half * 2 + 1];
                    float f0 = acc[s2][nt][0] + b2v.x;
                    float f1 = acc[s2][nt][1] + b2v.y;
                    float f2 = acc[s2][nt][2] + b2v.x;
                    float f3 = acc[s2][nt][3] + b2v.y;
                    float2 oa, ob;
                    oa.x = xa.x + ga * (f0 - xa.x);
                    oa.y = xa.y + ga * (f1 - xa.y);
                    ob.x = xv.x + gb * (f2 - xv.x);
                    ob.y = xv.y + gb * (f3 - xv.y);
                    *(float2*)(op + rA * Hn + col) = oa;
                    *(float2*)(op + rB * Hn + col) = ob;
                }
            }
        }
    }

    // ============== per-warp epoch drain barrier + special fixup ============
    int myv;
    if (lane == 0) {
        __threadfence();
        myv = atomicAdd(&g_done, 1);
    }
    if (blockIdx.x >= NFIXB) return;

    if (lane == 0) {
        int target = (myv / NWARPS + 1) * NWARPS;
        while (*(volatile int*)&g_done < target) {}
    }
    __syncwarp();
    __threadfence();

    {
        const int slab = blockIdx.x * 4 + w;    // 0..319, 16 flat edges each
        const int f0 = slab * 16 + g;
        const int f1 = f0 + 8;
        const int b0 = f0 / En, b1 = f1 / En;
        const int r0r = etype[f0], r1r = etype[f1];
        const float* x0 = base + ((size_t)(b0 * Rn + r0r)) * Hn;
        const float* x1 = base + ((size_t)(b1 * Rn + r1r)) * Hn;
        float* o0 = out + ((size_t)(b0 * Rn + r0r)) * Hn;
        float* o1 = out + ((size_t)(b1 * Rn + r1r)) * Hn;
        const float* q10 = g_q1 + (size_t)f0 * Hn;
        const float* q11 = g_q1 + (size_t)f1 * Hn;

        uint32_t ahi[4][4];
        float2 xk[4][4];
        float gd0 = 0.0f, gd1 = 0.0f;
        #pragma unroll
        for (int kt = 0; kt < 4; kt++) {
            int c0 = kt * 16 + 2 * tig;
            float2 p00 = *(const float2*)(x0 + c0);
            float2 p10 = *(const float2*)(x1 + c0);
            float2 p01 = *(const float2*)(x0 + c0 + 8);
            float2 p11 = *(const float2*)(x1 + c0 + 8);
            float2 gw0 = *(const float2*)(GWA + c0);
            float2 gw8 = *(const float2*)(GWA + c0 + 8);
            gd0 += p00.x * gw0.x + p00.y * gw0.y + p01.x * gw8.x + p01.y * gw8.y;
            gd1 += p10.x * gw0.x + p10.y * gw0.y + p11.x * gw8.x + p11.y * gw8.y;
            xk[kt][0] = p00; xk[kt][1] = p10; xk[kt][2] = p01; xk[kt][3] = p11;
            ahi[kt][0] = cvt_bf16x2(p00.y, p00.x);
            ahi[kt][1] = cvt_bf16x2(p10.y, p10.x);
            ahi[kt][2] = cvt_bf16x2(p01.y, p01.x);
            ahi[kt][3] = cvt_bf16x2(p11.y, p11.x);
        }
        gd0 += __shfl_xor_sync(~0u, gd0, 1);
        gd0 += __shfl_xor_sync(~0u, gd0, 2);
        gd1 += __shfl_xor_sync(~0u, gd1, 1);
        gd1 += __shfl_xor_sync(~0u, gd1, 2);

        float acc[8][4];
        #pragma unroll
        for (int nt = 0; nt < 8; nt++)
            acc[nt][0] = acc[nt][1] = acc[nt][2] = acc[nt][3] = 0.0f;
        #pragma unroll
        for (int kt = 0; kt < 4; kt++) {
            #pragma unroll
            for (int nt = 0; nt < 8; nt++) {
                uint2 bh = W1F[(kt * 8 + nt) * 32 + lane];
                mma_bf16(acc[nt], ahi[kt], bh.x, bh.y);
            }
        }

        uint32_t yhi[4][4];
        #pragma unroll
        for (int kt2 = 0; kt2 < 4; kt2++) {
            #pragma unroll
            for (int half = 0; half < 2; half++) {
                int nt = kt2 * 2 + half;
                int col = nt * 8 + 2 * tig;
                float2 ba = *(const float2*)(q10 + col);
                float2 bb = *(const float2*)(q11 + col);
                float y0 = fmaxf(acc[nt][0] + ba.x, 0.0f);
                float y1 = fmaxf(acc[nt][1] + ba.y, 0.0f);
                float y2 = fmaxf(acc[nt][2] + bb.x, 0.0f);
                float y3 = fmaxf(acc[nt][3] + bb.y, 0.0f);
                yhi[kt2][half * 2 + 0] = cvt_bf16x2(y1, y0);
                yhi[kt2][half * 2 + 1] = cvt_bf16x2(y3, y2);
            }
        }

        #pragma unroll
        for (int nt = 0; nt < 8; nt++)
            acc[nt][0] = acc[nt][1] = acc[nt][2] = acc[nt][3] = 0.0f;
        #pragma unroll
        for (int kt = 0; kt < 4; kt++) {
            #pragma unroll
            for (int nt = 0; nt < 8; nt++) {
                uint2 bh = W2F[(kt * 8 + nt) * 32 + lane];
                mma_bf16(acc[nt], yhi[kt], bh.x, bh.y);
            }
        }

        float ga = 1.0f / (1.0f + __expf(-(gd0 + g_qg[f0])));
        float gb = 1.0f / (1.0f + __expf(-(gd1 + g_qg[f1])));
        #pragma unroll
        for (int kt = 0; kt < 4; kt++) {
            #pragma unroll
            for (int half = 0; half < 2; half++) {
                int nt = kt * 2 + half;
                int col = nt * 8 + 2 * tig;
                float2 b2v = *(const float2*)(B2S + col);
                float2 xa = xk[kt][half * 2 + 0];
                float2 xv = xk[kt][half * 2 + 1];
                float f0v = acc[nt][0] + b2v.x;
                float f1v = acc[nt][1] + b2v.y;
                float f2v = acc[nt][2] + b2v.x;
                float f3v = acc[nt][3] + b2v.y;
                float2 oa, ob;
                oa.x = xa.x + ga * (f0v - xa.x);
                oa.y = xa.y + ga * (f1v - xa.y);
                ob.x = xv.x + gb * (f2v - xv.x);
                ob.y = xv.y + gb * (f3v - xv.y);
                *(float2*)(o0 + col) = oa;
                *(float2*)(o1 + col) = ob;
            }
        }
    }
}

// ---------------------------------------------------------------------------
extern "C" void kernel_launch(void* const* d_in, const int* in_sizes, int n_in,
                              void* d_out, int out_size) {
    const int*   qrel   = (const int*)  d_in[0];
    const int*   etype  = (const int*)  d_in[1];
    const float* base   = (const float*)d_in[2];
    const float* noise  = (const float*)d_in[3];
    const float* msg_W  = (const float*)d_in[4];
    const float* msg_b  = (const float*)d_in[5];
    const float* upd_W  = (const float*)d_in[6];
    const float* upd_b  = (const float*)d_in[7];
    const float* ln_g   = (const float*)d_in[8];
    const float* ln_b   = (const float*)d_in[9];
    const float* fus_W1 = (const float*)d_in[10];
    const float* fus_b1 = (const float*)d_in[11];
    const float* fus_W2 = (const float*)d_in[12];
    const float* fus_b2 = (const float*)d_in[13];
    const float* gate_W = (const float*)d_in[14];
    const float* gate_b = (const float*)d_in[15];
    float* out = (float*)d_out;

    cudaFuncSetAttribute(k2_fused, cudaFuncAttributeMaxDynamicSharedMemorySize,
                         SMEM_K2);
    k2_fused<<<NWORK, NTHR, SMEM_K2>>>(
        qrel, etype, noise, msg_W, msg_b, upd_W, upd_b, ln_g, ln_b,
        fus_W1, fus_b1, gate_W, gate_b, base, fus_W2, fus_b2, out);
}

// round 16
// speedup vs baseline: 4.0925x; 1.0231x over previous
#include <cuda_runtime.h>
#include <cuda_bf16.h>
#include <math.h>
#include <stdint.h>

#define Bn 256
#define Rn 2048
#define Hn 64
#define En 20
#define LN_EPSF 1e-5f
#define NMICRO (Bn * (Rn / 32))      // 16384 32-row microtiles
#define NWORK  444                   // 3 CTAs/SM x 148 SMs
#define NWARPS (NWORK * 4)           // 1776 worker warps
#define NFIXB  80                    // fixup blocks (80*4 warps = 320 slabs)
#define CLAIMS_PER_EPOCH (NMICRO + NWARPS)

// device scratch (no allocs allowed); counters monotonic (epoch arithmetic)
__device__ __align__(16) float g_q1[Bn * En * Hn];
__device__ float g_qg[Bn * En];
__device__ int g_tile_ctr;
__device__ int g_done;

static __device__ __forceinline__ uint32_t cvt_bf16x2(float e1, float e0) {
    uint32_t r;
    asm("cvt.rn.bf16x2.f32 %0, %1, %2;" : "=r"(r) : "f"(e1), "f"(e0));
    return r;
}
static __device__ __forceinline__ void mma_bf16(float* c, const uint32_t* a,
                                                uint32_t b0, uint32_t b1) {
    asm volatile(
        "mma.sync.aligned.m16n8k16.row.col.f32.bf16.bf16.f32 "
        "{%0,%1,%2,%3}, {%4,%5,%6,%7}, {%8,%9}, {%0,%1,%2,%3};"
        : "+f"(c[0]), "+f"(c[1]), "+f"(c[2]), "+f"(c[3])
        : "r"(a[0]), "r"(a[1]), "r"(a[2]), "r"(a[3]), "r"(b0), "r"(b1));
}

// ---------------------------------------------------------------------------
// K2: single persistent kernel, 444 CTAs, 3/SM (12 warps/SM, no spills).
// Warps claim 32-row microtiles independently; epilogue re-reads x from
// gmem (L1-hot). blocks [0,256) run prompts first; after a per-warp drain
// barrier, blocks [0,80) fix the special rows.
// ---------------------------------------------------------------------------
#define NTHR 128
// fusion smem
#define OW1F 0
#define OW2F 8192
#define OGWA 16384
#define OC1  16640
#define OB2  16896
#define OP0  17152
#define OCG  17408
// prompt smem (aliases same buffer; used before fusion staging)
#define P_WSUM 0
#define P_HS   16384
#define P_MS   21504
#define P_ER   26624
#define SMEM_K2 26752

__global__ __launch_bounds__(NTHR, 3)
void k2_fused(const int* __restrict__ qrel,
              const int* __restrict__ etype,
              const float* __restrict__ noise,
              const float* __restrict__ msg_W,
              const float* __restrict__ msg_b,
              const float* __restrict__ upd_W,
              const float* __restrict__ upd_b,
              const float* __restrict__ ln_g,
              const float* __restrict__ ln_b,
              const float* __restrict__ fus_W1,
              const float* __restrict__ fus_b1,
              const float* __restrict__ gate_W,
              const float* __restrict__ gate_b,
              const float* __restrict__ base,
              const float* __restrict__ fus_W2,
              const float* __restrict__ fus_b2,
              float* __restrict__ out) {
    extern __shared__ __align__(16) char sm[];
    const int tid = threadIdx.x;
    const int w = tid >> 5, lane = tid & 31;

    if (blockIdx.x < Bn) {
        // ================= prompt pipeline =================
        const int b  = blockIdx.x;
        const int j  = tid & 63;
        const int eg = tid >> 6;
        float* Wsum = (float*)(sm + P_WSUM);
        float (*hs)[Hn] = (float(*)[Hn])(sm + P_HS);
        float (*ms)[Hn] = (float(*)[Hn])(sm + P_MS);
        int* er = (int*)(sm + P_ER);

        for (int idx = tid; idx < Hn * Hn; idx += NTHR)
            Wsum[idx] = msg_W[idx] + msg_W[Hn * Hn + idx];
        if (tid < En) er[tid] = etype[b * En + tid];
        __syncthreads();

        int qr = qrel[b];
        for (int e = eg; e < En; e += 2) {
            int r = er[e];
            hs[e][j] = (r == qr) ? 1.0f
                                 : noise[((size_t)b * Rn + r) * Hn + j] * 0.1f;
        }
        __syncthreads();

        for (int e = eg; e < En; e += 2) {
            float m = msg_b[j];
            #pragma unroll 8
            for (int k = 0; k < Hn; k++) m = fmaf(hs[e][k], Wsum[k * Hn + j], m);
            ms[e][j] = fmaxf(m, 0.0f);
        }
        __syncthreads();

        for (int e = eg; e < En; e += 2) {
            float a = 0.0f;
            int re = er[e];
            #pragma unroll
            for (int e2 = 0; e2 < En; e2++)
                if (er[e2] == re) a += ms[e2][j];
            hs[e][j] = a;
        }
        __syncthreads();

        for (int e = eg; e < En; e += 2) {
            float u = upd_b[j];
            #pragma unroll 8
            for (int k = 0; k < Hn; k++)
                u = fmaf(hs[e][k], upd_W[k * Hn + j], u);
            ms[e][j] = u;
        }
        __syncthreads();
        for (int idx = tid; idx < Hn * Hn; idx += NTHR)
            Wsum[idx] = fus_W1[Hn * Hn + idx];    // W1b for q1
        __syncthreads();

        for (int e = w; e < En; e += 4) {
            float v0 = ms[e][lane], v1 = ms[e][lane + 32];
            float s = v0 + v1;
            #pragma unroll
            for (int o = 16; o > 0; o >>= 1) s += __shfl_xor_sync(~0u, s, o);
            float mu = s * (1.0f / Hn);
            float d0 = v0 - mu, d1 = v1 - mu;
            s = d0 * d0 + d1 * d1;
            #pragma unroll
            for (int o = 16; o > 0; o >>= 1) s += __shfl_xor_sync(~0u, s, o);
            float inv = rsqrtf(s * (1.0f / Hn) + LN_EPSF);
            ms[e][lane]      = d0 * inv * ln_g[lane] + ln_b[lane];
            ms[e][lane + 32] = d1 * inv * ln_g[lane + 32] + ln_b[lane + 32];
        }
        __syncthreads();

        for (int e = eg; e < En; e += 2) {
            float q = fus_b1[j];
            #pragma unroll 8
            for (int k = 0; k < Hn; k++) q = fmaf(ms[e][k], Wsum[k * Hn + j], q);
            g_q1[((size_t)b * En + e) * Hn + j] = q;
        }
        for (int e = w; e < En; e += 4) {
            float s = ms[e][lane] * gate_W[Hn + lane]
                    + ms[e][lane + 32] * gate_W[Hn + lane + 32];
            #pragma unroll
            for (int o = 16; o > 0; o >>= 1) s += __shfl_xor_sync(~0u, s, o);
            if (lane == 0) g_qg[b * En + e] = s + gate_b[0];
        }
        __syncthreads();   // prompt done; smem reused for fusion
    }

    // ================= fusion worker setup =================
    uint2* W1F = (uint2*)(sm + OW1F);
    uint2* W2F = (uint2*)(sm + OW2F);
    float* GWA = (float*)(sm + OGWA);
    float* C1S = (float*)(sm + OC1);
    float* B2S = (float*)(sm + OB2);
    float* P0S = (float*)(sm + OP0);
    float* CGS = (float*)(sm + OCG);

    #pragma unroll
    for (int s = 0; s < 8; s++) {
        int idx = tid + s * NTHR;
        int l = idx & 31;
        int t2 = idx >> 5;
        int nt = t2 & 7, kt = t2 >> 3;
        int n  = nt * 8 + (l >> 2);
        int k0 = kt * 16 + (l & 3) * 2;
        W1F[idx] = make_uint2(
            cvt_bf16x2(fus_W1[(k0 + 1) * Hn + n], fus_W1[k0 * Hn + n]),
            cvt_bf16x2(fus_W1[(k0 + 9) * Hn + n], fus_W1[(k0 + 8) * Hn + n]));
        W2F[idx] = make_uint2(
            cvt_bf16x2(fus_W2[(k0 + 1) * Hn + n], fus_W2[k0 * Hn + n]),
            cvt_bf16x2(fus_W2[(k0 + 9) * Hn + n], fus_W2[(k0 + 8) * Hn + n]));
    }
    if (w == 0) {
        float v0 = upd_b[lane], v1 = upd_b[lane + 32];
        float s = v0 + v1;
        #pragma unroll
        for (int o = 16; o > 0; o >>= 1) s += __shfl_xor_sync(~0u, s, o);
        float mu = s * (1.0f / Hn);
        float d0 = v0 - mu, d1 = v1 - mu;
        s = d0 * d0 + d1 * d1;
        #pragma unroll
        for (int o = 16; o > 0; o >>= 1) s += __shfl_xor_sync(~0u, s, o);
        float inv = rsqrtf(s * (1.0f / Hn) + LN_EPSF);
        P0S[lane]      = d0 * inv * ln_g[lane] + ln_b[lane];
        P0S[lane + 32] = d1 * inv * ln_g[lane + 32] + ln_b[lane + 32];
    }
    __syncthreads();

    if (tid < Hn) {
        float c = fus_b1[tid];
        #pragma unroll 8
        for (int k = 0; k < Hn; k++)
            c = fmaf(P0S[k], fus_W1[(Hn + k) * Hn + tid], c);
        C1S[tid] = c;
    }
    if (w == 2) {
        float s = P0S[lane] * gate_W[Hn + lane]
                + P0S[lane + 32] * gate_W[Hn + lane + 32];
        #pragma unroll
        for (int o = 16; o > 0; o >>= 1) s += __shfl_xor_sync(~0u, s, o);
        if (lane == 0) CGS[0] = s + gate_b[0];
    }
    if (w == 3) {
        if (lane < 16) ((float4*)GWA)[lane] = ((const float4*)gate_W)[lane];
        else ((float4*)B2S)[lane - 16] = ((const float4*)fus_b2)[lane - 16];
    }
    __syncthreads();   // last block-wide sync; warps free-run from here

    const float cgv = CGS[0];
    const int g = lane >> 2, tig = lane & 3;

    // ================= per-warp microtile loop (no block syncs) ============
    for (;;) {
        int t;
        if (lane == 0) t = atomicAdd(&g_tile_ctr, 1) % CLAIMS_PER_EPOCH;
        t = __shfl_sync(~0u, t, 0);
        if (t >= NMICRO) break;

        const int b  = t >> 6;              // 64 microtiles per sample
        const int r0 = (t & 63) << 5;       // 32 rows each
        const float* xb = base + ((size_t)(b * Rn + r0)) * Hn;
        float* op = out + ((size_t)(b * Rn + r0)) * Hn;

        uint32_t ahi[2][4][4];
        float gd[4] = {0.0f, 0.0f, 0.0f, 0.0f};
        #pragma unroll
        for (int s2 = 0; s2 < 2; s2++) {
            int rA = g + s2 * 16, rB = rA + 8;
            #pragma unroll
            for (int kt = 0; kt < 4; kt++) {
                int c0 = kt * 16 + 2 * tig;
                float2 p00 = *(const float2*)(xb + rA * Hn + c0);
                float2 p10 = *(const float2*)(xb + rB * Hn + c0);
                float2 p01 = *(const float2*)(xb + rA * Hn + c0 + 8);
                float2 p11 = *(const float2*)(xb + rB * Hn + c0 + 8);
                float2 gw0 = *(const float2*)(GWA + c0);
                float2 gw8 = *(const float2*)(GWA + c0 + 8);
                gd[s2 * 2 + 0] += p00.x * gw0.x + p00.y * gw0.y
                                + p01.x * gw8.x + p01.y * gw8.y;
                gd[s2 * 2 + 1] += p10.x * gw0.x + p10.y * gw0.y
                                + p11.x * gw8.x + p11.y * gw8.y;
                ahi[s2][kt][0] = cvt_bf16x2(p00.y, p00.x);
                ahi[s2][kt][1] = cvt_bf16x2(p10.y, p10.x);
                ahi[s2][kt][2] = cvt_bf16x2(p01.y, p01.x);
                ahi[s2][kt][3] = cvt_bf16x2(p11.y, p11.x);
            }
        }
        #pragma unroll
        for (int i = 0; i < 4; i++) {
            gd[i] += __shfl_xor_sync(~0u, gd[i], 1);
            gd[i] += __shfl_xor_sync(~0u, gd[i], 2);
        }

        // GEMM1 (kt outer, nt inner)
        float acc[2][8][4];
        #pragma unroll
        for (int s2 = 0; s2 < 2; s2++)
            #pragma unroll
            for (int nt = 0; nt < 8; nt++)
                acc[s2][nt][0] = acc[s2][nt][1] = acc[s2][nt][2] = acc[s2][nt][3] = 0.0f;
        #pragma unroll
        for (int kt = 0; kt < 4; kt++) {
            #pragma unroll
            for (int nt = 0; nt < 8; nt++) {
                uint2 bh = W1F[(kt * 8 + nt) * 32 + lane];
                #pragma unroll
                for (int s2 = 0; s2 < 2; s2++)
                    mma_bf16(acc[s2][nt], ahi[s2][kt], bh.x, bh.y);
            }
        }

        // epilogue1: bias c1, relu, repack as A2
        uint32_t yhi[2][4][4];
        #pragma unroll
        for (int kt2 = 0; kt2 < 4; kt2++) {
            #pragma unroll
            for (int half = 0; half < 2; half++) {
                int nt = kt2 * 2 + half;
                int col = nt * 8 + 2 * tig;
                float2 cb = *(const float2*)(C1S + col);
                #pragma unroll
                for (int s2 = 0; s2 < 2; s2++) {
                    float y0 = fmaxf(acc[s2][nt][0] + cb.x, 0.0f);
                    float y1 = fmaxf(acc[s2][nt][1] + cb.y, 0.0f);
                    float y2 = fmaxf(acc[s2][nt][2] + cb.x, 0.0f);
                    float y3 = fmaxf(acc[s2][nt][3] + cb.y, 0.0f);
                    yhi[s2][kt2][half * 2 + 0] = cvt_bf16x2(y1, y0);
                    yhi[s2][kt2][half * 2 + 1] = cvt_bf16x2(y3, y2);
                }
            }
        }

        // GEMM2
        #pragma unroll
        for (int s2 = 0; s2 < 2; s2++)
            #pragma unroll
            for (int nt = 0; nt < 8; nt++)
                acc[s2][nt][0] = acc[s2][nt][1] = acc[s2][nt][2] = acc[s2][nt][3] = 0.0f;
        #pragma unroll
        for (int kt = 0; kt < 4; kt++) {
            #pragma unroll
            for (int nt = 0; nt < 8; nt++) {
                uint2 bh = W2F[(kt * 8 + nt) * 32 + lane];
                #pragma unroll
                for (int s2 = 0; s2 < 2; s2++)
                    mma_bf16(acc[s2][nt], yhi[s2][kt], bh.x, bh.y);
            }
        }

        // epilogue2: x re-read (L1-hot: same warp loaded these lines)
        #pragma unroll
        for (int s2 = 0; s2 < 2; s2++) {
            int rA = g + s2 * 16, rB = rA + 8;
            float ga = 1.0f / (1.0f + __expf(-(gd[2 * s2 + 0] + cgv)));
            float gb = 1.0f / (1.0f + __expf(-(gd[2 * s2 + 1] + cgv)));
            #pragma unroll
            for (int nt = 0; nt < 8; nt++) {
                int col = nt * 8 + 2 * tig;
                float2 b2v = *(const float2*)(B2S + col);
                float2 xa = *(const float2*)(xb + rA * Hn + col);
                float2 xv = *(const float2*)(xb + rB * Hn + col);
                float f0 = acc[s2][nt][0] + b2v.x;
                float f1 = acc[s2][nt][1] + b2v.y;
                float f2 = acc[s2][nt][2] + b2v.x;
                float f3 = acc[s2][nt][3] + b2v.y;
                float2 oa, ob;
                oa.x = xa.x + ga * (f0 - xa.x);
                oa.y = xa.y + ga * (f1 - xa.y);
                ob.x = xv.x + gb * (f2 - xv.x);
                ob.y = xv.y + gb * (f3 - xv.y);
                *(float2*)(op + rA * Hn + col) = oa;
                *(float2*)(op + rB * Hn + col) = ob;
            }
        }
    }

    // ============== per-warp epoch drain barrier + special fixup ============
    int myv;
    if (lane == 0) {
        __threadfence();
        myv = atomicAdd(&g_done, 1);
    }
    if (blockIdx.x >= NFIXB) return;

    if (lane == 0) {
        int target = (myv / NWARPS + 1) * NWARPS;
        while (*(volatile int*)&g_done < target) {}
    }
    __syncwarp();
    __threadfence();

    {
        const int slab = blockIdx.x * 4 + w;    // 0..319, 16 flat edges each
        const int f0 = slab * 16 + g;
        const int f1 = f0 + 8;
        const int b0 = f0 / En, b1 = f1 / En;
        const int r0r = etype[f0], r1r = etype[f1];
        const float* x0 = base + ((size_t)(b0 * Rn + r0r)) * Hn;
        const float* x1 = base + ((size_t)(b1 * Rn + r1r)) * Hn;
        float* o0 = out + ((size_t)(b0 * Rn + r0r)) * Hn;
        float* o1 = out + ((size_t)(b1 * Rn + r1r)) * Hn;
        const float* q10 = g_q1 + (size_t)f0 * Hn;
        const float* q11 = g_q1 + (size_t)f1 * Hn;

        uint32_t ahi[4][4];
        float gd0 = 0.0f, gd1 = 0.0f;
        #pragma unroll
        for (int kt = 0; kt < 4; kt++) {
            int c0 = kt * 16 + 2 * tig;
            float2 p00 = *(const float2*)(x0 + c0);
            float2 p10 = *(const float2*)(x1 + c0);
            float2 p01 = *(const float2*)(x0 + c0 + 8);
            float2 p11 = *(const float2*)(x1 + c0 + 8);
            float2 gw0 = *(const float2*)(GWA + c0);
            float2 gw8 = *(const float2*)(GWA + c0 + 8);
            gd0 += p00.x * gw0.x + p00.y * gw0.y + p01.x * gw8.x + p01.y * gw8.y;
            gd1 += p10.x * gw0.x + p10.y * gw0.y + p11.x * gw8.x + p11.y * gw8.y;
            ahi[kt][0] = cvt_bf16x2(p00.y, p00.x);
            ahi[kt][1] = cvt_bf16x2(p10.y, p10.x);
            ahi[kt][2] = cvt_bf16x2(p01.y, p01.x);
            ahi[kt][3] = cvt_bf16x2(p11.y, p11.x);
        }
        gd0 += __shfl_xor_sync(~0u, gd0, 1);
        gd0 += __shfl_xor_sync(~0u, gd0, 2);
        gd1 += __shfl_xor_sync(~0u, gd1, 1);
        gd1 += __shfl_xor_sync(~0u, gd1, 2);

        float acc[8][4];
        #pragma unroll
        for (int nt = 0; nt < 8; nt++)
            acc[nt][0] = acc[nt][1] = acc[nt][2] = acc[nt][3] = 0.0f;
        #pragma unroll
        for (int kt = 0; kt < 4; kt++) {
            #pragma unroll
            for (int nt = 0; nt < 8; nt++) {
                uint2 bh = W1F[(kt * 8 + nt) * 32 + lane];
                mma_bf16(acc[nt], ahi[kt], bh.x, bh.y);
            }
        }

        uint32_t yhi[4][4];
        #pragma unroll
        for (int kt2 = 0; kt2 < 4; kt2++) {
            #pragma unroll
            for (int half = 0; half < 2; half++) {
                int nt = kt2 * 2 + half;
                int col = nt * 8 + 2 * tig;
                float2 ba = *(const float2*)(q10 + col);
                float2 bb = *(const float2*)(q11 + col);
                float y0 = fmaxf(acc[nt][0] + ba.x, 0.0f);
                float y1 = fmaxf(acc[nt][1] + ba.y, 0.0f);
                float y2 = fmaxf(acc[nt][2] + bb.x, 0.0f);
                float y3 = fmaxf(acc[nt][3] + bb.y, 0.0f);
                yhi[kt2][half * 2 + 0] = cvt_bf16x2(y1, y0);
                yhi[kt2][half * 2 + 1] = cvt_bf16x2(y3, y2);
            }
        }

        #pragma unroll
        for (int nt = 0; nt < 8; nt++)
            acc[nt][0] = acc[nt][1] = acc[nt][2] = acc[nt][3] = 0.0f;
        #pragma unroll
        for (int kt = 0; kt < 4; kt++) {
            #pragma unroll
            for (int nt = 0; nt < 8; nt++) {
                uint2 bh = W2F[(kt * 8 + nt) * 32 + lane];
                mma_bf16(acc[nt], yhi[kt], bh.x, bh.y);
            }
        }

        float ga = 1.0f / (1.0f + __expf(-(gd0 + g_qg[f0])));
        float gb = 1.0f / (1.0f + __expf(-(gd1 + g_qg[f1])));
        #pragma unroll
        for (int nt = 0; nt < 8; nt++) {
            int col = nt * 8 + 2 * tig;
            float2 b2v = *(const float2*)(B2S + col);
            float2 xa = *(const float2*)(x0 + col);
            float2 xv = *(const float2*)(x1 + col);
            float f0v = acc[nt][0] + b2v.x;
            float f1v = acc[nt][1] + b2v.y;
            float f2v = acc[nt][2] + b2v.x;
            float f3v = acc[nt][3] + b2v.y;
            float2 oa, ob;
            oa.x = xa.x + ga * (f0v - xa.x);
            oa.y = xa.y + ga * (f1v - xa.y);
            ob.x = xv.x + gb * (f2v - xv.x);
            ob.y = xv.y + gb * (f3v - xv.y);
            *(float2*)(o0 + col) = oa;
            *(float2*)(o1 + col) = ob;
        }
    }
}

// ---------------------------------------------------------------------------
extern "C" void kernel_launch(void* const* d_in, const int* in_sizes, int n_in,
                              void* d_out, int out_size) {
    const int*   qrel   = (const int*)  d_in[0];
    const int*   etype  = (const int*)  d_in[1];
    const float* base   = (const float*)d_in[2];
    const float* noise  = (const float*)d_in[3];
    const float* msg_W  = (const float*)d_in[4];
    const float* msg_b  = (const float*)d_in[5];
    const float* upd_W  = (const float*)d_in[6];
    const float* upd_b  = (const float*)d_in[7];
    const float* ln_g   = (const float*)d_in[8];
    const float* ln_b   = (const float*)d_in[9];
    const float* fus_W1 = (const float*)d_in[10];
    const float* fus_b1 = (const float*)d_in[11];
    const float* fus_W2 = (const float*)d_in[12];
    const float* fus_b2 = (const float*)d_in[13];
    const float* gate_W = (const float*)d_in[14];
    const float* gate_b = (const float*)d_in[15];
    float* out = (float*)d_out;

    cudaFuncSetAttribute(k2_fused, cudaFuncAttributeMaxDynamicSharedMemorySize,
                         SMEM_K2);
    k2_fused<<<NWORK, NTHR, SMEM_K2>>>(
        qrel, etype, noise, msg_W, msg_b, upd_W, upd_b, ln_g, ln_b,
        fus_W1, fus_b1, gate_W, gate_b, base, fus_W2, fus_b2, out);
}

// round 17
// speedup vs baseline: 4.3552x; 1.0642x over previous
#include <cuda_runtime.h>
#include <cuda_bf16.h>
#include <math.h>
#include <stdint.h>

#define Bn 256
#define Rn 2048
#define Hn 64
#define En 20
#define LN_EPSF 1e-5f
#define NMICRO (Bn * (Rn / 32))      // 16384 32-row microtiles
#define NWORK  444                   // 3 CTAs/SM x 148 SMs
#define NWARPS (NWORK * 4)           // 1776 worker warps
#define NFIXB  80                    // fixup blocks (80*4 warps = 320 slabs)
#define CLAIMS_PER_EPOCH (NMICRO + NWARPS)
#define XPADF 72                     // row stride in floats: 72 mod 32 = 8 banks
                                     // -> fragment-pattern LDS/STS conflict-free

// device scratch (no allocs allowed); counters monotonic (epoch arithmetic)
__device__ __align__(16) float g_q1[Bn * En * Hn];
__device__ float g_qg[Bn * En];
__device__ int g_tile_ctr;
__device__ int g_done;

static __device__ __forceinline__ uint32_t cvt_bf16x2(float e1, float e0) {
    uint32_t r;
    asm("cvt.rn.bf16x2.f32 %0, %1, %2;" : "=r"(r) : "f"(e1), "f"(e0));
    return r;
}
static __device__ __forceinline__ void mma_bf16(float* c, const uint32_t* a,
                                                uint32_t b0, uint32_t b1) {
    asm volatile(
        "mma.sync.aligned.m16n8k16.row.col.f32.bf16.bf16.f32 "
        "{%0,%1,%2,%3}, {%4,%5,%6,%7}, {%8,%9}, {%0,%1,%2,%3};"
        : "+f"(c[0]), "+f"(c[1]), "+f"(c[2]), "+f"(c[3])
        : "r"(a[0]), "r"(a[1]), "r"(a[2]), "r"(a[3]), "r"(b0), "r"(b1));
}

// ---------------------------------------------------------------------------
// K2: single persistent kernel, 444 CTAs (3/SM). Warps claim 32-row
// microtiles; each warp stages its tile through a private padded smem
// buffer so ALL gmem traffic is coalesced (LDG.128/STG.128) and all
// fragment-pattern accesses are conflict-free smem. blocks [0,256) run
// prompts first; after a per-warp drain barrier, blocks [0,80) fix specials.
// ---------------------------------------------------------------------------
#define NTHR 128
// fusion smem
#define OW1F 0
#define OW2F 8192
#define OGWA 16384
#define OC1  16640
#define OB2  16896
#define OP0  17152
#define OCG  17408
#define OGZ  17424                    // 4 warps x 32 floats
#define OXS  17952                    // 4 warps x 32x72 floats (9216 B each)
#define SMEM_K2 54816
// prompt smem (aliases same buffer; used before fusion staging)
#define P_WSUM 0
#define P_HS   16384
#define P_MS   21504
#define P_ER   26624

__global__ __launch_bounds__(NTHR, 3)
void k2_fused(const int* __restrict__ qrel,
              const int* __restrict__ etype,
              const float* __restrict__ noise,
              const float* __restrict__ msg_W,
              const float* __restrict__ msg_b,
              const float* __restrict__ upd_W,
              const float* __restrict__ upd_b,
              const float* __restrict__ ln_g,
              const float* __restrict__ ln_b,
              const float* __restrict__ fus_W1,
              const float* __restrict__ fus_b1,
              const float* __restrict__ gate_W,
              const float* __restrict__ gate_b,
              const float* __restrict__ base,
              const float* __restrict__ fus_W2,
              const float* __restrict__ fus_b2,
              float* __restrict__ out) {
    extern __shared__ __align__(16) char sm[];
    const int tid = threadIdx.x;
    const int w = tid >> 5, lane = tid & 31;

    if (blockIdx.x < Bn) {
        // ================= prompt pipeline =================
        const int b  = blockIdx.x;
        const int j  = tid & 63;
        const int eg = tid >> 6;
        float* Wsum = (float*)(sm + P_WSUM);
        float (*hs)[Hn] = (float(*)[Hn])(sm + P_HS);
        float (*ms)[Hn] = (float(*)[Hn])(sm + P_MS);
        int* er = (int*)(sm + P_ER);

        for (int idx = tid; idx < Hn * Hn; idx += NTHR)
            Wsum[idx] = msg_W[idx] + msg_W[Hn * Hn + idx];
        if (tid < En) er[tid] = etype[b * En + tid];
        __syncthreads();

        int qr = qrel[b];
        for (int e = eg; e < En; e += 2) {
            int r = er[e];
            hs[e][j] = (r == qr) ? 1.0f
                                 : noise[((size_t)b * Rn + r) * Hn + j] * 0.1f;
        }
        __syncthreads();

        for (int e = eg; e < En; e += 2) {
            float m = msg_b[j];
            #pragma unroll 8
            for (int k = 0; k < Hn; k++) m = fmaf(hs[e][k], Wsum[k * Hn + j], m);
            ms[e][j] = fmaxf(m, 0.0f);
        }
        __syncthreads();

        for (int e = eg; e < En; e += 2) {
            float a = 0.0f;
            int re = er[e];
            #pragma unroll
            for (int e2 = 0; e2 < En; e2++)
                if (er[e2] == re) a += ms[e2][j];
            hs[e][j] = a;
        }
        __syncthreads();

        for (int e = eg; e < En; e += 2) {
            float u = upd_b[j];
            #pragma unroll 8
            for (int k = 0; k < Hn; k++)
                u = fmaf(hs[e][k], upd_W[k * Hn + j], u);
            ms[e][j] = u;
        }
        __syncthreads();
        for (int idx = tid; idx < Hn * Hn; idx += NTHR)
            Wsum[idx] = fus_W1[Hn * Hn + idx];    // W1b for q1
        __syncthreads();

        for (int e = w; e < En; e += 4) {
            float v0 = ms[e][lane], v1 = ms[e][lane + 32];
            float s = v0 + v1;
            #pragma unroll
            for (int o = 16; o > 0; o >>= 1) s += __shfl_xor_sync(~0u, s, o);
            float mu = s * (1.0f / Hn);
            float d0 = v0 - mu, d1 = v1 - mu;
            s = d0 * d0 + d1 * d1;
            #pragma unroll
            for (int o = 16; o > 0; o >>= 1) s += __shfl_xor_sync(~0u, s, o);
            float inv = rsqrtf(s * (1.0f / Hn) + LN_EPSF);
            ms[e][lane]      = d0 * inv * ln_g[lane] + ln_b[lane];
            ms[e][lane + 32] = d1 * inv * ln_g[lane + 32] + ln_b[lane + 32];
        }
        __syncthreads();

        for (int e = eg; e < En; e += 2) {
            float q = fus_b1[j];
            #pragma unroll 8
            for (int k = 0; k < Hn; k++) q = fmaf(ms[e][k], Wsum[k * Hn + j], q);
            g_q1[((size_t)b * En + e) * Hn + j] = q;
        }
        for (int e = w; e < En; e += 4) {
            float s = ms[e][lane] * gate_W[Hn + lane]
                    + ms[e][lane + 32] * gate_W[Hn + lane + 32];
            #pragma unroll
            for (int o = 16; o > 0; o >>= 1) s += __shfl_xor_sync(~0u, s, o);
            if (lane == 0) g_qg[b * En + e] = s + gate_b[0];
        }
        __syncthreads();   // prompt done; smem reused for fusion
    }

    // ================= fusion worker setup =================
    uint2* W1F = (uint2*)(sm + OW1F);
    uint2* W2F = (uint2*)(sm + OW2F);
    float* GWA = (float*)(sm + OGWA);
    float* C1S = (float*)(sm + OC1);
    float* B2S = (float*)(sm + OB2);
    float* P0S = (float*)(sm + OP0);
    float* CGS = (float*)(sm + OCG);
    float* GZ  = (float*)(sm + OGZ) + w * 32;
    float* XS  = (float*)(sm + OXS + w * (32 * XPADF * 4));

    #pragma unroll
    for (int s = 0; s < 8; s++) {
        int idx = tid + s * NTHR;
        int l = idx & 31;
        int t2 = idx >> 5;
        int nt = t2 & 7, kt = t2 >> 3;
        int n  = nt * 8 + (l >> 2);
        int k0 = kt * 16 + (l & 3) * 2;
        W1F[idx] = make_uint2(
            cvt_bf16x2(fus_W1[(k0 + 1) * Hn + n], fus_W1[k0 * Hn + n]),
            cvt_bf16x2(fus_W1[(k0 + 9) * Hn + n], fus_W1[(k0 + 8) * Hn + n]));
        W2F[idx] = make_uint2(
            cvt_bf16x2(fus_W2[(k0 + 1) * Hn + n], fus_W2[k0 * Hn + n]),
            cvt_bf16x2(fus_W2[(k0 + 9) * Hn + n], fus_W2[(k0 + 8) * Hn + n]));
    }
    if (w == 0) {
        float v0 = upd_b[lane], v1 = upd_b[lane + 32];
        float s = v0 + v1;
        #pragma unroll
        for (int o = 16; o > 0; o >>= 1) s += __shfl_xor_sync(~0u, s, o);
        float mu = s * (1.0f / Hn);
        float d0 = v0 - mu, d1 = v1 - mu;
        s = d0 * d0 + d1 * d1;
        #pragma unroll
        for (int o = 16; o > 0; o >>= 1) s += __shfl_xor_sync(~0u, s, o);
        float inv = rsqrtf(s * (1.0f / Hn) + LN_EPSF);
        P0S[lane]      = d0 * inv * ln_g[lane] + ln_b[lane];
        P0S[lane + 32] = d1 * inv * ln_g[lane + 32] + ln_b[lane + 32];
    }
    __syncthreads();

    if (tid < Hn) {
        float c = fus_b1[tid];
        #pragma unroll 8
        for (int k = 0; k < Hn; k++)
            c = fmaf(P0S[k], fus_W1[(Hn + k) * Hn + tid], c);
        C1S[tid] = c;
    }
    if (w == 2) {
        float s = P0S[lane] * gate_W[Hn + lane]
                + P0S[lane + 32] * gate_W[Hn + lane + 32];
        #pragma unroll
        for (int o = 16; o > 0; o >>= 1) s += __shfl_xor_sync(~0u, s, o);
        if (lane == 0) CGS[0] = s + gate_b[0];
    }
    if (w == 3) {
        if (lane < 16) ((float4*)GWA)[lane] = ((const float4*)gate_W)[lane];
        else ((float4*)B2S)[lane - 16] = ((const float4*)fus_b2)[lane - 16];
    }
    __syncthreads();   // last block-wide sync; warps free-run from here

    const float cgv = CGS[0];
    const int g = lane >> 2, tig = lane & 3;
    // per-lane gate weight slice (c4 = lane&15 is constant per lane)
    const float4 gw4 = ((const float4*)GWA)[lane & 15];
    const int halfsel = lane >> 4;   // 0: even row of pair, 1: odd

    // ================= per-warp microtile loop (no block syncs) ============
    for (;;) {
        int t;
        if (lane == 0) t = atomicAdd(&g_tile_ctr, 1) % CLAIMS_PER_EPOCH;
        t = __shfl_sync(~0u, t, 0);
        if (t >= NMICRO) break;

        const int b  = t >> 6;              // 64 microtiles per sample
        const int r0 = (t & 63) << 5;       // 32 rows each
        const float4* xb4 = (const float4*)(base + ((size_t)(b * Rn + r0)) * Hn);
        float4* op4 = (float4*)(out + ((size_t)(b * Rn + r0)) * Hn);

        // ---- stage tile coalesced + fused gate dot ----
        #pragma unroll
        for (int i = 0; i < 16; i++) {
            int f = i * 32 + lane;
            int row = f >> 4, c4 = f & 15;
            float4 v = xb4[f];
            ((float4*)XS)[row * (XPADF / 4) + c4] = v;
            float s = v.x * gw4.x + v.y * gw4.y + v.z * gw4.z + v.w * gw4.w;
            s += __shfl_xor_sync(~0u, s, 1);
            s += __shfl_xor_sync(~0u, s, 2);
            s += __shfl_xor_sync(~0u, s, 4);
            s += __shfl_xor_sync(~0u, s, 8);
            if ((lane & 15) == 0) GZ[2 * i + halfsel] = s;
        }
        __syncwarp();

        // ---- A fragments from smem (conflict-free with XPADF=72) ----
        uint32_t ahi[2][4][4];
        #pragma unroll
        for (int s2 = 0; s2 < 2; s2++) {
            int rA = g + s2 * 16, rB = rA + 8;
            #pragma unroll
            for (int kt = 0; kt < 4; kt++) {
                int c0 = kt * 16 + 2 * tig;
                float2 p00 = *(const float2*)(XS + rA * XPADF + c0);
                float2 p10 = *(const float2*)(XS + rB * XPADF + c0);
                float2 p01 = *(const float2*)(XS + rA * XPADF + c0 + 8);
                float2 p11 = *(const float2*)(XS + rB * XPADF + c0 + 8);
                ahi[s2][kt][0] = cvt_bf16x2(p00.y, p00.x);
                ahi[s2][kt][1] = cvt_bf16x2(p10.y, p10.x);
                ahi[s2][kt][2] = cvt_bf16x2(p01.y, p01.x);
                ahi[s2][kt][3] = cvt_bf16x2(p11.y, p11.x);
            }
        }

        // GEMM1 (kt outer, nt inner)
        float acc[2][8][4];
        #pragma unroll
        for (int s2 = 0; s2 < 2; s2++)
            #pragma unroll
            for (int nt = 0; nt < 8; nt++)
                acc[s2][nt][0] = acc[s2][nt][1] = acc[s2][nt][2] = acc[s2][nt][3] = 0.0f;
        #pragma unroll
        for (int kt = 0; kt < 4; kt++) {
            #pragma unroll
            for (int nt = 0; nt < 8; nt++) {
                uint2 bh = W1F[(kt * 8 + nt) * 32 + lane];
                #pragma unroll
                for (int s2 = 0; s2 < 2; s2++)
                    mma_bf16(acc[s2][nt], ahi[s2][kt], bh.x, bh.y);
            }
        }

        // epilogue1: bias c1, relu, repack as A2
        uint32_t yhi[2][4][4];
        #pragma unroll
        for (int kt2 = 0; kt2 < 4; kt2++) {
            #pragma unroll
            for (int half = 0; half < 2; half++) {
                int nt = kt2 * 2 + half;
                int col = nt * 8 + 2 * tig;
                float2 cb = *(const float2*)(C1S + col);
                #pragma unroll
                for (int s2 = 0; s2 < 2; s2++) {
                    float y0 = fmaxf(acc[s2][nt][0] + cb.x, 0.0f);
                    float y1 = fmaxf(acc[s2][nt][1] + cb.y, 0.0f);
                    float y2 = fmaxf(acc[s2][nt][2] + cb.x, 0.0f);
                    float y3 = fmaxf(acc[s2][nt][3] + cb.y, 0.0f);
                    yhi[s2][kt2][half * 2 + 0] = cvt_bf16x2(y1, y0);
                    yhi[s2][kt2][half * 2 + 1] = cvt_bf16x2(y3, y2);
                }
            }
        }

        // GEMM2
        #pragma unroll
        for (int s2 = 0; s2 < 2; s2++)
            #pragma unroll
            for (int nt = 0; nt < 8; nt++)
                acc[s2][nt][0] = acc[s2][nt][1] = acc[s2][nt][2] = acc[s2][nt][3] = 0.0f;
        #pragma unroll
        for (int kt = 0; kt < 4; kt++) {
            #pragma unroll
            for (int nt = 0; nt < 8; nt++) {
                uint2 bh = W2F[(kt * 8 + nt) * 32 + lane];
                #pragma unroll
                for (int s2 = 0; s2 < 2; s2++)
                    mma_bf16(acc[s2][nt], yhi[s2][kt], bh.x, bh.y);
            }
        }

        // epilogue2: blend against smem x (conflict-free), write back in place
        #pragma unroll
        for (int s2 = 0; s2 < 2; s2++) {
            int rA = g + s2 * 16, rB = rA + 8;
            float ga = 1.0f / (1.0f + __expf(-(GZ[rA] + cgv)));
            float gb = 1.0f / (1.0f + __expf(-(GZ[rB] + cgv)));
            #pragma unroll
            for (int nt = 0; nt < 8; nt++) {
                int col = nt * 8 + 2 * tig;
                float2 b2v = *(const float2*)(B2S + col);
                float2 xa = *(const float2*)(XS + rA * XPADF + col);
                float2 xv = *(const float2*)(XS + rB * XPADF + col);
                float f0 = acc[s2][nt][0] + b2v.x;
                float f1 = acc[s2][nt][1] + b2v.y;
                float f2 = acc[s2][nt][2] + b2v.x;
                float f3 = acc[s2][nt][3] + b2v.y;
                xa.x += ga * (f0 - xa.x);
                xa.y += ga * (f1 - xa.y);
                xv.x += gb * (f2 - xv.x);
                xv.y += gb * (f3 - xv.y);
                *(float2*)(XS + rA * XPADF + col) = xa;
                *(float2*)(XS + rB * XPADF + col) = xv;
            }
        }
        __syncwarp();

        // ---- coalesced store ----
        #pragma unroll
        for (int i = 0; i < 16; i++) {
            int f = i * 32 + lane;
            int row = f >> 4, c4 = f & 15;
            op4[f] = ((const float4*)XS)[row * (XPADF / 4) + c4];
        }
    }

    // ============== per-warp epoch drain barrier + special fixup ============
    int myv;
    if (lane == 0) {
        __threadfence();
        myv = atomicAdd(&g_done, 1);
    }
    if (blockIdx.x >= NFIXB) return;

    if (lane == 0) {
        int target = (myv / NWARPS + 1) * NWARPS;
        while (*(volatile int*)&g_done < target) {}
    }
    __syncwarp();
    __threadfence();

    {
        const int slab = blockIdx.x * 4 + w;    // 0..319, 16 flat edges each
        const int f0 = slab * 16 + g;
        const int f1 = f0 + 8;
        const int b0 = f0 / En, b1 = f1 / En;
        const int r0r = etype[f0], r1r = etype[f1];
        const float* x0 = base + ((size_t)(b0 * Rn + r0r)) * Hn;
        const float* x1 = base + ((size_t)(b1 * Rn + r1r)) * Hn;
        float* o0 = out + ((size_t)(b0 * Rn + r0r)) * Hn;
        float* o1 = out + ((size_t)(b1 * Rn + r1r)) * Hn;
        const float* q10 = g_q1 + (size_t)f0 * Hn;
        const float* q11 = g_q1 + (size_t)f1 * Hn;

        uint32_t ahi[4][4];
        float gd0 = 0.0f, gd1 = 0.0f;
        #pragma unroll
        for (int kt = 0; kt < 4; kt++) {
            int c0 = kt * 16 + 2 * tig;
            float2 p00 = *(const float2*)(x0 + c0);
            float2 p10 = *(const float2*)(x1 + c0);
            float2 p01 = *(const float2*)(x0 + c0 + 8);
            float2 p11 = *(const float2*)(x1 + c0 + 8);
            float2 gw0 = *(const float2*)(GWA + c0);
            float2 gw8 = *(const float2*)(GWA + c0 + 8);
            gd0 += p00.x * gw0.x + p00.y * gw0.y + p01.x * gw8.x + p01.y * gw8.y;
            gd1 += p10.x * gw0.x + p10.y * gw0.y + p11.x * gw8.x + p11.y * gw8.y;
            ahi[kt][0] = cvt_bf16x2(p00.y, p00.x);
            ahi[kt][1] = cvt_bf16x2(p10.y, p10.x);
            ahi[kt][2] = cvt_bf16x2(p01.y, p01.x);
            ahi[kt][3] = cvt_bf16x2(p11.y, p11.x);
        }
        gd0 += __shfl_xor_sync(~0u, gd0, 1);
        gd0 += __shfl_xor_sync(~0u, gd0, 2);
        gd1 += __shfl_xor_sync(~0u, gd1, 1);
        gd1 += __shfl_xor_sync(~0u, gd1, 2);

        float acc[8][4];
        #pragma unroll
        for (int nt = 0; nt < 8; nt++)
            acc[nt][0] = acc[nt][1] = acc[nt][2] = acc[nt][3] = 0.0f;
        #pragma unroll
        for (int kt = 0; kt < 4; kt++) {
            #pragma unroll
            for (int nt = 0; nt < 8; nt++) {
                uint2 bh = W1F[(kt * 8 + nt) * 32 + lane];
                mma_bf16(acc[nt], ahi[kt], bh.x, bh.y);
            }
        }

        uint32_t yhi[4][4];
        #pragma unroll
        for (int kt2 = 0; kt2 < 4; kt2++) {
            #pragma unroll
            for (int half = 0; half < 2; half++) {
                int nt = kt2 * 2 + half;
                int col = nt * 8 + 2 * tig;
                float2 ba = *(const float2*)(q10 + col);
                float2 bb = *(const float2*)(q11 + col);
                float y0 = fmaxf(acc[nt][0] + ba.x, 0.0f);
                float y1 = fmaxf(acc[nt][1] + ba.y, 0.0f);
                float y2 = fmaxf(acc[nt][2] + bb.x, 0.0f);
                float y3 = fmaxf(acc[nt][3] + bb.y, 0.0f);
                yhi[kt2][half * 2 + 0] = cvt_bf16x2(y1, y0);
                yhi[kt2][half * 2 + 1] = cvt_bf16x2(y3, y2);
            }
        }

        #pragma unroll
        for (int nt = 0; nt < 8; nt++)
            acc[nt][0] = acc[nt][1] = acc[nt][2] = acc[nt][3] = 0.0f;
        #pragma unroll
        for (int kt = 0; kt < 4; kt++) {
            #pragma unroll
            for (int nt = 0; nt < 8; nt++) {
                uint2 bh = W2F[(kt * 8 + nt) * 32 + lane];
                mma_bf16(acc[nt], yhi[kt], bh.x, bh.y);
            }
        }

        float ga = 1.0f / (1.0f + __expf(-(gd0 + g_qg[f0])));
        float gb = 1.0f / (1.0f + __expf(-(gd1 + g_qg[f1])));
        #pragma unroll
        for (int nt = 0; nt < 8; nt++) {
            int col = nt * 8 + 2 * tig;
            float2 b2v = *(const float2*)(B2S + col);
            float2 xa = *(const float2*)(x0 + col);
            float2 xv = *(const float2*)(x1 + col);
            float f0v = acc[nt][0] + b2v.x;
            float f1v = acc[nt][1] + b2v.y;
            float f2v = acc[nt][2] + b2v.x;
            float f3v = acc[nt][3] + b2v.y;
            float2 oa, ob;
            oa.x = xa.x + ga * (f0v - xa.x);
            oa.y = xa.y + ga * (f1v - xa.y);
            ob.x = xv.x + gb * (f2v - xv.x);
            ob.y = xv.y + gb * (f3v - xv.y);
            *(float2*)(o0 + col) = oa;
            *(float2*)(o1 + col) = ob;
        }
    }
}

// ---------------------------------------------------------------------------
extern "C" void kernel_launch(void* const* d_in, const int* in_sizes, int n_in,
                              void* d_out, int out_size) {
    const int*   qrel   = (const int*)  d_in[0];
    const int*   etype  = (const int*)  d_in[1];
    const float* base   = (const float*)d_in[2];
    const float* noise  = (const float*)d_in[3];
    const float* msg_W  = (const float*)d_in[4];
    const float* msg_b  = (const float*)d_in[5];
    const float* upd_W  = (const float*)d_in[6];
    const float* upd_b  = (const float*)d_in[7];
    const float* ln_g   = (const float*)d_in[8];
    const float* ln_b   = (const float*)d_in[9];
    const float* fus_W1 = (const float*)d_in[10];
    const float* fus_b1 = (const float*)d_in[11];
    const float* fus_W2 = (const float*)d_in[12];
    const float* fus_b2 = (const float*)d_in[13];
    const float* gate_W = (const float*)d_in[14];
    const float* gate_b = (const float*)d_in[15];
    float* out = (float*)d_out;

    cudaFuncSetAttribute(k2_fused, cudaFuncAttributeMaxDynamicSharedMemorySize,
                         SMEM_K2);
    k2_fused<<<NWORK, NTHR, SMEM_K2>>>(
        qrel, etype, noise, msg_W, msg_b, upd_W, upd_b, ln_g, ln_b,
        fus_W1, fus_b1, gate_W, gate_b, base, fus_W2, fus_b2, out);
}